// round 11
// baseline (speedup 1.0000x reference)
#include <cuda_runtime.h>
#include <cuda.h>
#include <cuda_bf16.h>
#include <math.h>
#include <stdint.h>

// ---------------- constants ----------------
#define T_      2048
#define H_      2048
#define NH_     16
#define KVH_    4
#define HD_     128
#define WIN_    512
#define SINK_   64
#define S_      64
#define NG_     4
#define MLPI_   5504
#define CK_     4
#define INTER_  2048
#define CONVD_  2560
#define NPROJ_  4624
#define LMEM_   1472
#define EPS_    1e-6f
#define MEPS_   1e-5f

// ---------------- scratch ----------------
__device__ float g_pre   [T_ * H_];
__device__ float g_proj  [LMEM_ * NPROJ_];
__device__ float g_xbc   [LMEM_ * CONVD_];
__device__ float g_dt    [LMEM_ * NH_];
__device__ float g_y     [LMEM_ * INTER_];
__device__ float g_g     [LMEM_ * INTER_];
__device__ float g_q     [T_ * (NH_ * HD_)];
__device__ float g_k     [T_ * (KVH_ * HD_)];
__device__ float g_v     [T_ * (KVH_ * HD_)];
__device__ float g_merged[T_ * INTER_];
__device__ float g_tmp   [T_ * H_];
__device__ float g_h     [T_ * H_];
__device__ float g_m     [T_ * H_];
__device__ float g_gu    [T_ * 2 * MLPI_];
__device__ float g_gate  [T_ * MLPI_];
// tf32-rounded weight copies
__device__ float g_wq  [(NH_*HD_) * H_];
__device__ float g_wk  [(KVH_*HD_) * H_];
__device__ float g_wv  [(KVH_*HD_) * H_];
__device__ float g_wo  [H_ * (NH_*HD_)];
__device__ float g_win [NPROJ_ * H_];
__device__ float g_wout[H_ * INTER_];
__device__ float g_wgu [2 * MLPI_ * H_];
__device__ float g_wd  [H_ * MLPI_];

// ---------------- ptx helpers (baseline-safe) ----------------
__device__ __forceinline__ uint32_t smem_u32(const void* p) {
    uint32_t a;
    asm("{ .reg .u64 t; cvta.to.shared.u64 t, %1; cvt.u32.u64 %0, t; }" : "=r"(a) : "l"(p));
    return a;
}
__device__ __forceinline__ float rtf32(float x) {
    float y; asm("cvt.rna.tf32.f32 %0, %1;" : "=f"(y) : "f"(x)); return y;
}

#define MBARRIER_INIT(addr, cnt) \
    asm volatile("mbarrier.init.shared.b64 [%0], %1;" :: "r"((uint32_t)(addr)), "r"((uint32_t)(cnt)) : "memory")
#define MBARRIER_EXPECT_TX(addr, bytes) \
    asm volatile("mbarrier.arrive.expect_tx.shared.b64 _, [%0], %1;" :: "r"((uint32_t)(addr)), "r"((uint32_t)(bytes)) : "memory")
#define MBARRIER_WAIT_PARITY(addr, ph) do { \
    uint32_t _m = (uint32_t)(addr); uint32_t _p = (uint32_t)(ph); uint32_t _d; \
    asm volatile("{\n\t.reg .pred p;\n\t" \
        "mbarrier.try_wait.parity.acquire.cta.shared::cta.b64 p, [%1], %2;\n\t" \
        "selp.b32 %0, 1, 0, p;\n\t}" : "=r"(_d) : "r"(_m), "r"(_p) : "memory"); \
    if (!_d) { asm volatile("{\n\t.reg .pred P1;\n\t" \
        "WL_%=:\n\t" \
        "mbarrier.try_wait.parity.acquire.cta.shared::cta.b64 P1, [%0], %1, 0x989680;\n\t" \
        "@P1 bra.uni WD_%=;\n\tbra.uni WL_%=;\n\tWD_%=:\n\t}" \
        :: "r"(_m), "r"(_p) : "memory"); } \
} while (0)

__device__ __forceinline__ void tma2d(uint32_t smem, const void* tm, int x, int y, uint32_t mbar) {
    asm volatile("cp.async.bulk.tensor.2d.shared::cta.global.tile.mbarrier::complete_tx::bytes "
                 "[%0], [%1, {%2, %3}], [%4];"
                 :: "r"(smem), "l"(tm), "r"(x), "r"(y), "r"(mbar) : "memory");
}

// ---------------- tcgen05 (arch-specific: sm_103a pass only) ----------------
#if defined(__CUDA_ARCH_FEAT_SM103_ALL)
#define HAS_TCGEN05 1

#define TCGEN05_ALLOC(smem_addr, nCols) \
    asm volatile("tcgen05.alloc.cta_group::1.sync.aligned.shared::cta.b32 [%0], %1;" \
        :: "r"((uint32_t)(smem_addr)), "r"((uint32_t)(nCols)) : "memory")
#define TCGEN05_DEALLOC(tmem, nCols) \
    asm volatile("tcgen05.dealloc.cta_group::1.sync.aligned.b32 %0, %1;" :: "r"(tmem), "r"((uint32_t)(nCols)))
#define TCGEN05_COMMIT(mbar) \
    asm volatile("tcgen05.commit.cta_group::1.mbarrier::arrive::one.shared::cluster.b64 [%0];" \
        :: "r"((uint32_t)(mbar)) : "memory")
#define TCGEN05_FENCE_AFTER() asm volatile("tcgen05.fence::after_thread_sync;" ::: "memory")
#define TCGEN05_WAIT_LD() asm volatile("tcgen05.wait::ld.sync.aligned;" ::: "memory")

#define TCGEN05_LD_32X32B_X32(r, tmem_addr) \
    asm volatile("tcgen05.ld.sync.aligned.32x32b.x32.b32 " \
        "{%0, %1, %2, %3, %4, %5, %6, %7, %8, %9, %10, %11, %12, %13, %14, %15, " \
        " %16, %17, %18, %19, %20, %21, %22, %23, %24, %25, %26, %27, %28, %29, %30, %31}, [%32];" \
        : "=r"((r)[0]),  "=r"((r)[1]),  "=r"((r)[2]),  "=r"((r)[3]), \
          "=r"((r)[4]),  "=r"((r)[5]),  "=r"((r)[6]),  "=r"((r)[7]), \
          "=r"((r)[8]),  "=r"((r)[9]),  "=r"((r)[10]), "=r"((r)[11]), \
          "=r"((r)[12]), "=r"((r)[13]), "=r"((r)[14]), "=r"((r)[15]), \
          "=r"((r)[16]), "=r"((r)[17]), "=r"((r)[18]), "=r"((r)[19]), \
          "=r"((r)[20]), "=r"((r)[21]), "=r"((r)[22]), "=r"((r)[23]), \
          "=r"((r)[24]), "=r"((r)[25]), "=r"((r)[26]), "=r"((r)[27]), \
          "=r"((r)[28]), "=r"((r)[29]), "=r"((r)[30]), "=r"((r)[31]) \
        : "r"(tmem_addr))

__device__ __forceinline__ void mma_tf32_ss(uint32_t d, uint64_t ad, uint64_t bd,
                                            uint32_t idesc, uint32_t en) {
    asm volatile("{\n\t.reg .pred p;\n\tsetp.ne.u32 p, %4, 0;\n\t"
                 "tcgen05.mma.cta_group::1.kind::tf32 [%0], %1, %2, %3, {%5, %5, %5, %5}, p;\n\t}"
                 :: "r"(d), "l"(ad), "l"(bd), "r"(idesc), "r"(en), "r"(0u) : "memory");
}
#endif

// SW128 K-major SMEM descriptor (LBO=1, SBO=64, version=1)
static constexpr uint64_t SMEM_DESC_BASE_SW128 =
    (uint64_t(2) << 61) | (uint64_t(1) << 46) | (uint64_t(64) << 32) | (uint64_t(1) << 16);
#define MAKE_SMEM_DESC(base_addr) (SMEM_DESC_BASE_SW128 | ((uint64_t)((base_addr) >> 4) & 0x3FFF))

// ---------------- tcgen05 tf32 GEMM: C[M,N] = A[M,K] * B[N,K]^T (+bias) ----------------
#define GBM 128
#define GBN 256
#define GBK 32
#define GDEPTH 4
#define SM_A_OFF 1024
#define SM_B_OFF (1024 + GDEPTH * 16384)
#define GSMEM (1024 + GDEPTH * 16384 + GDEPTH * 32768)

template<bool ROUND>
__global__ void __launch_bounds__(128, 1)
gemm_tc(const __grid_constant__ CUtensorMap tmA,
        const __grid_constant__ CUtensorMap tmB,
        const float* __restrict__ Araw, const float* __restrict__ Braw,
        const float* __restrict__ bias, float* __restrict__ C,
        int M, int N, int K) {
#if defined(HAS_TCGEN05)
    extern __shared__ __align__(1024) char smem[];
    uint32_t sb = smem_u32(smem);
    int tid = threadIdx.x, wid = tid >> 5, lane = tid & 31;
    int m0 = blockIdx.y * GBM, n0 = blockIdx.x * GBN;

    if (wid == 0) TCGEN05_ALLOC(sb + 0, 256);
    if (tid == 0) {
        for (int s = 0; s < GDEPTH; s++) {
            MBARRIER_INIT(sb + 8 + s * 16, 1);       // full
            MBARRIER_INIT(sb + 8 + s * 16 + 8, 1);   // empty
        }
    }
    __syncthreads();
    uint32_t tmem;
    asm volatile("ld.shared.b32 %0, [%1];" : "=r"(tmem) : "r"(sb + 0));

    int nst = K / GBK;
    if (tid == 0) {
        int pre = nst < GDEPTH ? nst : GDEPTH;
        for (int s = 0; s < pre; s++) {
            uint32_t full = sb + 8 + s * 16;
            MBARRIER_EXPECT_TX(full, 49152);
            tma2d(sb + SM_A_OFF + s * 16384, &tmA, s * GBK, m0, full);
            tma2d(sb + SM_B_OFF + s * 32768, &tmB, s * GBK, n0, full);
        }
        const uint32_t idesc = (1u << 4) | (2u << 7) | (2u << 10) |
                               ((GBN / 8) << 17) | ((GBM / 16) << 24);
        for (int s = 0; s < nst; s++) {
            int slot = s & (GDEPTH - 1);
            int ph = (s / GDEPTH) & 1;
            uint32_t full = sb + 8 + slot * 16;
            uint32_t empty = full + 8;
            MBARRIER_WAIT_PARITY(full, ph);
            uint64_t ad = MAKE_SMEM_DESC(sb + SM_A_OFF + slot * 16384);
            uint64_t bd = MAKE_SMEM_DESC(sb + SM_B_OFF + slot * 32768);
#pragma unroll
            for (int kk = 0; kk < 4; kk++)
                mma_tf32_ss(tmem, ad + kk * 2, bd + kk * 2, idesc,
                            (s > 0 || kk > 0) ? 1u : 0u);
            TCGEN05_COMMIT(empty);
            if (s > 0) {
                int rs = s - 1 + GDEPTH;
                if (rs < nst) {
                    int rslot = (s - 1) & (GDEPTH - 1);
                    int rph = ((s - 1) / GDEPTH) & 1;
                    uint32_t rfull = sb + 8 + rslot * 16;
                    MBARRIER_WAIT_PARITY(rfull + 8, rph);
                    MBARRIER_EXPECT_TX(rfull, 49152);
                    tma2d(sb + SM_A_OFF + rslot * 16384, &tmA, rs * GBK, m0, rfull);
                    tma2d(sb + SM_B_OFF + rslot * 32768, &tmB, rs * GBK, n0, rfull);
                }
            }
        }
        int ls = nst - 1;
        MBARRIER_WAIT_PARITY(sb + 8 + (ls & (GDEPTH - 1)) * 16 + 8, (ls / GDEPTH) & 1);
    }
    __syncthreads();
    TCGEN05_FENCE_AFTER();

    int m = m0 + wid * 32 + lane;
    bool mok = (m < M);
#pragma unroll 1
    for (int b = 0; b < 8; b++) {
        uint32_t r[32];
        TCGEN05_LD_32X32B_X32(r, tmem + b * 32);
        TCGEN05_WAIT_LD();
        if (mok) {
            float* crow = C + (size_t)m * N;
#pragma unroll
            for (int j4 = 0; j4 < 8; j4++) {
                int c = n0 + b * 32 + j4 * 4;
                if (c < N) {
                    float4 v;
                    v.x = __uint_as_float(r[j4 * 4 + 0]);
                    v.y = __uint_as_float(r[j4 * 4 + 1]);
                    v.z = __uint_as_float(r[j4 * 4 + 2]);
                    v.w = __uint_as_float(r[j4 * 4 + 3]);
                    if (bias) {
                        float4 bb = *(const float4*)(bias + c);
                        v.x += bb.x; v.y += bb.y; v.z += bb.z; v.w += bb.w;
                    }
                    if (ROUND) {
                        v.x = rtf32(v.x); v.y = rtf32(v.y);
                        v.z = rtf32(v.z); v.w = rtf32(v.w);
                    }
                    *(float4*)(crow + c) = v;
                }
            }
        }
    }
    __syncthreads();
    if (wid == 0) TCGEN05_DEALLOC(tmem, 256);
#else
    // Fallback for the generic compute_103 PTX pass (never run on GB300).
    int m0 = blockIdx.y * GBM, n0 = blockIdx.x * GBN;
    for (int idx = threadIdx.x; idx < GBM * GBN; idx += blockDim.x) {
        int mi = idx / GBN, ni = idx % GBN;
        int m = m0 + mi, n = n0 + ni;
        if (m < M && n < N) {
            const float* a = Araw + (size_t)m * K;
            const float* b = Braw + (size_t)n * K;
            float acc = 0.f;
            for (int k = 0; k < K; k++) acc += a[k] * b[k];
            if (bias) acc += bias[n];
            if (ROUND) acc = rtf32(acc);
            C[(size_t)m * N + n] = acc;
        }
    }
#endif
}

// ---------------- weight rounding: persistent grid-stride, 4-way ILP ----------------
__global__ void roundw_k(const float4* __restrict__ src, float4* __restrict__ dst, int n4) {
    int stride = gridDim.x * blockDim.x;
    for (int base = blockIdx.x * blockDim.x + threadIdx.x; base < n4; base += stride * 4) {
        float4 v[4];
        int idx[4];
        bool ok[4];
#pragma unroll
        for (int j = 0; j < 4; j++) {
            idx[j] = base + j * stride;
            ok[j] = idx[j] < n4;
            if (ok[j]) v[j] = src[idx[j]];
        }
#pragma unroll
        for (int j = 0; j < 4; j++) {
            if (ok[j]) {
                float4 w = v[j];
                w.x = rtf32(w.x); w.y = rtf32(w.y); w.z = rtf32(w.z); w.w = rtf32(w.w);
                dst[idx[j]] = w;
            }
        }
    }
}

// ---------------- rmsnorm ----------------
__global__ void rmsnorm_k(const float* __restrict__ x, const float* __restrict__ w,
                          float* __restrict__ out, int cols, float eps, int do_round) {
    int row = blockIdx.x;
    const float* xr = x + (size_t)row * cols;
    float ss = 0.f;
    for (int i = threadIdx.x; i < cols; i += blockDim.x) { float v = xr[i]; ss += v * v; }
    __shared__ float sh[32];
#pragma unroll
    for (int o = 16; o; o >>= 1) ss += __shfl_xor_sync(0xFFFFFFFFu, ss, o);
    if ((threadIdx.x & 31) == 0) sh[threadIdx.x >> 5] = ss;
    __syncthreads();
    if (threadIdx.x < 32) {
        float v = (threadIdx.x < (blockDim.x >> 5)) ? sh[threadIdx.x] : 0.f;
#pragma unroll
        for (int o = 16; o; o >>= 1) v += __shfl_xor_sync(0xFFFFFFFFu, v, o);
        if (threadIdx.x == 0) sh[0] = v;
    }
    __syncthreads();
    float scale = rsqrtf(sh[0] / (float)cols + eps);
    for (int i = threadIdx.x; i < cols; i += blockDim.x) {
        float v = xr[i] * scale * w[i];
        out[(size_t)row * cols + i] = do_round ? rtf32(v) : v;
    }
}

// ---------------- conv + silu ----------------
__global__ void conv_silu_k(const float* __restrict__ proj, const float* __restrict__ cw,
                            const float* __restrict__ cb, float* __restrict__ xbc) {
    int idx = blockIdx.x * blockDim.x + threadIdx.x;
    if (idx >= LMEM_ * CONVD_) return;
    int l = idx / CONVD_, c = idx % CONVD_;
    float acc = cb[c];
#pragma unroll
    for (int j = 0; j < CK_; j++) {
        int t = l + j - (CK_ - 1);
        if (t >= 0) acc += cw[c * CK_ + j] * proj[(size_t)t * NPROJ_ + INTER_ + c];
    }
    xbc[idx] = acc / (1.f + expf(-acc));
}

__global__ void dt_k(const float* __restrict__ proj, const float* __restrict__ dtb,
                     float* __restrict__ dt) {
    int idx = blockIdx.x * blockDim.x + threadIdx.x;
    if (idx >= LMEM_ * NH_) return;
    int l = idx / NH_, h = idx % NH_;
    float x = proj[(size_t)l * NPROJ_ + (INTER_ + CONVD_) + h] + dtb[h];
    dt[idx] = (x > 20.f) ? x : log1pf(expf(x));
}

// ---------------- mamba2 scan (serial layout; tree-sum for the y reduction) ----------------
__global__ void scan_k(const float* __restrict__ xbc, const float* __restrict__ dt,
                       const float* __restrict__ A_log, const float* __restrict__ Dp,
                       float* __restrict__ y) {
    int h = blockIdx.x;
    int tid = threadIdx.x;
    int g = h >> 2;
    float A  = -expf(A_log[h]);
    float Dh = Dp[h];
    __shared__ float Bs[2][S_], Cs[2][S_];
    float st[S_];
#pragma unroll
    for (int s = 0; s < S_; s++) st[s] = 0.f;

    float xv  = xbc[(size_t)0 * CONVD_ + h * HD_ + tid];
    float bv  = (tid < S_) ? xbc[INTER_ + g * S_ + tid]
                           : xbc[INTER_ + NG_ * S_ + g * S_ + (tid - S_)];
    float dtl = dt[h];

    for (int l = 0; l < LMEM_; l++) {
        int buf = l & 1;
        if (tid < S_) Bs[buf][tid] = bv; else Cs[buf][tid - S_] = bv;
        __syncthreads();
        float xn = 0.f, bn = 0.f, dtn = 0.f;
        if (l + 1 < LMEM_) {
            const float* nx = xbc + (size_t)(l + 1) * CONVD_;
            xn  = nx[h * HD_ + tid];
            bn  = (tid < S_) ? nx[INTER_ + g * S_ + tid]
                             : nx[INTER_ + NG_ * S_ + g * S_ + (tid - S_)];
            dtn = dt[(size_t)(l + 1) * NH_ + h];
        }
        float decay = expf(dtl * A);
        float dtx   = dtl * xv;
        // 8 parallel accumulators -> depth-3 tree (breaks the 64-deep serial yv chain)
        float ya0 = 0.f, ya1 = 0.f, ya2 = 0.f, ya3 = 0.f;
        float ya4 = 0.f, ya5 = 0.f, ya6 = 0.f, ya7 = 0.f;
#pragma unroll
        for (int s = 0; s < S_; s += 8) {
            st[s+0] = decay * st[s+0] + dtx * Bs[buf][s+0]; ya0 += st[s+0] * Cs[buf][s+0];
            st[s+1] = decay * st[s+1] + dtx * Bs[buf][s+1]; ya1 += st[s+1] * Cs[buf][s+1];
            st[s+2] = decay * st[s+2] + dtx * Bs[buf][s+2]; ya2 += st[s+2] * Cs[buf][s+2];
            st[s+3] = decay * st[s+3] + dtx * Bs[buf][s+3]; ya3 += st[s+3] * Cs[buf][s+3];
            st[s+4] = decay * st[s+4] + dtx * Bs[buf][s+4]; ya4 += st[s+4] * Cs[buf][s+4];
            st[s+5] = decay * st[s+5] + dtx * Bs[buf][s+5]; ya5 += st[s+5] * Cs[buf][s+5];
            st[s+6] = decay * st[s+6] + dtx * Bs[buf][s+6]; ya6 += st[s+6] * Cs[buf][s+6];
            st[s+7] = decay * st[s+7] + dtx * Bs[buf][s+7]; ya7 += st[s+7] * Cs[buf][s+7];
        }
        float yv = ((ya0 + ya1) + (ya2 + ya3)) + ((ya4 + ya5) + (ya6 + ya7));
        yv += Dh * xv;
        y[(size_t)l * INTER_ + h * HD_ + tid] = yv;
        xv = xn; bv = bn; dtl = dtn;
    }
}

// ---------------- gated rmsnorm ----------------
__global__ void gatenorm_k(const float* __restrict__ y, const float* __restrict__ proj,
                           const float* __restrict__ mw, float* __restrict__ out) {
    int row = blockIdx.x;
    __shared__ float gsh[INTER_];
    __shared__ float sh[32];
    float ss = 0.f;
    for (int i = threadIdx.x; i < INTER_; i += blockDim.x) {
        float z  = proj[(size_t)row * NPROJ_ + i];
        float gv = y[(size_t)row * INTER_ + i] * (z / (1.f + expf(-z)));
        gsh[i] = gv;
        ss += gv * gv;
    }
#pragma unroll
    for (int o = 16; o; o >>= 1) ss += __shfl_xor_sync(0xFFFFFFFFu, ss, o);
    if ((threadIdx.x & 31) == 0) sh[threadIdx.x >> 5] = ss;
    __syncthreads();
    if (threadIdx.x < 32) {
        float v = (threadIdx.x < (blockDim.x >> 5)) ? sh[threadIdx.x] : 0.f;
#pragma unroll
        for (int o = 16; o; o >>= 1) v += __shfl_xor_sync(0xFFFFFFFFu, v, o);
        if (threadIdx.x == 0) sh[0] = v;
    }
    __syncthreads();
    float scale = rsqrtf(sh[0] / (float)INTER_ + MEPS_);
    for (int i = threadIdx.x; i < INTER_; i += blockDim.x)
        out[(size_t)row * INTER_ + i] = rtf32(gsh[i] * scale * mw[i]);
}

// ---------------- RoPE ----------------
__global__ void rope_q_k(float* __restrict__ q, const float* __restrict__ cosb,
                         const float* __restrict__ sinb) {
    int ri = blockIdx.y;
    int r = (ri < SINK_) ? ri : (T_ - WIN_) + (ri - SINK_);
    int i = blockIdx.x * blockDim.x + threadIdx.x;
    if (i >= NH_ * (HD_ / 2)) return;
    int hh = i >> 6, d = i & 63;
    float* qr = q + (size_t)r * (NH_ * HD_) + hh * HD_;
    float c0 = cosb[r * HD_ + d],      s0 = sinb[r * HD_ + d];
    float c1 = cosb[r * HD_ + d + 64], s1 = sinb[r * HD_ + d + 64];
    float a = qr[d], b = qr[d + 64];
    qr[d]      = a * c0 - b * s0;
    qr[d + 64] = b * c1 + a * s1;
}

__global__ void rope_k_k(float* __restrict__ k, const float* __restrict__ cosb,
                         const float* __restrict__ sinb) {
    int r = blockIdx.y;
    int i = threadIdx.x;
    if (i >= KVH_ * (HD_ / 2)) return;
    int hh = i >> 6, d = i & 63;
    float* kr = k + (size_t)r * (KVH_ * HD_) + hh * HD_;
    float c0 = cosb[r * HD_ + d],      s0 = sinb[r * HD_ + d];
    float c1 = cosb[r * HD_ + d + 64], s1 = sinb[r * HD_ + d + 64];
    float a = kr[d], b = kr[d + 64];
    kr[d]      = a * c0 - b * s0;
    kr[d + 64] = b * c1 + a * s1;
}

// ---------------- k/v row SINK replacement ----------------
__global__ void memact_kv_k(const float* __restrict__ merged,
                            const float* __restrict__ kw, const float* __restrict__ kb,
                            const float* __restrict__ vw, const float* __restrict__ vb,
                            float* __restrict__ kbuf, float* __restrict__ vbuf) {
    int p = blockIdx.x;
    const float* act = merged + (size_t)(SINK_ + LMEM_ - 1) * INTER_;
    int pp = (p < KVH_ * HD_) ? p : p - KVH_ * HD_;
    const float* W = (p < KVH_ * HD_) ? kw : vw;
    float bs       = (p < KVH_ * HD_) ? kb[pp] : vb[pp];
    float ss = 0.f;
    for (int i = threadIdx.x; i < H_; i += blockDim.x) ss += act[i] * W[(size_t)pp * H_ + i];
    __shared__ float sh[32];
#pragma unroll
    for (int o = 16; o; o >>= 1) ss += __shfl_xor_sync(0xFFFFFFFFu, ss, o);
    if ((threadIdx.x & 31) == 0) sh[threadIdx.x >> 5] = ss;
    __syncthreads();
    if (threadIdx.x == 0) {
        float v = 0.f;
        for (int w = 0; w < (int)(blockDim.x >> 5); w++) v += sh[w];
        v += bs;
        if (p < KVH_ * HD_) kbuf[(size_t)SINK_ * (KVH_ * HD_) + pp] = v;
        else                vbuf[(size_t)SINK_ * (KVH_ * HD_) + pp] = v;
    }
}

// ---------------- attention ----------------
__global__ void attn_k(const float* __restrict__ q, const float* __restrict__ k,
                       const float* __restrict__ v, float* __restrict__ merged) {
    int wid_g = blockIdx.x * (blockDim.x >> 5) + (threadIdx.x >> 5);
    if (wid_g >= (SINK_ + WIN_) * NH_) return;
    int lane = threadIdx.x & 31;
    int ri = wid_g >> 4;
    int h  = wid_g & 15;
    int r  = (ri < SINK_) ? ri : (T_ - WIN_) + (ri - SINK_);
    int g  = h >> 2;
    const float4 q4 = *(const float4*)(q + (size_t)r * (NH_ * HD_) + h * HD_ + lane * 4);
    const float scale = 0.08838834764831845f;
    const float sink_bonus = 0.5f * (float)(T_ - SINK_ - WIN_) / (float)T_;
    float mmax = -1e30f, denom = 0.f;
    float4 acc = make_float4(0.f, 0.f, 0.f, 0.f);

    for (int seg = 0; seg < 2; seg++) {
        int cbeg = seg ? max(SINK_ + 1, r - WIN_) : 0;
        int cend = seg ? r : min(r, SINK_);
        for (int c = cbeg; c <= cend; c++) {
            const float4 k4 = *(const float4*)(k + (size_t)c * (KVH_ * HD_) + g * HD_ + lane * 4);
            float s = q4.x * k4.x + q4.y * k4.y + q4.z * k4.z + q4.w * k4.w;
#pragma unroll
            for (int o = 16; o; o >>= 1) s += __shfl_xor_sync(0xFFFFFFFFu, s, o);
            s = s * scale + ((c == SINK_) ? sink_bonus : 0.f);
            float mn = fmaxf(mmax, s);
            float corr = expf(mmax - mn);
            float p = expf(s - mn);
            mmax = mn;
            denom = denom * corr + p;
            const float4 v4 = *(const float4*)(v + (size_t)c * (KVH_ * HD_) + g * HD_ + lane * 4);
            acc.x = acc.x * corr + p * v4.x;
            acc.y = acc.y * corr + p * v4.y;
            acc.z = acc.z * corr + p * v4.z;
            acc.w = acc.w * corr + p * v4.w;
        }
    }
    float inv = 1.f / denom;
    float4 o4;
    o4.x = rtf32(acc.x * inv); o4.y = rtf32(acc.y * inv);
    o4.z = rtf32(acc.z * inv); o4.w = rtf32(acc.w * inv);
    *(float4*)(merged + (size_t)r * INTER_ + h * HD_ + lane * 4) = o4;
}

// ---------------- elementwise ----------------
__global__ void add_k(const float* __restrict__ a, const float* __restrict__ b,
                      float* __restrict__ o, int n) {
    int i = blockIdx.x * blockDim.x + threadIdx.x;
    if (i < n) o[i] = a[i] + b[i];
}
__global__ void swiglu_fused_k(const float* __restrict__ gu, float* __restrict__ o) {
    int i = blockIdx.x * blockDim.x + threadIdx.x;
    if (i >= T_ * MLPI_) return;
    int row = i / MLPI_, c = i % MLPI_;
    float x = gu[(size_t)row * (2 * MLPI_) + c];
    float u = gu[(size_t)row * (2 * MLPI_) + MLPI_ + c];
    o[i] = rtf32((x / (1.f + expf(-x))) * u);
}

// ---------------- host ----------------
typedef CUresult (*PFN_encodeTiled)(CUtensorMap*, CUtensorMapDataType, cuuint32_t, void*,
                                    const cuuint64_t*, const cuuint64_t*, const cuuint32_t*,
                                    const cuuint32_t*, CUtensorMapInterleave, CUtensorMapSwizzle,
                                    CUtensorMapL2promotion, CUtensorMapFloatOOBfill);

static PFN_encodeTiled get_encoder() {
    void* p = nullptr;
    cudaDriverEntryPointQueryResult st;
    cudaGetDriverEntryPointByVersion("cuTensorMapEncodeTiled", &p, 12000, cudaEnableDefault, &st);
    return (PFN_encodeTiled)p;
}

static void make_tm(PFN_encodeTiled enc, CUtensorMap* tm, const float* base,
                    int rows, int cols, int box_rows) {
    cuuint64_t dims[2]    = {(cuuint64_t)cols, (cuuint64_t)rows};
    cuuint64_t strides[1] = {(cuuint64_t)cols * 4};
    cuuint32_t box[2]     = {32u, (cuuint32_t)box_rows};
    cuuint32_t es[2]      = {1u, 1u};
    enc(tm, CU_TENSOR_MAP_DATA_TYPE_FLOAT32, 2, (void*)base, dims, strides, box, es,
        CU_TENSOR_MAP_INTERLEAVE_NONE, CU_TENSOR_MAP_SWIZZLE_128B,
        CU_TENSOR_MAP_L2_PROMOTION_L2_128B, CU_TENSOR_MAP_FLOAT_OOB_FILL_NONE);
}

static PFN_encodeTiled g_enc = nullptr;

static void launch_gemm_tc(const float* A, const float* B,
                           const float* bias, float* C, int M, int N, int K, bool roundOut) {
    CUtensorMap tmA, tmB;
    make_tm(g_enc, &tmA, A, M, K, 128);
    make_tm(g_enc, &tmB, B, N, K, 256);
    dim3 grid((N + GBN - 1) / GBN, (M + GBM - 1) / GBM);
    if (roundOut) gemm_tc<true><<<grid, 128, GSMEM>>>(tmA, tmB, A, B, bias, C, M, N, K);
    else          gemm_tc<false><<<grid, 128, GSMEM>>>(tmA, tmB, A, B, bias, C, M, N, K);
}

static void roundw(const float* src, float* dst, int n) {
    int n4 = n / 4;
    int blocks = (n4 + 256 * 4 - 1) / (256 * 4);
    if (blocks > 148 * 4) blocks = 148 * 4;
    roundw_k<<<blocks, 256>>>((const float4*)src, (float4*)dst, n4);
}

extern "C" void kernel_launch(void* const* d_in, const int* in_sizes, int n_in,
                              void* d_out, int out_size) {
    const float* hs      = (const float*)d_in[0];
    const float* cosb    = (const float*)d_in[1];
    const float* sinb    = (const float*)d_in[2];
    const float* ln1_w   = (const float*)d_in[3];
    const float* q_w     = (const float*)d_in[4];
    const float* q_b     = (const float*)d_in[5];
    const float* k_w     = (const float*)d_in[6];
    const float* k_b     = (const float*)d_in[7];
    const float* v_w     = (const float*)d_in[8];
    const float* v_b     = (const float*)d_in[9];
    const float* o_w     = (const float*)d_in[10];
    const float* inpj_w  = (const float*)d_in[11];
    const float* conv_w  = (const float*)d_in[12];
    const float* conv_b  = (const float*)d_in[13];
    const float* dt_bias = (const float*)d_in[14];
    const float* A_log   = (const float*)d_in[15];
    const float* Dp      = (const float*)d_in[16];
    const float* mnorm_w = (const float*)d_in[17];
    const float* outp_w  = (const float*)d_in[18];
    const float* ln2_w   = (const float*)d_in[19];
    const float* gate_w  = (const float*)d_in[20];
    const float* up_w    = (const float*)d_in[21];
    const float* down_w  = (const float*)d_in[22];
    float* out = (float*)d_out;

    float *pre, *proj, *xbc, *dtb, *ybuf, *gbuf, *qb, *kb, *vb, *merged, *tmp, *hb, *mb, *gub, *gateb;
    float *wq, *wk, *wv, *wo, *win, *wout, *wgu, *wd;
    cudaGetSymbolAddress((void**)&pre,    g_pre);
    cudaGetSymbolAddress((void**)&proj,   g_proj);
    cudaGetSymbolAddress((void**)&xbc,    g_xbc);
    cudaGetSymbolAddress((void**)&dtb,    g_dt);
    cudaGetSymbolAddress((void**)&ybuf,   g_y);
    cudaGetSymbolAddress((void**)&gbuf,   g_g);
    cudaGetSymbolAddress((void**)&qb,     g_q);
    cudaGetSymbolAddress((void**)&kb,     g_k);
    cudaGetSymbolAddress((void**)&vb,     g_v);
    cudaGetSymbolAddress((void**)&merged, g_merged);
    cudaGetSymbolAddress((void**)&tmp,    g_tmp);
    cudaGetSymbolAddress((void**)&hb,     g_h);
    cudaGetSymbolAddress((void**)&mb,     g_m);
    cudaGetSymbolAddress((void**)&gub,    g_gu);
    cudaGetSymbolAddress((void**)&gateb,  g_gate);
    cudaGetSymbolAddress((void**)&wq,     g_wq);
    cudaGetSymbolAddress((void**)&wk,     g_wk);
    cudaGetSymbolAddress((void**)&wv,     g_wv);
    cudaGetSymbolAddress((void**)&wo,     g_wo);
    cudaGetSymbolAddress((void**)&win,    g_win);
    cudaGetSymbolAddress((void**)&wout,   g_wout);
    cudaGetSymbolAddress((void**)&wgu,    g_wgu);
    cudaGetSymbolAddress((void**)&wd,     g_wd);

    if (!g_enc) g_enc = get_encoder();
    static bool attrs_set = false;
    if (!attrs_set) {
        cudaFuncSetAttribute(gemm_tc<false>, cudaFuncAttributeMaxDynamicSharedMemorySize, GSMEM);
        cudaFuncSetAttribute(gemm_tc<true>,  cudaFuncAttributeMaxDynamicSharedMemorySize, GSMEM);
        attrs_set = true;
    }

    // 0. round weights to tf32 (unbiased rna); gate|up concatenated
    roundw(q_w,    wq,   NH_ * HD_ * H_);
    roundw(k_w,    wk,   KVH_ * HD_ * H_);
    roundw(v_w,    wv,   KVH_ * HD_ * H_);
    roundw(o_w,    wo,   H_ * NH_ * HD_);
    roundw(inpj_w, win,  NPROJ_ * H_);
    roundw(outp_w, wout, H_ * INTER_);
    roundw(gate_w, wgu,                       MLPI_ * H_);
    roundw(up_w,   wgu + (size_t)MLPI_ * H_,  MLPI_ * H_);
    roundw(down_w, wd,   H_ * MLPI_);

    // 1. pre-norm (tf32-rounded: feeds GEMMs only)
    rmsnorm_k<<<T_, 256>>>(hs, ln1_w, pre, H_, EPS_, 1);

    // 2. mamba branch on pre rows [64, 1536)
    launch_gemm_tc(pre + (size_t)SINK_ * H_, win, nullptr, proj, LMEM_, NPROJ_, H_, false);
    conv_silu_k<<<(LMEM_ * CONVD_ + 255) / 256, 256>>>(proj, conv_w, conv_b, xbc);
    dt_k<<<(LMEM_ * NH_ + 255) / 256, 256>>>(proj, dt_bias, dtb);
    scan_k<<<NH_, 128>>>(xbc, dtb, A_log, Dp, ybuf);
    gatenorm_k<<<LMEM_, 256>>>(ybuf, proj, mnorm_w, gbuf);
    launch_gemm_tc(gbuf, wout, nullptr, merged + (size_t)SINK_ * INTER_, LMEM_, INTER_, H_, true);

    // 3. q projection on consumed rows only; full k/v
    launch_gemm_tc(pre, wq, q_b, qb, SINK_, NH_ * HD_, H_, false);
    launch_gemm_tc(pre + (size_t)(T_ - WIN_) * H_, wq, q_b,
                   qb + (size_t)(T_ - WIN_) * (NH_ * HD_), WIN_, NH_ * HD_, H_, false);
    launch_gemm_tc(pre, wk, k_b, kb, T_, KVH_ * HD_, H_, false);
    launch_gemm_tc(pre, wv, v_b, vb, T_, KVH_ * HD_, H_, false);

    // 4. RoPE
    rope_q_k<<<dim3(4, SINK_ + WIN_), 256>>>(qb, cosb, sinb);
    rope_k_k<<<dim3(1, T_), 256>>>(kb, cosb, sinb);

    // 5. replace k/v at row SINK with mem_act projection (exact fp32 GEMV)
    memact_kv_k<<<2 * KVH_ * HD_, 256>>>(merged, k_w, k_b, v_w, v_b, kb, vb);

    // 6. attention -> merged rows [0,64) and [1536,2048)
    attn_k<<<((SINK_ + WIN_) * NH_ + 7) / 8, 256>>>(qb, kb, vb, merged);

    // 7. o projection + residual
    launch_gemm_tc(merged, wo, nullptr, tmp, T_, H_, NH_ * HD_, false);
    add_k<<<(T_ * H_ + 255) / 256, 256>>>(hs, tmp, hb, T_ * H_);

    // 8. MLP (gate+up fused)
    rmsnorm_k<<<T_, 256>>>(hb, ln2_w, mb, H_, EPS_, 1);
    launch_gemm_tc(mb, wgu, nullptr, gub, T_, 2 * MLPI_, H_, false);
    swiglu_fused_k<<<(T_ * MLPI_ + 255) / 256, 256>>>(gub, gateb);
    launch_gemm_tc(gateb, wd, nullptr, tmp, T_, H_, MLPI_, false);
    add_k<<<(T_ * H_ + 255) / 256, 256>>>(hb, tmp, out, T_ * H_);
}

// round 12
// speedup vs baseline: 1.0441x; 1.0441x over previous
#include <cuda_runtime.h>
#include <cuda.h>
#include <cuda_bf16.h>
#include <math.h>
#include <stdint.h>

// ---------------- constants ----------------
#define T_      2048
#define H_      2048
#define NH_     16
#define KVH_    4
#define HD_     128
#define WIN_    512
#define SINK_   64
#define S_      64
#define NG_     4
#define MLPI_   5504
#define CK_     4
#define INTER_  2048
#define CONVD_  2560
#define NPROJ_  4624
#define LMEM_   1472
#define EPS_    1e-6f
#define MEPS_   1e-5f

// ---------------- scratch ----------------
__device__ float g_pre   [T_ * H_];
__device__ float g_proj  [LMEM_ * NPROJ_];
__device__ float g_xbc   [LMEM_ * CONVD_];
__device__ float g_dt    [LMEM_ * NH_];
__device__ float g_y     [LMEM_ * INTER_];
__device__ float g_g     [LMEM_ * INTER_];
__device__ float g_q     [T_ * (NH_ * HD_)];
__device__ float g_k     [T_ * (KVH_ * HD_)];
__device__ float g_v     [T_ * (KVH_ * HD_)];
__device__ float g_merged[T_ * INTER_];
__device__ float g_h     [T_ * H_];
__device__ float g_m     [T_ * H_];
__device__ float g_gu    [T_ * 2 * MLPI_];   // fused gate|up output
__device__ float g_gate  [T_ * MLPI_];       // swiglu result
// tf32-rounded weight copies
__device__ float g_wq  [(NH_*HD_) * H_];
__device__ float g_wk  [(KVH_*HD_) * H_];
__device__ float g_wv  [(KVH_*HD_) * H_];
__device__ float g_wo  [H_ * (NH_*HD_)];
__device__ float g_win [NPROJ_ * H_];
__device__ float g_wout[H_ * INTER_];
__device__ float g_wgu [2 * MLPI_ * H_];     // wg | wu concatenated
__device__ float g_wd  [H_ * MLPI_];

// ---------------- ptx helpers (baseline-safe) ----------------
__device__ __forceinline__ uint32_t smem_u32(const void* p) {
    uint32_t a;
    asm("{ .reg .u64 t; cvta.to.shared.u64 t, %1; cvt.u32.u64 %0, t; }" : "=r"(a) : "l"(p));
    return a;
}
__device__ __forceinline__ float rtf32(float x) {
    float y; asm("cvt.rna.tf32.f32 %0, %1;" : "=f"(y) : "f"(x)); return y;
}

#define MBARRIER_INIT(addr, cnt) \
    asm volatile("mbarrier.init.shared.b64 [%0], %1;" :: "r"((uint32_t)(addr)), "r"((uint32_t)(cnt)) : "memory")
#define MBARRIER_EXPECT_TX(addr, bytes) \
    asm volatile("mbarrier.arrive.expect_tx.shared.b64 _, [%0], %1;" :: "r"((uint32_t)(addr)), "r"((uint32_t)(bytes)) : "memory")
#define MBARRIER_WAIT_PARITY(addr, ph) do { \
    uint32_t _m = (uint32_t)(addr); uint32_t _p = (uint32_t)(ph); uint32_t _d; \
    asm volatile("{\n\t.reg .pred p;\n\t" \
        "mbarrier.try_wait.parity.acquire.cta.shared::cta.b64 p, [%1], %2;\n\t" \
        "selp.b32 %0, 1, 0, p;\n\t}" : "=r"(_d) : "r"(_m), "r"(_p) : "memory"); \
    if (!_d) { asm volatile("{\n\t.reg .pred P1;\n\t" \
        "WL_%=:\n\t" \
        "mbarrier.try_wait.parity.acquire.cta.shared::cta.b64 P1, [%0], %1, 0x989680;\n\t" \
        "@P1 bra.uni WD_%=;\n\tbra.uni WL_%=;\n\tWD_%=:\n\t}" \
        :: "r"(_m), "r"(_p) : "memory"); } \
} while (0)

__device__ __forceinline__ void tma2d(uint32_t smem, const void* tm, int x, int y, uint32_t mbar) {
    asm volatile("cp.async.bulk.tensor.2d.shared::cta.global.tile.mbarrier::complete_tx::bytes "
                 "[%0], [%1, {%2, %3}], [%4];"
                 :: "r"(smem), "l"(tm), "r"(x), "r"(y), "r"(mbar) : "memory");
}

// ---------------- tcgen05 (arch-specific: sm_103a pass only) ----------------
#if defined(__CUDA_ARCH_FEAT_SM103_ALL)
#define HAS_TCGEN05 1

#define TCGEN05_ALLOC(smem_addr, nCols) \
    asm volatile("tcgen05.alloc.cta_group::1.sync.aligned.shared::cta.b32 [%0], %1;" \
        :: "r"((uint32_t)(smem_addr)), "r"((uint32_t)(nCols)) : "memory")
#define TCGEN05_DEALLOC(tmem, nCols) \
    asm volatile("tcgen05.dealloc.cta_group::1.sync.aligned.b32 %0, %1;" :: "r"(tmem), "r"((uint32_t)(nCols)))
#define TCGEN05_COMMIT(mbar) \
    asm volatile("tcgen05.commit.cta_group::1.mbarrier::arrive::one.shared::cluster.b64 [%0];" \
        :: "r"((uint32_t)(mbar)) : "memory")
#define TCGEN05_FENCE_AFTER() asm volatile("tcgen05.fence::after_thread_sync;" ::: "memory")
#define TCGEN05_WAIT_LD() asm volatile("tcgen05.wait::ld.sync.aligned;" ::: "memory")

#define TCGEN05_LD_32X32B_X32(r, tmem_addr) \
    asm volatile("tcgen05.ld.sync.aligned.32x32b.x32.b32 " \
        "{%0, %1, %2, %3, %4, %5, %6, %7, %8, %9, %10, %11, %12, %13, %14, %15, " \
        " %16, %17, %18, %19, %20, %21, %22, %23, %24, %25, %26, %27, %28, %29, %30, %31}, [%32];" \
        : "=r"((r)[0]),  "=r"((r)[1]),  "=r"((r)[2]),  "=r"((r)[3]), \
          "=r"((r)[4]),  "=r"((r)[5]),  "=r"((r)[6]),  "=r"((r)[7]), \
          "=r"((r)[8]),  "=r"((r)[9]),  "=r"((r)[10]), "=r"((r)[11]), \
          "=r"((r)[12]), "=r"((r)[13]), "=r"((r)[14]), "=r"((r)[15]), \
          "=r"((r)[16]), "=r"((r)[17]), "=r"((r)[18]), "=r"((r)[19]), \
          "=r"((r)[20]), "=r"((r)[21]), "=r"((r)[22]), "=r"((r)[23]), \
          "=r"((r)[24]), "=r"((r)[25]), "=r"((r)[26]), "=r"((r)[27]), \
          "=r"((r)[28]), "=r"((r)[29]), "=r"((r)[30]), "=r"((r)[31]) \
        : "r"(tmem_addr))

__device__ __forceinline__ void mma_tf32_ss(uint32_t d, uint64_t ad, uint64_t bd,
                                            uint32_t idesc, uint32_t en) {
    asm volatile("{\n\t.reg .pred p;\n\tsetp.ne.u32 p, %4, 0;\n\t"
                 "tcgen05.mma.cta_group::1.kind::tf32 [%0], %1, %2, %3, {%5, %5, %5, %5}, p;\n\t}"
                 :: "r"(d), "l"(ad), "l"(bd), "r"(idesc), "r"(en), "r"(0u) : "memory");
}
#endif

// SW128 K-major SMEM descriptor (LBO=1, SBO=64, version=1)
static constexpr uint64_t SMEM_DESC_BASE_SW128 =
    (uint64_t(2) << 61) | (uint64_t(1) << 46) | (uint64_t(64) << 32) | (uint64_t(1) << 16);
#define MAKE_SMEM_DESC(base_addr) (SMEM_DESC_BASE_SW128 | ((uint64_t)((base_addr) >> 4) & 0x3FFF))

// ---------------- tcgen05 tf32 GEMM: C[M,N] = A[M,K] * B[N,K]^T (+bias) (+res) ----------------
#define GBM 128
#define GBN 256
#define GBK 32
#define GDEPTH 4
#define SM_A_OFF 1024
#define SM_B_OFF (1024 + GDEPTH * 16384)
#define GSMEM (1024 + GDEPTH * 16384 + GDEPTH * 32768)

template<bool ROUND>
__global__ void __launch_bounds__(128, 1)
gemm_tc(const __grid_constant__ CUtensorMap tmA,
        const __grid_constant__ CUtensorMap tmB,
        const float* __restrict__ Araw, const float* __restrict__ Braw,
        const float* __restrict__ bias, const float* __restrict__ res,
        float* __restrict__ C, int M, int N, int K) {
#if defined(HAS_TCGEN05)
    extern __shared__ __align__(1024) char smem[];
    uint32_t sb = smem_u32(smem);
    int tid = threadIdx.x, wid = tid >> 5, lane = tid & 31;
    int m0 = blockIdx.y * GBM, n0 = blockIdx.x * GBN;

    if (wid == 0) TCGEN05_ALLOC(sb + 0, 256);
    if (tid == 0) {
        for (int s = 0; s < GDEPTH; s++) {
            MBARRIER_INIT(sb + 8 + s * 16, 1);       // full
            MBARRIER_INIT(sb + 8 + s * 16 + 8, 1);   // empty
        }
    }
    __syncthreads();
    uint32_t tmem;
    asm volatile("ld.shared.b32 %0, [%1];" : "=r"(tmem) : "r"(sb + 0));

    int nst = K / GBK;
    if (tid == 0) {
        int pre = nst < GDEPTH ? nst : GDEPTH;
        for (int s = 0; s < pre; s++) {
            uint32_t full = sb + 8 + s * 16;
            MBARRIER_EXPECT_TX(full, 49152);
            tma2d(sb + SM_A_OFF + s * 16384, &tmA, s * GBK, m0, full);
            tma2d(sb + SM_B_OFF + s * 32768, &tmB, s * GBK, n0, full);
        }
        const uint32_t idesc = (1u << 4) | (2u << 7) | (2u << 10) |
                               ((GBN / 8) << 17) | ((GBM / 16) << 24);
        for (int s = 0; s < nst; s++) {
            int slot = s & (GDEPTH - 1);
            int ph = (s / GDEPTH) & 1;
            uint32_t full = sb + 8 + slot * 16;
            uint32_t empty = full + 8;
            MBARRIER_WAIT_PARITY(full, ph);
            uint64_t ad = MAKE_SMEM_DESC(sb + SM_A_OFF + slot * 16384);
            uint64_t bd = MAKE_SMEM_DESC(sb + SM_B_OFF + slot * 32768);
#pragma unroll
            for (int kk = 0; kk < 4; kk++)
                mma_tf32_ss(tmem, ad + kk * 2, bd + kk * 2, idesc,
                            (s > 0 || kk > 0) ? 1u : 0u);
            TCGEN05_COMMIT(empty);
            if (s > 0) {
                int rs = s - 1 + GDEPTH;
                if (rs < nst) {
                    int rslot = (s - 1) & (GDEPTH - 1);
                    int rph = ((s - 1) / GDEPTH) & 1;
                    uint32_t rfull = sb + 8 + rslot * 16;
                    MBARRIER_WAIT_PARITY(rfull + 8, rph);
                    MBARRIER_EXPECT_TX(rfull, 49152);
                    tma2d(sb + SM_A_OFF + rslot * 16384, &tmA, rs * GBK, m0, rfull);
                    tma2d(sb + SM_B_OFF + rslot * 32768, &tmB, rs * GBK, n0, rfull);
                }
            }
        }
        int ls = nst - 1;
        MBARRIER_WAIT_PARITY(sb + 8 + (ls & (GDEPTH - 1)) * 16 + 8, (ls / GDEPTH) & 1);
    }
    __syncthreads();
    TCGEN05_FENCE_AFTER();

    int m = m0 + wid * 32 + lane;
    bool mok = (m < M);
#pragma unroll 1
    for (int b = 0; b < 8; b++) {
        uint32_t r[32];
        TCGEN05_LD_32X32B_X32(r, tmem + b * 32);
        TCGEN05_WAIT_LD();
        if (mok) {
            float* crow = C + (size_t)m * N;
#pragma unroll
            for (int j4 = 0; j4 < 8; j4++) {
                int c = n0 + b * 32 + j4 * 4;
                if (c < N) {
                    float4 v;
                    v.x = __uint_as_float(r[j4 * 4 + 0]);
                    v.y = __uint_as_float(r[j4 * 4 + 1]);
                    v.z = __uint_as_float(r[j4 * 4 + 2]);
                    v.w = __uint_as_float(r[j4 * 4 + 3]);
                    if (bias) {
                        float4 bb = *(const float4*)(bias + c);
                        v.x += bb.x; v.y += bb.y; v.z += bb.z; v.w += bb.w;
                    }
                    if (res) {
                        float4 rr = *(const float4*)(res + (size_t)m * N + c);
                        v.x += rr.x; v.y += rr.y; v.z += rr.z; v.w += rr.w;
                    }
                    if (ROUND) {
                        v.x = rtf32(v.x); v.y = rtf32(v.y);
                        v.z = rtf32(v.z); v.w = rtf32(v.w);
                    }
                    *(float4*)(crow + c) = v;
                }
            }
        }
    }
    __syncthreads();
    if (wid == 0) TCGEN05_DEALLOC(tmem, 256);
#else
    // Fallback for the generic compute_103 PTX pass (never run on GB300).
    int m0 = blockIdx.y * GBM, n0 = blockIdx.x * GBN;
    for (int idx = threadIdx.x; idx < GBM * GBN; idx += blockDim.x) {
        int mi = idx / GBN, ni = idx % GBN;
        int m = m0 + mi, n = n0 + ni;
        if (m < M && n < N) {
            const float* a = Araw + (size_t)m * K;
            const float* b = Braw + (size_t)n * K;
            float acc = 0.f;
            for (int k = 0; k < K; k++) acc += a[k] * b[k];
            if (bias) acc += bias[n];
            if (res) acc += res[(size_t)m * N + n];
            if (ROUND) acc = rtf32(acc);
            C[(size_t)m * N + n] = acc;
        }
    }
#endif
}

// ---------------- weight rounding (R3 version — proven) ----------------
__global__ void roundw_k(const float* __restrict__ src, float* __restrict__ dst, int n4) {
    int i = blockIdx.x * blockDim.x + threadIdx.x;
    if (i < n4) {
        float4 v = ((const float4*)src)[i];
        v.x = rtf32(v.x); v.y = rtf32(v.y); v.z = rtf32(v.z); v.w = rtf32(v.w);
        ((float4*)dst)[i] = v;
    }
}

// ---------------- rmsnorm ----------------
__global__ void rmsnorm_k(const float* __restrict__ x, const float* __restrict__ w,
                          float* __restrict__ out, int cols, float eps, int do_round) {
    int row = blockIdx.x;
    const float* xr = x + (size_t)row * cols;
    float ss = 0.f;
    for (int i = threadIdx.x; i < cols; i += blockDim.x) { float v = xr[i]; ss += v * v; }
    __shared__ float sh[32];
#pragma unroll
    for (int o = 16; o; o >>= 1) ss += __shfl_xor_sync(0xFFFFFFFFu, ss, o);
    if ((threadIdx.x & 31) == 0) sh[threadIdx.x >> 5] = ss;
    __syncthreads();
    if (threadIdx.x < 32) {
        float v = (threadIdx.x < (blockDim.x >> 5)) ? sh[threadIdx.x] : 0.f;
#pragma unroll
        for (int o = 16; o; o >>= 1) v += __shfl_xor_sync(0xFFFFFFFFu, v, o);
        if (threadIdx.x == 0) sh[0] = v;
    }
    __syncthreads();
    float scale = rsqrtf(sh[0] / (float)cols + eps);
    for (int i = threadIdx.x; i < cols; i += blockDim.x) {
        float v = xr[i] * scale * w[i];
        out[(size_t)row * cols + i] = do_round ? rtf32(v) : v;
    }
}

// ---------------- conv + silu ----------------
__global__ void conv_silu_k(const float* __restrict__ proj, const float* __restrict__ cw,
                            const float* __restrict__ cb, float* __restrict__ xbc) {
    int idx = blockIdx.x * blockDim.x + threadIdx.x;
    if (idx >= LMEM_ * CONVD_) return;
    int l = idx / CONVD_, c = idx % CONVD_;
    float acc = cb[c];
#pragma unroll
    for (int j = 0; j < CK_; j++) {
        int t = l + j - (CK_ - 1);
        if (t >= 0) acc += cw[c * CK_ + j] * proj[(size_t)t * NPROJ_ + INTER_ + c];
    }
    xbc[idx] = acc / (1.f + expf(-acc));
}

__global__ void dt_k(const float* __restrict__ proj, const float* __restrict__ dtb,
                     float* __restrict__ dt) {
    int idx = blockIdx.x * blockDim.x + threadIdx.x;
    if (idx >= LMEM_ * NH_) return;
    int l = idx / NH_, h = idx % NH_;
    float x = proj[(size_t)l * NPROJ_ + (INTER_ + CONVD_) + h] + dtb[h];
    dt[idx] = (x > 20.f) ? x : log1pf(expf(x));
}

// ---------------- mamba2 scan (R3 serial version — proven fastest) ----------------
__global__ void scan_k(const float* __restrict__ xbc, const float* __restrict__ dt,
                       const float* __restrict__ A_log, const float* __restrict__ Dp,
                       float* __restrict__ y) {
    int h = blockIdx.x;
    int tid = threadIdx.x;
    int g = h >> 2;
    float A  = -expf(A_log[h]);
    float Dh = Dp[h];
    __shared__ float Bs[2][S_], Cs[2][S_];
    float st[S_];
#pragma unroll
    for (int s = 0; s < S_; s++) st[s] = 0.f;

    float xv  = xbc[(size_t)0 * CONVD_ + h * HD_ + tid];
    float bv  = (tid < S_) ? xbc[INTER_ + g * S_ + tid]
                           : xbc[INTER_ + NG_ * S_ + g * S_ + (tid - S_)];
    float dtl = dt[h];

    for (int l = 0; l < LMEM_; l++) {
        int buf = l & 1;
        if (tid < S_) Bs[buf][tid] = bv; else Cs[buf][tid - S_] = bv;
        __syncthreads();
        float xn = 0.f, bn = 0.f, dtn = 0.f;
        if (l + 1 < LMEM_) {
            const float* nx = xbc + (size_t)(l + 1) * CONVD_;
            xn  = nx[h * HD_ + tid];
            bn  = (tid < S_) ? nx[INTER_ + g * S_ + tid]
                             : nx[INTER_ + NG_ * S_ + g * S_ + (tid - S_)];
            dtn = dt[(size_t)(l + 1) * NH_ + h];
        }
        float decay = expf(dtl * A);
        float dtx   = dtl * xv;
        float yv = 0.f;
#pragma unroll
        for (int s = 0; s < S_; s++) {
            st[s] = decay * st[s] + dtx * Bs[buf][s];
            yv += st[s] * Cs[buf][s];
        }
        yv += Dh * xv;
        y[(size_t)l * INTER_ + h * HD_ + tid] = yv;
        xv = xn; bv = bn; dtl = dtn;
    }
}

// ---------------- gated rmsnorm ----------------
__global__ void gatenorm_k(const float* __restrict__ y, const float* __restrict__ proj,
                           const float* __restrict__ mw, float* __restrict__ out) {
    int row = blockIdx.x;
    __shared__ float gsh[INTER_];
    __shared__ float sh[32];
    float ss = 0.f;
    for (int i = threadIdx.x; i < INTER_; i += blockDim.x) {
        float z  = proj[(size_t)row * NPROJ_ + i];
        float gv = y[(size_t)row * INTER_ + i] * (z / (1.f + expf(-z)));
        gsh[i] = gv;
        ss += gv * gv;
    }
#pragma unroll
    for (int o = 16; o; o >>= 1) ss += __shfl_xor_sync(0xFFFFFFFFu, ss, o);
    if ((threadIdx.x & 31) == 0) sh[threadIdx.x >> 5] = ss;
    __syncthreads();
    if (threadIdx.x < 32) {
        float v = (threadIdx.x < (blockDim.x >> 5)) ? sh[threadIdx.x] : 0.f;
#pragma unroll
        for (int o = 16; o; o >>= 1) v += __shfl_xor_sync(0xFFFFFFFFu, v, o);
        if (threadIdx.x == 0) sh[0] = v;
    }
    __syncthreads();
    float scale = rsqrtf(sh[0] / (float)INTER_ + MEPS_);
    for (int i = threadIdx.x; i < INTER_; i += blockDim.x)
        out[(size_t)row * INTER_ + i] = rtf32(gsh[i] * scale * mw[i]);
}

// ---------------- RoPE ----------------
__global__ void rope_q_k(float* __restrict__ q, const float* __restrict__ cosb,
                         const float* __restrict__ sinb) {
    int ri = blockIdx.y;
    int r = (ri < SINK_) ? ri : (T_ - WIN_) + (ri - SINK_);
    int i = blockIdx.x * blockDim.x + threadIdx.x;
    if (i >= NH_ * (HD_ / 2)) return;
    int hh = i >> 6, d = i & 63;
    float* qr = q + (size_t)r * (NH_ * HD_) + hh * HD_;
    float c0 = cosb[r * HD_ + d],      s0 = sinb[r * HD_ + d];
    float c1 = cosb[r * HD_ + d + 64], s1 = sinb[r * HD_ + d + 64];
    float a = qr[d], b = qr[d + 64];
    qr[d]      = a * c0 - b * s0;
    qr[d + 64] = b * c1 + a * s1;
}

__global__ void rope_k_k(float* __restrict__ k, const float* __restrict__ cosb,
                         const float* __restrict__ sinb) {
    int r = blockIdx.y;
    int i = threadIdx.x;
    if (i >= KVH_ * (HD_ / 2)) return;
    int hh = i >> 6, d = i & 63;
    float* kr = k + (size_t)r * (KVH_ * HD_) + hh * HD_;
    float c0 = cosb[r * HD_ + d],      s0 = sinb[r * HD_ + d];
    float c1 = cosb[r * HD_ + d + 64], s1 = sinb[r * HD_ + d + 64];
    float a = kr[d], b = kr[d + 64];
    kr[d]      = a * c0 - b * s0;
    kr[d + 64] = b * c1 + a * s1;
}

// ---------------- k/v row SINK replacement ----------------
__global__ void memact_kv_k(const float* __restrict__ merged,
                            const float* __restrict__ kw, const float* __restrict__ kb,
                            const float* __restrict__ vw, const float* __restrict__ vb,
                            float* __restrict__ kbuf, float* __restrict__ vbuf) {
    int p = blockIdx.x;
    const float* act = merged + (size_t)(SINK_ + LMEM_ - 1) * INTER_;
    int pp = (p < KVH_ * HD_) ? p : p - KVH_ * HD_;
    const float* W = (p < KVH_ * HD_) ? kw : vw;
    float bs       = (p < KVH_ * HD_) ? kb[pp] : vb[pp];
    float ss = 0.f;
    for (int i = threadIdx.x; i < H_; i += blockDim.x) ss += act[i] * W[(size_t)pp * H_ + i];
    __shared__ float sh[32];
#pragma unroll
    for (int o = 16; o; o >>= 1) ss += __shfl_xor_sync(0xFFFFFFFFu, ss, o);
    if ((threadIdx.x & 31) == 0) sh[threadIdx.x >> 5] = ss;
    __syncthreads();
    if (threadIdx.x == 0) {
        float v = 0.f;
        for (int w = 0; w < (int)(blockDim.x >> 5); w++) v += sh[w];
        v += bs;
        if (p < KVH_ * HD_) kbuf[(size_t)SINK_ * (KVH_ * HD_) + pp] = v;
        else                vbuf[(size_t)SINK_ * (KVH_ * HD_) + pp] = v;
    }
}

// ---------------- attention ----------------
__global__ void attn_k(const float* __restrict__ q, const float* __restrict__ k,
                       const float* __restrict__ v, float* __restrict__ merged) {
    int wid_g = blockIdx.x * (blockDim.x >> 5) + (threadIdx.x >> 5);
    if (wid_g >= (SINK_ + WIN_) * NH_) return;
    int lane = threadIdx.x & 31;
    int ri = wid_g >> 4;
    int h  = wid_g & 15;
    int r  = (ri < SINK_) ? ri : (T_ - WIN_) + (ri - SINK_);
    int g  = h >> 2;
    const float4 q4 = *(const float4*)(q + (size_t)r * (NH_ * HD_) + h * HD_ + lane * 4);
    const float scale = 0.08838834764831845f;
    const float sink_bonus = 0.5f * (float)(T_ - SINK_ - WIN_) / (float)T_;
    float mmax = -1e30f, denom = 0.f;
    float4 acc = make_float4(0.f, 0.f, 0.f, 0.f);

    for (int seg = 0; seg < 2; seg++) {
        int cbeg = seg ? max(SINK_ + 1, r - WIN_) : 0;
        int cend = seg ? r : min(r, SINK_);
        for (int c = cbeg; c <= cend; c++) {
            const float4 k4 = *(const float4*)(k + (size_t)c * (KVH_ * HD_) + g * HD_ + lane * 4);
            float s = q4.x * k4.x + q4.y * k4.y + q4.z * k4.z + q4.w * k4.w;
#pragma unroll
            for (int o = 16; o; o >>= 1) s += __shfl_xor_sync(0xFFFFFFFFu, s, o);
            s = s * scale + ((c == SINK_) ? sink_bonus : 0.f);
            float mn = fmaxf(mmax, s);
            float corr = expf(mmax - mn);
            float p = expf(s - mn);
            mmax = mn;
            denom = denom * corr + p;
            const float4 v4 = *(const float4*)(v + (size_t)c * (KVH_ * HD_) + g * HD_ + lane * 4);
            acc.x = acc.x * corr + p * v4.x;
            acc.y = acc.y * corr + p * v4.y;
            acc.z = acc.z * corr + p * v4.z;
            acc.w = acc.w * corr + p * v4.w;
        }
    }
    float inv = 1.f / denom;
    float4 o4;
    o4.x = rtf32(acc.x * inv); o4.y = rtf32(acc.y * inv);
    o4.z = rtf32(acc.z * inv); o4.w = rtf32(acc.w * inv);
    *(float4*)(merged + (size_t)r * INTER_ + h * HD_ + lane * 4) = o4;
}

// ---------------- elementwise ----------------
__global__ void swiglu_fused_k(const float* __restrict__ gu, float* __restrict__ o) {
    int i = blockIdx.x * blockDim.x + threadIdx.x;
    if (i >= T_ * MLPI_) return;
    int row = i / MLPI_, c = i % MLPI_;
    float x = gu[(size_t)row * (2 * MLPI_) + c];
    float u = gu[(size_t)row * (2 * MLPI_) + MLPI_ + c];
    o[i] = rtf32((x / (1.f + expf(-x))) * u);
}

// ---------------- host ----------------
typedef CUresult (*PFN_encodeTiled)(CUtensorMap*, CUtensorMapDataType, cuuint32_t, void*,
                                    const cuuint64_t*, const cuuint64_t*, const cuuint32_t*,
                                    const cuuint32_t*, CUtensorMapInterleave, CUtensorMapSwizzle,
                                    CUtensorMapL2promotion, CUtensorMapFloatOOBfill);

static PFN_encodeTiled get_encoder() {
    void* p = nullptr;
    cudaDriverEntryPointQueryResult st;
    cudaGetDriverEntryPointByVersion("cuTensorMapEncodeTiled", &p, 12000, cudaEnableDefault, &st);
    return (PFN_encodeTiled)p;
}

static void make_tm(PFN_encodeTiled enc, CUtensorMap* tm, const float* base,
                    int rows, int cols, int box_rows) {
    cuuint64_t dims[2]    = {(cuuint64_t)cols, (cuuint64_t)rows};
    cuuint64_t strides[1] = {(cuuint64_t)cols * 4};
    cuuint32_t box[2]     = {32u, (cuuint32_t)box_rows};
    cuuint32_t es[2]      = {1u, 1u};
    enc(tm, CU_TENSOR_MAP_DATA_TYPE_FLOAT32, 2, (void*)base, dims, strides, box, es,
        CU_TENSOR_MAP_INTERLEAVE_NONE, CU_TENSOR_MAP_SWIZZLE_128B,
        CU_TENSOR_MAP_L2_PROMOTION_L2_128B, CU_TENSOR_MAP_FLOAT_OOB_FILL_NONE);
}

static PFN_encodeTiled g_enc = nullptr;

static void launch_gemm_tc(const float* A, const float* B,
                           const float* bias, const float* res, float* C,
                           int M, int N, int K, bool roundOut) {
    CUtensorMap tmA, tmB;
    make_tm(g_enc, &tmA, A, M, K, 128);
    make_tm(g_enc, &tmB, B, N, K, 256);
    dim3 grid((N + GBN - 1) / GBN, (M + GBM - 1) / GBM);
    if (roundOut) gemm_tc<true><<<grid, 128, GSMEM>>>(tmA, tmB, A, B, bias, res, C, M, N, K);
    else          gemm_tc<false><<<grid, 128, GSMEM>>>(tmA, tmB, A, B, bias, res, C, M, N, K);
}

static void roundw(const float* src, float* dst, int n) {
    int n4 = n / 4;
    roundw_k<<<(n4 + 255) / 256, 256>>>(src, dst, n4);
}

extern "C" void kernel_launch(void* const* d_in, const int* in_sizes, int n_in,
                              void* d_out, int out_size) {
    const float* hs      = (const float*)d_in[0];
    const float* cosb    = (const float*)d_in[1];
    const float* sinb    = (const float*)d_in[2];
    const float* ln1_w   = (const float*)d_in[3];
    const float* q_w     = (const float*)d_in[4];
    const float* q_b     = (const float*)d_in[5];
    const float* k_w     = (const float*)d_in[6];
    const float* k_b     = (const float*)d_in[7];
    const float* v_w     = (const float*)d_in[8];
    const float* v_b     = (const float*)d_in[9];
    const float* o_w     = (const float*)d_in[10];
    const float* inpj_w  = (const float*)d_in[11];
    const float* conv_w  = (const float*)d_in[12];
    const float* conv_b  = (const float*)d_in[13];
    const float* dt_bias = (const float*)d_in[14];
    const float* A_log   = (const float*)d_in[15];
    const float* Dp      = (const float*)d_in[16];
    const float* mnorm_w = (const float*)d_in[17];
    const float* outp_w  = (const float*)d_in[18];
    const float* ln2_w   = (const float*)d_in[19];
    const float* gate_w  = (const float*)d_in[20];
    const float* up_w    = (const float*)d_in[21];
    const float* down_w  = (const float*)d_in[22];
    float* out = (float*)d_out;

    float *pre, *proj, *xbc, *dtb, *ybuf, *gbuf, *qb, *kb, *vb, *merged, *hb, *mb, *gub, *gateb;
    float *wq, *wk, *wv, *wo, *win, *wout, *wgu, *wd;
    cudaGetSymbolAddress((void**)&pre,    g_pre);
    cudaGetSymbolAddress((void**)&proj,   g_proj);
    cudaGetSymbolAddress((void**)&xbc,    g_xbc);
    cudaGetSymbolAddress((void**)&dtb,    g_dt);
    cudaGetSymbolAddress((void**)&ybuf,   g_y);
    cudaGetSymbolAddress((void**)&gbuf,   g_g);
    cudaGetSymbolAddress((void**)&qb,     g_q);
    cudaGetSymbolAddress((void**)&kb,     g_k);
    cudaGetSymbolAddress((void**)&vb,     g_v);
    cudaGetSymbolAddress((void**)&merged, g_merged);
    cudaGetSymbolAddress((void**)&hb,     g_h);
    cudaGetSymbolAddress((void**)&mb,     g_m);
    cudaGetSymbolAddress((void**)&gub,    g_gu);
    cudaGetSymbolAddress((void**)&gateb,  g_gate);
    cudaGetSymbolAddress((void**)&wq,     g_wq);
    cudaGetSymbolAddress((void**)&wk,     g_wk);
    cudaGetSymbolAddress((void**)&wv,     g_wv);
    cudaGetSymbolAddress((void**)&wo,     g_wo);
    cudaGetSymbolAddress((void**)&win,    g_win);
    cudaGetSymbolAddress((void**)&wout,   g_wout);
    cudaGetSymbolAddress((void**)&wgu,    g_wgu);
    cudaGetSymbolAddress((void**)&wd,     g_wd);

    if (!g_enc) g_enc = get_encoder();
    static bool attrs_set = false;
    if (!attrs_set) {
        cudaFuncSetAttribute(gemm_tc<false>, cudaFuncAttributeMaxDynamicSharedMemorySize, GSMEM);
        cudaFuncSetAttribute(gemm_tc<true>,  cudaFuncAttributeMaxDynamicSharedMemorySize, GSMEM);
        attrs_set = true;
    }

    // 0. round weights to tf32 (unbiased rna); gate|up concatenated
    roundw(q_w,    wq,   NH_ * HD_ * H_);
    roundw(k_w,    wk,   KVH_ * HD_ * H_);
    roundw(v_w,    wv,   KVH_ * HD_ * H_);
    roundw(o_w,    wo,   H_ * NH_ * HD_);
    roundw(inpj_w, win,  NPROJ_ * H_);
    roundw(outp_w, wout, H_ * INTER_);
    roundw(gate_w, wgu,                       MLPI_ * H_);
    roundw(up_w,   wgu + (size_t)MLPI_ * H_,  MLPI_ * H_);
    roundw(down_w, wd,   H_ * MLPI_);

    // 1. pre-norm (tf32-rounded: feeds GEMMs only)
    rmsnorm_k<<<T_, 256>>>(hs, ln1_w, pre, H_, EPS_, 1);

    // 2. mamba branch on pre rows [64, 1536)
    launch_gemm_tc(pre + (size_t)SINK_ * H_, win, nullptr, nullptr, proj, LMEM_, NPROJ_, H_, false);
    conv_silu_k<<<(LMEM_ * CONVD_ + 255) / 256, 256>>>(proj, conv_w, conv_b, xbc);
    dt_k<<<(LMEM_ * NH_ + 255) / 256, 256>>>(proj, dt_bias, dtb);
    scan_k<<<NH_, 128>>>(xbc, dtb, A_log, Dp, ybuf);
    gatenorm_k<<<LMEM_, 256>>>(ybuf, proj, mnorm_w, gbuf);
    launch_gemm_tc(gbuf, wout, nullptr, nullptr, merged + (size_t)SINK_ * INTER_, LMEM_, INTER_, H_, true);

    // 3. q projection on consumed rows only; full k/v
    launch_gemm_tc(pre, wq, q_b, nullptr, qb, SINK_, NH_ * HD_, H_, false);
    launch_gemm_tc(pre + (size_t)(T_ - WIN_) * H_, wq, q_b, nullptr,
                   qb + (size_t)(T_ - WIN_) * (NH_ * HD_), WIN_, NH_ * HD_, H_, false);
    launch_gemm_tc(pre, wk, k_b, nullptr, kb, T_, KVH_ * HD_, H_, false);
    launch_gemm_tc(pre, wv, v_b, nullptr, vb, T_, KVH_ * HD_, H_, false);

    // 4. RoPE
    rope_q_k<<<dim3(4, SINK_ + WIN_), 256>>>(qb, cosb, sinb);
    rope_k_k<<<dim3(1, T_), 256>>>(kb, cosb, sinb);

    // 5. replace k/v at row SINK with mem_act projection (exact fp32 GEMV)
    memact_kv_k<<<2 * KVH_ * HD_, 256>>>(merged, k_w, k_b, v_w, v_b, kb, vb);

    // 6. attention -> merged rows [0,64) and [1536,2048)
    attn_k<<<((SINK_ + WIN_) * NH_ + 7) / 8, 256>>>(qb, kb, vb, merged);

    // 7. o projection + FUSED residual -> hb  (removes add_k pass)
    launch_gemm_tc(merged, wo, nullptr, hs, hb, T_, H_, NH_ * HD_, false);

    // 8. MLP (gate+up fused); down-proj + FUSED residual -> out
    rmsnorm_k<<<T_, 256>>>(hb, ln2_w, mb, H_, EPS_, 1);
    launch_gemm_tc(mb, wgu, nullptr, nullptr, gub, T_, 2 * MLPI_, H_, false);
    swiglu_fused_k<<<(T_ * MLPI_ + 255) / 256, 256>>>(gub, gateb);
    launch_gemm_tc(gateb, wd, nullptr, hb, out, T_, H_, MLPI_, false);
}

// round 13
// speedup vs baseline: 1.0787x; 1.0332x over previous
#include <cuda_runtime.h>
#include <cuda.h>
#include <cuda_bf16.h>
#include <math.h>
#include <stdint.h>

// ---------------- constants ----------------
#define T_      2048
#define H_      2048
#define NH_     16
#define KVH_    4
#define HD_     128
#define WIN_    512
#define SINK_   64
#define S_      64
#define NG_     4
#define MLPI_   5504
#define CK_     4
#define INTER_  2048
#define CONVD_  2560
#define NPROJ_  4624
#define LMEM_   1472
#define EPS_    1e-6f
#define MEPS_   1e-5f

// ---------------- scratch ----------------
__device__ float g_pre   [T_ * H_];
__device__ float g_proj  [LMEM_ * NPROJ_];
__device__ float g_xbc   [LMEM_ * CONVD_];
__device__ float g_dt    [LMEM_ * NH_];
__device__ float g_y     [LMEM_ * INTER_];
__device__ float g_g     [LMEM_ * INTER_];
__device__ float g_q     [T_ * (NH_ * HD_)];
__device__ float g_k     [T_ * (KVH_ * HD_)];
__device__ float g_v     [T_ * (KVH_ * HD_)];
__device__ float g_merged[T_ * INTER_];
__device__ float g_h     [T_ * H_];
__device__ float g_m     [T_ * H_];
__device__ float g_gu    [T_ * 2 * MLPI_];
__device__ float g_gate  [T_ * MLPI_];
// tf32-rounded weight copies
__device__ float g_wq  [(NH_*HD_) * H_];
__device__ float g_wk  [(KVH_*HD_) * H_];
__device__ float g_wv  [(KVH_*HD_) * H_];
__device__ float g_wo  [H_ * (NH_*HD_)];
__device__ float g_win [NPROJ_ * H_];
__device__ float g_wout[H_ * INTER_];
__device__ float g_wgu [2 * MLPI_ * H_];
__device__ float g_wd  [H_ * MLPI_];

// ---------------- ptx helpers (baseline-safe) ----------------
__device__ __forceinline__ uint32_t smem_u32(const void* p) {
    uint32_t a;
    asm("{ .reg .u64 t; cvta.to.shared.u64 t, %1; cvt.u32.u64 %0, t; }" : "=r"(a) : "l"(p));
    return a;
}
__device__ __forceinline__ float rtf32(float x) {
    float y; asm("cvt.rna.tf32.f32 %0, %1;" : "=f"(y) : "f"(x)); return y;
}

#define MBARRIER_INIT(addr, cnt) \
    asm volatile("mbarrier.init.shared.b64 [%0], %1;" :: "r"((uint32_t)(addr)), "r"((uint32_t)(cnt)) : "memory")
#define MBARRIER_EXPECT_TX(addr, bytes) \
    asm volatile("mbarrier.arrive.expect_tx.shared.b64 _, [%0], %1;" :: "r"((uint32_t)(addr)), "r"((uint32_t)(bytes)) : "memory")
#define MBARRIER_WAIT_PARITY(addr, ph) do { \
    uint32_t _m = (uint32_t)(addr); uint32_t _p = (uint32_t)(ph); uint32_t _d; \
    asm volatile("{\n\t.reg .pred p;\n\t" \
        "mbarrier.try_wait.parity.acquire.cta.shared::cta.b64 p, [%1], %2;\n\t" \
        "selp.b32 %0, 1, 0, p;\n\t}" : "=r"(_d) : "r"(_m), "r"(_p) : "memory"); \
    if (!_d) { asm volatile("{\n\t.reg .pred P1;\n\t" \
        "WL_%=:\n\t" \
        "mbarrier.try_wait.parity.acquire.cta.shared::cta.b64 P1, [%0], %1, 0x989680;\n\t" \
        "@P1 bra.uni WD_%=;\n\tbra.uni WL_%=;\n\tWD_%=:\n\t}" \
        :: "r"(_m), "r"(_p) : "memory"); } \
} while (0)

__device__ __forceinline__ void tma2d(uint32_t smem, const void* tm, int x, int y, uint32_t mbar) {
    asm volatile("cp.async.bulk.tensor.2d.shared::cta.global.tile.mbarrier::complete_tx::bytes "
                 "[%0], [%1, {%2, %3}], [%4];"
                 :: "r"(smem), "l"(tm), "r"(x), "r"(y), "r"(mbar) : "memory");
}

// ---------------- tcgen05 (arch-specific: sm_103a pass only) ----------------
#if defined(__CUDA_ARCH_FEAT_SM103_ALL)
#define HAS_TCGEN05 1

#define TCGEN05_ALLOC(smem_addr, nCols) \
    asm volatile("tcgen05.alloc.cta_group::1.sync.aligned.shared::cta.b32 [%0], %1;" \
        :: "r"((uint32_t)(smem_addr)), "r"((uint32_t)(nCols)) : "memory")
#define TCGEN05_DEALLOC(tmem, nCols) \
    asm volatile("tcgen05.dealloc.cta_group::1.sync.aligned.b32 %0, %1;" :: "r"(tmem), "r"((uint32_t)(nCols)))
#define TCGEN05_COMMIT(mbar) \
    asm volatile("tcgen05.commit.cta_group::1.mbarrier::arrive::one.shared::cluster.b64 [%0];" \
        :: "r"((uint32_t)(mbar)) : "memory")
#define TCGEN05_FENCE_AFTER() asm volatile("tcgen05.fence::after_thread_sync;" ::: "memory")
#define TCGEN05_WAIT_LD() asm volatile("tcgen05.wait::ld.sync.aligned;" ::: "memory")

#define TCGEN05_LD_32X32B_X32(r, tmem_addr) \
    asm volatile("tcgen05.ld.sync.aligned.32x32b.x32.b32 " \
        "{%0, %1, %2, %3, %4, %5, %6, %7, %8, %9, %10, %11, %12, %13, %14, %15, " \
        " %16, %17, %18, %19, %20, %21, %22, %23, %24, %25, %26, %27, %28, %29, %30, %31}, [%32];" \
        : "=r"((r)[0]),  "=r"((r)[1]),  "=r"((r)[2]),  "=r"((r)[3]), \
          "=r"((r)[4]),  "=r"((r)[5]),  "=r"((r)[6]),  "=r"((r)[7]), \
          "=r"((r)[8]),  "=r"((r)[9]),  "=r"((r)[10]), "=r"((r)[11]), \
          "=r"((r)[12]), "=r"((r)[13]), "=r"((r)[14]), "=r"((r)[15]), \
          "=r"((r)[16]), "=r"((r)[17]), "=r"((r)[18]), "=r"((r)[19]), \
          "=r"((r)[20]), "=r"((r)[21]), "=r"((r)[22]), "=r"((r)[23]), \
          "=r"((r)[24]), "=r"((r)[25]), "=r"((r)[26]), "=r"((r)[27]), \
          "=r"((r)[28]), "=r"((r)[29]), "=r"((r)[30]), "=r"((r)[31]) \
        : "r"(tmem_addr))

__device__ __forceinline__ void mma_tf32_ss(uint32_t d, uint64_t ad, uint64_t bd,
                                            uint32_t idesc, uint32_t en) {
    asm volatile("{\n\t.reg .pred p;\n\tsetp.ne.u32 p, %4, 0;\n\t"
                 "tcgen05.mma.cta_group::1.kind::tf32 [%0], %1, %2, %3, {%5, %5, %5, %5}, p;\n\t}"
                 :: "r"(d), "l"(ad), "l"(bd), "r"(idesc), "r"(en), "r"(0u) : "memory");
}
#endif

// SW128 K-major SMEM descriptor (LBO=1, SBO=64, version=1)
static constexpr uint64_t SMEM_DESC_BASE_SW128 =
    (uint64_t(2) << 61) | (uint64_t(1) << 46) | (uint64_t(64) << 32) | (uint64_t(1) << 16);
#define MAKE_SMEM_DESC(base_addr) (SMEM_DESC_BASE_SW128 | ((uint64_t)((base_addr) >> 4) & 0x3FFF))

// ---------------- tcgen05 tf32 GEMM: C[M,N] = A[M,K] * B[N,K]^T (+bias) (+res) ----------------
#define GBM 128
#define GBN 256
#define GBK 32
#define GDEPTH 4
#define SM_A_OFF 1024
#define SM_B_OFF (1024 + GDEPTH * 16384)
#define GSMEM (1024 + GDEPTH * 16384 + GDEPTH * 32768)

template<bool ROUND>
__global__ void __launch_bounds__(128, 1)
gemm_tc(const __grid_constant__ CUtensorMap tmA,
        const __grid_constant__ CUtensorMap tmB,
        const float* __restrict__ Araw, const float* __restrict__ Braw,
        const float* __restrict__ bias, const float* __restrict__ res,
        float* __restrict__ C, int M, int N, int K) {
#if defined(HAS_TCGEN05)
    extern __shared__ __align__(1024) char smem[];
    uint32_t sb = smem_u32(smem);
    int tid = threadIdx.x, wid = tid >> 5, lane = tid & 31;
    int m0 = blockIdx.y * GBM, n0 = blockIdx.x * GBN;

    if (wid == 0) TCGEN05_ALLOC(sb + 0, 256);
    if (tid == 0) {
        for (int s = 0; s < GDEPTH; s++) {
            MBARRIER_INIT(sb + 8 + s * 16, 1);       // full
            MBARRIER_INIT(sb + 8 + s * 16 + 8, 1);   // empty
        }
    }
    __syncthreads();
    uint32_t tmem;
    asm volatile("ld.shared.b32 %0, [%1];" : "=r"(tmem) : "r"(sb + 0));

    int nst = K / GBK;
    if (tid == 0) {
        int pre = nst < GDEPTH ? nst : GDEPTH;
        for (int s = 0; s < pre; s++) {
            uint32_t full = sb + 8 + s * 16;
            MBARRIER_EXPECT_TX(full, 49152);
            tma2d(sb + SM_A_OFF + s * 16384, &tmA, s * GBK, m0, full);
            tma2d(sb + SM_B_OFF + s * 32768, &tmB, s * GBK, n0, full);
        }
        const uint32_t idesc = (1u << 4) | (2u << 7) | (2u << 10) |
                               ((GBN / 8) << 17) | ((GBM / 16) << 24);
        for (int s = 0; s < nst; s++) {
            int slot = s & (GDEPTH - 1);
            int ph = (s / GDEPTH) & 1;
            uint32_t full = sb + 8 + slot * 16;
            uint32_t empty = full + 8;
            MBARRIER_WAIT_PARITY(full, ph);
            uint64_t ad = MAKE_SMEM_DESC(sb + SM_A_OFF + slot * 16384);
            uint64_t bd = MAKE_SMEM_DESC(sb + SM_B_OFF + slot * 32768);
#pragma unroll
            for (int kk = 0; kk < 4; kk++)
                mma_tf32_ss(tmem, ad + kk * 2, bd + kk * 2, idesc,
                            (s > 0 || kk > 0) ? 1u : 0u);
            TCGEN05_COMMIT(empty);
            if (s > 0) {
                int rs = s - 1 + GDEPTH;
                if (rs < nst) {
                    int rslot = (s - 1) & (GDEPTH - 1);
                    int rph = ((s - 1) / GDEPTH) & 1;
                    uint32_t rfull = sb + 8 + rslot * 16;
                    MBARRIER_WAIT_PARITY(rfull + 8, rph);
                    MBARRIER_EXPECT_TX(rfull, 49152);
                    tma2d(sb + SM_A_OFF + rslot * 16384, &tmA, rs * GBK, m0, rfull);
                    tma2d(sb + SM_B_OFF + rslot * 32768, &tmB, rs * GBK, n0, rfull);
                }
            }
        }
        int ls = nst - 1;
        MBARRIER_WAIT_PARITY(sb + 8 + (ls & (GDEPTH - 1)) * 16 + 8, (ls / GDEPTH) & 1);
    }
    __syncthreads();
    TCGEN05_FENCE_AFTER();

    int m = m0 + wid * 32 + lane;
    bool mok = (m < M);
#pragma unroll 1
    for (int b = 0; b < 8; b++) {
        uint32_t r[32];
        TCGEN05_LD_32X32B_X32(r, tmem + b * 32);
        TCGEN05_WAIT_LD();
        if (mok) {
            float* crow = C + (size_t)m * N;
#pragma unroll
            for (int j4 = 0; j4 < 8; j4++) {
                int c = n0 + b * 32 + j4 * 4;
                if (c < N) {
                    float4 v;
                    v.x = __uint_as_float(r[j4 * 4 + 0]);
                    v.y = __uint_as_float(r[j4 * 4 + 1]);
                    v.z = __uint_as_float(r[j4 * 4 + 2]);
                    v.w = __uint_as_float(r[j4 * 4 + 3]);
                    if (bias) {
                        float4 bb = *(const float4*)(bias + c);
                        v.x += bb.x; v.y += bb.y; v.z += bb.z; v.w += bb.w;
                    }
                    if (res) {
                        float4 rr = *(const float4*)(res + (size_t)m * N + c);
                        v.x += rr.x; v.y += rr.y; v.z += rr.z; v.w += rr.w;
                    }
                    if (ROUND) {
                        v.x = rtf32(v.x); v.y = rtf32(v.y);
                        v.z = rtf32(v.z); v.w = rtf32(v.w);
                    }
                    *(float4*)(crow + c) = v;
                }
            }
        }
    }
    __syncthreads();
    if (wid == 0) TCGEN05_DEALLOC(tmem, 256);
#else
    // Fallback for the generic compute_103 PTX pass (never run on GB300).
    int m0 = blockIdx.y * GBM, n0 = blockIdx.x * GBN;
    for (int idx = threadIdx.x; idx < GBM * GBN; idx += blockDim.x) {
        int mi = idx / GBN, ni = idx % GBN;
        int m = m0 + mi, n = n0 + ni;
        if (m < M && n < N) {
            const float* a = Araw + (size_t)m * K;
            const float* b = Braw + (size_t)n * K;
            float acc = 0.f;
            for (int k = 0; k < K; k++) acc += a[k] * b[k];
            if (bias) acc += bias[n];
            if (res) acc += res[(size_t)m * N + n];
            if (ROUND) acc = rtf32(acc);
            C[(size_t)m * N + n] = acc;
        }
    }
#endif
}

// ---------------- weight rounding ----------------
__global__ void roundw_k(const float* __restrict__ src, float* __restrict__ dst, int n4) {
    int i = blockIdx.x * blockDim.x + threadIdx.x;
    if (i < n4) {
        float4 v = ((const float4*)src)[i];
        v.x = rtf32(v.x); v.y = rtf32(v.y); v.z = rtf32(v.z); v.w = rtf32(v.w);
        ((float4*)dst)[i] = v;
    }
}

// ---------------- rmsnorm ----------------
__global__ void rmsnorm_k(const float* __restrict__ x, const float* __restrict__ w,
                          float* __restrict__ out, int cols, float eps, int do_round) {
    int row = blockIdx.x;
    const float* xr = x + (size_t)row * cols;
    float ss = 0.f;
    for (int i = threadIdx.x; i < cols; i += blockDim.x) { float v = xr[i]; ss += v * v; }
    __shared__ float sh[32];
#pragma unroll
    for (int o = 16; o; o >>= 1) ss += __shfl_xor_sync(0xFFFFFFFFu, ss, o);
    if ((threadIdx.x & 31) == 0) sh[threadIdx.x >> 5] = ss;
    __syncthreads();
    if (threadIdx.x < 32) {
        float v = (threadIdx.x < (blockDim.x >> 5)) ? sh[threadIdx.x] : 0.f;
#pragma unroll
        for (int o = 16; o; o >>= 1) v += __shfl_xor_sync(0xFFFFFFFFu, v, o);
        if (threadIdx.x == 0) sh[0] = v;
    }
    __syncthreads();
    float scale = rsqrtf(sh[0] / (float)cols + eps);
    for (int i = threadIdx.x; i < cols; i += blockDim.x) {
        float v = xr[i] * scale * w[i];
        out[(size_t)row * cols + i] = do_round ? rtf32(v) : v;
    }
}

// ---------------- conv + silu ----------------
__global__ void conv_silu_k(const float* __restrict__ proj, const float* __restrict__ cw,
                            const float* __restrict__ cb, float* __restrict__ xbc) {
    int idx = blockIdx.x * blockDim.x + threadIdx.x;
    if (idx >= LMEM_ * CONVD_) return;
    int l = idx / CONVD_, c = idx % CONVD_;
    float acc = cb[c];
#pragma unroll
    for (int j = 0; j < CK_; j++) {
        int t = l + j - (CK_ - 1);
        if (t >= 0) acc += cw[c * CK_ + j] * proj[(size_t)t * NPROJ_ + INTER_ + c];
    }
    xbc[idx] = acc / (1.f + expf(-acc));
}

__global__ void dt_k(const float* __restrict__ proj, const float* __restrict__ dtb,
                     float* __restrict__ dt) {
    int idx = blockIdx.x * blockDim.x + threadIdx.x;
    if (idx >= LMEM_ * NH_) return;
    int l = idx / NH_, h = idx % NH_;
    float x = proj[(size_t)l * NPROJ_ + (INTER_ + CONVD_) + h] + dtb[h];
    dt[idx] = (x > 20.f) ? x : log1pf(expf(x));
}

// ---------------- mamba2 scan (R3 serial version — proven fastest) ----------------
__global__ void scan_k(const float* __restrict__ xbc, const float* __restrict__ dt,
                       const float* __restrict__ A_log, const float* __restrict__ Dp,
                       float* __restrict__ y) {
    int h = blockIdx.x;
    int tid = threadIdx.x;
    int g = h >> 2;
    float A  = -expf(A_log[h]);
    float Dh = Dp[h];
    __shared__ float Bs[2][S_], Cs[2][S_];
    float st[S_];
#pragma unroll
    for (int s = 0; s < S_; s++) st[s] = 0.f;

    float xv  = xbc[(size_t)0 * CONVD_ + h * HD_ + tid];
    float bv  = (tid < S_) ? xbc[INTER_ + g * S_ + tid]
                           : xbc[INTER_ + NG_ * S_ + g * S_ + (tid - S_)];
    float dtl = dt[h];

    for (int l = 0; l < LMEM_; l++) {
        int buf = l & 1;
        if (tid < S_) Bs[buf][tid] = bv; else Cs[buf][tid - S_] = bv;
        __syncthreads();
        float xn = 0.f, bn = 0.f, dtn = 0.f;
        if (l + 1 < LMEM_) {
            const float* nx = xbc + (size_t)(l + 1) * CONVD_;
            xn  = nx[h * HD_ + tid];
            bn  = (tid < S_) ? nx[INTER_ + g * S_ + tid]
                             : nx[INTER_ + NG_ * S_ + g * S_ + (tid - S_)];
            dtn = dt[(size_t)(l + 1) * NH_ + h];
        }
        float decay = expf(dtl * A);
        float dtx   = dtl * xv;
        float yv = 0.f;
#pragma unroll
        for (int s = 0; s < S_; s++) {
            st[s] = decay * st[s] + dtx * Bs[buf][s];
            yv += st[s] * Cs[buf][s];
        }
        yv += Dh * xv;
        y[(size_t)l * INTER_ + h * HD_ + tid] = yv;
        xv = xn; bv = bn; dtl = dtn;
    }
}

// ---------------- gated rmsnorm ----------------
__global__ void gatenorm_k(const float* __restrict__ y, const float* __restrict__ proj,
                           const float* __restrict__ mw, float* __restrict__ out) {
    int row = blockIdx.x;
    __shared__ float gsh[INTER_];
    __shared__ float sh[32];
    float ss = 0.f;
    for (int i = threadIdx.x; i < INTER_; i += blockDim.x) {
        float z  = proj[(size_t)row * NPROJ_ + i];
        float gv = y[(size_t)row * INTER_ + i] * (z / (1.f + expf(-z)));
        gsh[i] = gv;
        ss += gv * gv;
    }
#pragma unroll
    for (int o = 16; o; o >>= 1) ss += __shfl_xor_sync(0xFFFFFFFFu, ss, o);
    if ((threadIdx.x & 31) == 0) sh[threadIdx.x >> 5] = ss;
    __syncthreads();
    if (threadIdx.x < 32) {
        float v = (threadIdx.x < (blockDim.x >> 5)) ? sh[threadIdx.x] : 0.f;
#pragma unroll
        for (int o = 16; o; o >>= 1) v += __shfl_xor_sync(0xFFFFFFFFu, v, o);
        if (threadIdx.x == 0) sh[0] = v;
    }
    __syncthreads();
    float scale = rsqrtf(sh[0] / (float)INTER_ + MEPS_);
    for (int i = threadIdx.x; i < INTER_; i += blockDim.x)
        out[(size_t)row * INTER_ + i] = rtf32(gsh[i] * scale * mw[i]);
}

// ---------------- RoPE ----------------
__global__ void rope_q_k(float* __restrict__ q, const float* __restrict__ cosb,
                         const float* __restrict__ sinb) {
    int ri = blockIdx.y;
    int r = (ri < SINK_) ? ri : (T_ - WIN_) + (ri - SINK_);
    int i = blockIdx.x * blockDim.x + threadIdx.x;
    if (i >= NH_ * (HD_ / 2)) return;
    int hh = i >> 6, d = i & 63;
    float* qr = q + (size_t)r * (NH_ * HD_) + hh * HD_;
    float c0 = cosb[r * HD_ + d],      s0 = sinb[r * HD_ + d];
    float c1 = cosb[r * HD_ + d + 64], s1 = sinb[r * HD_ + d + 64];
    float a = qr[d], b = qr[d + 64];
    qr[d]      = a * c0 - b * s0;
    qr[d + 64] = b * c1 + a * s1;
}

__global__ void rope_k_k(float* __restrict__ k, const float* __restrict__ cosb,
                         const float* __restrict__ sinb) {
    int r = blockIdx.y;
    int i = threadIdx.x;
    if (i >= KVH_ * (HD_ / 2)) return;
    int hh = i >> 6, d = i & 63;
    float* kr = k + (size_t)r * (KVH_ * HD_) + hh * HD_;
    float c0 = cosb[r * HD_ + d],      s0 = sinb[r * HD_ + d];
    float c1 = cosb[r * HD_ + d + 64], s1 = sinb[r * HD_ + d + 64];
    float a = kr[d], b = kr[d + 64];
    kr[d]      = a * c0 - b * s0;
    kr[d + 64] = b * c1 + a * s1;
}

// ---------------- k/v row SINK replacement ----------------
__global__ void memact_kv_k(const float* __restrict__ merged,
                            const float* __restrict__ kw, const float* __restrict__ kb,
                            const float* __restrict__ vw, const float* __restrict__ vb,
                            float* __restrict__ kbuf, float* __restrict__ vbuf) {
    int p = blockIdx.x;
    const float* act = merged + (size_t)(SINK_ + LMEM_ - 1) * INTER_;
    int pp = (p < KVH_ * HD_) ? p : p - KVH_ * HD_;
    const float* W = (p < KVH_ * HD_) ? kw : vw;
    float bs       = (p < KVH_ * HD_) ? kb[pp] : vb[pp];
    float ss = 0.f;
    for (int i = threadIdx.x; i < H_; i += blockDim.x) ss += act[i] * W[(size_t)pp * H_ + i];
    __shared__ float sh[32];
#pragma unroll
    for (int o = 16; o; o >>= 1) ss += __shfl_xor_sync(0xFFFFFFFFu, ss, o);
    if ((threadIdx.x & 31) == 0) sh[threadIdx.x >> 5] = ss;
    __syncthreads();
    if (threadIdx.x == 0) {
        float v = 0.f;
        for (int w = 0; w < (int)(blockDim.x >> 5); w++) v += sh[w];
        v += bs;
        if (p < KVH_ * HD_) kbuf[(size_t)SINK_ * (KVH_ * HD_) + pp] = v;
        else                vbuf[(size_t)SINK_ * (KVH_ * HD_) + pp] = v;
    }
}

// ---------------- attention: 2-key ILP online softmax ----------------
__global__ void attn_k(const float* __restrict__ q, const float* __restrict__ k,
                       const float* __restrict__ v, float* __restrict__ merged) {
    int wid_g = blockIdx.x * (blockDim.x >> 5) + (threadIdx.x >> 5);
    if (wid_g >= (SINK_ + WIN_) * NH_) return;
    int lane = threadIdx.x & 31;
    int ri = wid_g >> 4;
    int h  = wid_g & 15;
    int r  = (ri < SINK_) ? ri : (T_ - WIN_) + (ri - SINK_);
    int g  = h >> 2;
    const float4 q4 = *(const float4*)(q + (size_t)r * (NH_ * HD_) + h * HD_ + lane * 4);
    const float* kb = k + g * HD_ + lane * 4;
    const float* vb = v + g * HD_ + lane * 4;
    const float scale = 0.08838834764831845f;
    const float sink_bonus = 0.5f * (float)(T_ - SINK_ - WIN_) / (float)T_;
    float mmax = -1e30f, denom = 0.f;
    float4 acc = make_float4(0.f, 0.f, 0.f, 0.f);

    for (int seg = 0; seg < 2; seg++) {
        int cbeg = seg ? max(SINK_ + 1, r - WIN_) : 0;
        int cend = seg ? r : min(r, SINK_);
        int c = cbeg;
        // paired keys: two independent shfl chains share the latency window
        for (; c + 1 <= cend; c += 2) {
            const float4 k0 = *(const float4*)(kb + (size_t)c * (KVH_ * HD_));
            const float4 k1 = *(const float4*)(kb + (size_t)(c + 1) * (KVH_ * HD_));
            float s0 = q4.x * k0.x + q4.y * k0.y + q4.z * k0.z + q4.w * k0.w;
            float s1 = q4.x * k1.x + q4.y * k1.y + q4.z * k1.z + q4.w * k1.w;
#pragma unroll
            for (int o = 16; o; o >>= 1) {
                s0 += __shfl_xor_sync(0xFFFFFFFFu, s0, o);
                s1 += __shfl_xor_sync(0xFFFFFFFFu, s1, o);
            }
            s0 = s0 * scale + ((c == SINK_) ? sink_bonus : 0.f);
            s1 = s1 * scale + ((c + 1 == SINK_) ? sink_bonus : 0.f);
            float mn = fmaxf(mmax, fmaxf(s0, s1));
            float corr = expf(mmax - mn);
            float p0 = expf(s0 - mn);
            float p1 = expf(s1 - mn);
            mmax = mn;
            denom = denom * corr + p0 + p1;
            const float4 v0 = *(const float4*)(vb + (size_t)c * (KVH_ * HD_));
            const float4 v1 = *(const float4*)(vb + (size_t)(c + 1) * (KVH_ * HD_));
            acc.x = acc.x * corr + p0 * v0.x + p1 * v1.x;
            acc.y = acc.y * corr + p0 * v0.y + p1 * v1.y;
            acc.z = acc.z * corr + p0 * v0.z + p1 * v1.z;
            acc.w = acc.w * corr + p0 * v0.w + p1 * v1.w;
        }
        // remainder key
        if (c <= cend) {
            const float4 k0 = *(const float4*)(kb + (size_t)c * (KVH_ * HD_));
            float s0 = q4.x * k0.x + q4.y * k0.y + q4.z * k0.z + q4.w * k0.w;
#pragma unroll
            for (int o = 16; o; o >>= 1) s0 += __shfl_xor_sync(0xFFFFFFFFu, s0, o);
            s0 = s0 * scale + ((c == SINK_) ? sink_bonus : 0.f);
            float mn = fmaxf(mmax, s0);
            float corr = expf(mmax - mn);
            float p0 = expf(s0 - mn);
            mmax = mn;
            denom = denom * corr + p0;
            const float4 v0 = *(const float4*)(vb + (size_t)c * (KVH_ * HD_));
            acc.x = acc.x * corr + p0 * v0.x;
            acc.y = acc.y * corr + p0 * v0.y;
            acc.z = acc.z * corr + p0 * v0.z;
            acc.w = acc.w * corr + p0 * v0.w;
        }
    }
    float inv = 1.f / denom;
    float4 o4;
    o4.x = rtf32(acc.x * inv); o4.y = rtf32(acc.y * inv);
    o4.z = rtf32(acc.z * inv); o4.w = rtf32(acc.w * inv);
    *(float4*)(merged + (size_t)r * INTER_ + h * HD_ + lane * 4) = o4;
}

// ---------------- elementwise ----------------
__global__ void swiglu_fused_k(const float* __restrict__ gu, float* __restrict__ o) {
    int i = blockIdx.x * blockDim.x + threadIdx.x;
    if (i >= T_ * MLPI_) return;
    int row = i / MLPI_, c = i % MLPI_;
    float x = gu[(size_t)row * (2 * MLPI_) + c];
    float u = gu[(size_t)row * (2 * MLPI_) + MLPI_ + c];
    o[i] = rtf32((x / (1.f + expf(-x))) * u);
}

// ---------------- host ----------------
typedef CUresult (*PFN_encodeTiled)(CUtensorMap*, CUtensorMapDataType, cuuint32_t, void*,
                                    const cuuint64_t*, const cuuint64_t*, const cuuint32_t*,
                                    const cuuint32_t*, CUtensorMapInterleave, CUtensorMapSwizzle,
                                    CUtensorMapL2promotion, CUtensorMapFloatOOBfill);

static PFN_encodeTiled get_encoder() {
    void* p = nullptr;
    cudaDriverEntryPointQueryResult st;
    cudaGetDriverEntryPointByVersion("cuTensorMapEncodeTiled", &p, 12000, cudaEnableDefault, &st);
    return (PFN_encodeTiled)p;
}

static void make_tm(PFN_encodeTiled enc, CUtensorMap* tm, const float* base,
                    int rows, int cols, int box_rows) {
    cuuint64_t dims[2]    = {(cuuint64_t)cols, (cuuint64_t)rows};
    cuuint64_t strides[1] = {(cuuint64_t)cols * 4};
    cuuint32_t box[2]     = {32u, (cuuint32_t)box_rows};
    cuuint32_t es[2]      = {1u, 1u};
    enc(tm, CU_TENSOR_MAP_DATA_TYPE_FLOAT32, 2, (void*)base, dims, strides, box, es,
        CU_TENSOR_MAP_INTERLEAVE_NONE, CU_TENSOR_MAP_SWIZZLE_128B,
        CU_TENSOR_MAP_L2_PROMOTION_L2_128B, CU_TENSOR_MAP_FLOAT_OOB_FILL_NONE);
}

static PFN_encodeTiled g_enc = nullptr;

static void launch_gemm_tc(const float* A, const float* B,
                           const float* bias, const float* res, float* C,
                           int M, int N, int K, bool roundOut) {
    CUtensorMap tmA, tmB;
    make_tm(g_enc, &tmA, A, M, K, 128);
    make_tm(g_enc, &tmB, B, N, K, 256);
    dim3 grid((N + GBN - 1) / GBN, (M + GBM - 1) / GBM);
    if (roundOut) gemm_tc<true><<<grid, 128, GSMEM>>>(tmA, tmB, A, B, bias, res, C, M, N, K);
    else          gemm_tc<false><<<grid, 128, GSMEM>>>(tmA, tmB, A, B, bias, res, C, M, N, K);
}

static void roundw(const float* src, float* dst, int n) {
    int n4 = n / 4;
    roundw_k<<<(n4 + 255) / 256, 256>>>(src, dst, n4);
}

extern "C" void kernel_launch(void* const* d_in, const int* in_sizes, int n_in,
                              void* d_out, int out_size) {
    const float* hs      = (const float*)d_in[0];
    const float* cosb    = (const float*)d_in[1];
    const float* sinb    = (const float*)d_in[2];
    const float* ln1_w   = (const float*)d_in[3];
    const float* q_w     = (const float*)d_in[4];
    const float* q_b     = (const float*)d_in[5];
    const float* k_w     = (const float*)d_in[6];
    const float* k_b     = (const float*)d_in[7];
    const float* v_w     = (const float*)d_in[8];
    const float* v_b     = (const float*)d_in[9];
    const float* o_w     = (const float*)d_in[10];
    const float* inpj_w  = (const float*)d_in[11];
    const float* conv_w  = (const float*)d_in[12];
    const float* conv_b  = (const float*)d_in[13];
    const float* dt_bias = (const float*)d_in[14];
    const float* A_log   = (const float*)d_in[15];
    const float* Dp      = (const float*)d_in[16];
    const float* mnorm_w = (const float*)d_in[17];
    const float* outp_w  = (const float*)d_in[18];
    const float* ln2_w   = (const float*)d_in[19];
    const float* gate_w  = (const float*)d_in[20];
    const float* up_w    = (const float*)d_in[21];
    const float* down_w  = (const float*)d_in[22];
    float* out = (float*)d_out;

    float *pre, *proj, *xbc, *dtb, *ybuf, *gbuf, *qb, *kb, *vb, *merged, *hb, *mb, *gub, *gateb;
    float *wq, *wk, *wv, *wo, *win, *wout, *wgu, *wd;
    cudaGetSymbolAddress((void**)&pre,    g_pre);
    cudaGetSymbolAddress((void**)&proj,   g_proj);
    cudaGetSymbolAddress((void**)&xbc,    g_xbc);
    cudaGetSymbolAddress((void**)&dtb,    g_dt);
    cudaGetSymbolAddress((void**)&ybuf,   g_y);
    cudaGetSymbolAddress((void**)&gbuf,   g_g);
    cudaGetSymbolAddress((void**)&qb,     g_q);
    cudaGetSymbolAddress((void**)&kb,     g_k);
    cudaGetSymbolAddress((void**)&vb,     g_v);
    cudaGetSymbolAddress((void**)&merged, g_merged);
    cudaGetSymbolAddress((void**)&hb,     g_h);
    cudaGetSymbolAddress((void**)&mb,     g_m);
    cudaGetSymbolAddress((void**)&gub,    g_gu);
    cudaGetSymbolAddress((void**)&gateb,  g_gate);
    cudaGetSymbolAddress((void**)&wq,     g_wq);
    cudaGetSymbolAddress((void**)&wk,     g_wk);
    cudaGetSymbolAddress((void**)&wv,     g_wv);
    cudaGetSymbolAddress((void**)&wo,     g_wo);
    cudaGetSymbolAddress((void**)&win,    g_win);
    cudaGetSymbolAddress((void**)&wout,   g_wout);
    cudaGetSymbolAddress((void**)&wgu,    g_wgu);
    cudaGetSymbolAddress((void**)&wd,     g_wd);

    if (!g_enc) g_enc = get_encoder();
    static bool attrs_set = false;
    if (!attrs_set) {
        cudaFuncSetAttribute(gemm_tc<false>, cudaFuncAttributeMaxDynamicSharedMemorySize, GSMEM);
        cudaFuncSetAttribute(gemm_tc<true>,  cudaFuncAttributeMaxDynamicSharedMemorySize, GSMEM);
        attrs_set = true;
    }

    // 0. round weights to tf32 (unbiased rna); gate|up concatenated
    roundw(q_w,    wq,   NH_ * HD_ * H_);
    roundw(k_w,    wk,   KVH_ * HD_ * H_);
    roundw(v_w,    wv,   KVH_ * HD_ * H_);
    roundw(o_w,    wo,   H_ * NH_ * HD_);
    roundw(inpj_w, win,  NPROJ_ * H_);
    roundw(outp_w, wout, H_ * INTER_);
    roundw(gate_w, wgu,                       MLPI_ * H_);
    roundw(up_w,   wgu + (size_t)MLPI_ * H_,  MLPI_ * H_);
    roundw(down_w, wd,   H_ * MLPI_);

    // 1. pre-norm (tf32-rounded: feeds GEMMs only)
    rmsnorm_k<<<T_, 256>>>(hs, ln1_w, pre, H_, EPS_, 1);

    // 2. mamba branch on pre rows [64, 1536)
    launch_gemm_tc(pre + (size_t)SINK_ * H_, win, nullptr, nullptr, proj, LMEM_, NPROJ_, H_, false);
    conv_silu_k<<<(LMEM_ * CONVD_ + 255) / 256, 256>>>(proj, conv_w, conv_b, xbc);
    dt_k<<<(LMEM_ * NH_ + 255) / 256, 256>>>(proj, dt_bias, dtb);
    scan_k<<<NH_, 128>>>(xbc, dtb, A_log, Dp, ybuf);
    gatenorm_k<<<LMEM_, 256>>>(ybuf, proj, mnorm_w, gbuf);
    launch_gemm_tc(gbuf, wout, nullptr, nullptr, merged + (size_t)SINK_ * INTER_, LMEM_, INTER_, H_, true);

    // 3. q projection on consumed rows only; full k/v
    launch_gemm_tc(pre, wq, q_b, nullptr, qb, SINK_, NH_ * HD_, H_, false);
    launch_gemm_tc(pre + (size_t)(T_ - WIN_) * H_, wq, q_b, nullptr,
                   qb + (size_t)(T_ - WIN_) * (NH_ * HD_), WIN_, NH_ * HD_, H_, false);
    launch_gemm_tc(pre, wk, k_b, nullptr, kb, T_, KVH_ * HD_, H_, false);
    launch_gemm_tc(pre, wv, v_b, nullptr, vb, T_, KVH_ * HD_, H_, false);

    // 4. RoPE
    rope_q_k<<<dim3(4, SINK_ + WIN_), 256>>>(qb, cosb, sinb);
    rope_k_k<<<dim3(1, T_), 256>>>(kb, cosb, sinb);

    // 5. replace k/v at row SINK with mem_act projection (exact fp32 GEMV)
    memact_kv_k<<<2 * KVH_ * HD_, 256>>>(merged, k_w, k_b, v_w, v_b, kb, vb);

    // 6. attention -> merged rows [0,64) and [1536,2048)
    attn_k<<<((SINK_ + WIN_) * NH_ + 7) / 8, 256>>>(qb, kb, vb, merged);

    // 7. o projection + FUSED residual -> hb
    launch_gemm_tc(merged, wo, nullptr, hs, hb, T_, H_, NH_ * HD_, false);

    // 8. MLP (gate+up fused); down-proj + FUSED residual -> out
    rmsnorm_k<<<T_, 256>>>(hb, ln2_w, mb, H_, EPS_, 1);
    launch_gemm_tc(mb, wgu, nullptr, nullptr, gub, T_, 2 * MLPI_, H_, false);
    swiglu_fused_k<<<(T_ * MLPI_ + 255) / 256, 256>>>(gub, gateb);
    launch_gemm_tc(gateb, wd, nullptr, hb, out, T_, H_, MLPI_, false);
}

// round 14
// speedup vs baseline: 1.1013x; 1.0210x over previous
#include <cuda_runtime.h>
#include <cuda.h>
#include <cuda_bf16.h>
#include <math.h>
#include <stdint.h>

// ---------------- constants ----------------
#define T_      2048
#define H_      2048
#define NH_     16
#define KVH_    4
#define HD_     128
#define WIN_    512
#define SINK_   64
#define S_      64
#define NG_     4
#define MLPI_   5504
#define CK_     4
#define INTER_  2048
#define CONVD_  2560
#define NPROJ_  4624
#define LMEM_   1472
#define EPS_    1e-6f
#define MEPS_   1e-5f

// ---------------- scratch ----------------
__device__ float g_pre   [T_ * H_];
__device__ float g_proj  [LMEM_ * NPROJ_];
__device__ float g_xbc   [LMEM_ * CONVD_];
__device__ float g_dt    [LMEM_ * NH_];
__device__ float g_y     [LMEM_ * INTER_];
__device__ float g_g     [LMEM_ * INTER_];
__device__ float g_q     [T_ * (NH_ * HD_)];
__device__ float g_k     [T_ * (KVH_ * HD_)];
__device__ float g_v     [T_ * (KVH_ * HD_)];
__device__ float g_merged[T_ * INTER_];
__device__ float g_h     [T_ * H_];
__device__ float g_m     [T_ * H_];
__device__ float g_gu    [T_ * 2 * MLPI_];
__device__ float g_gate  [T_ * MLPI_];
// tf32-rounded weight copies
__device__ float g_wq  [(NH_*HD_) * H_];
__device__ float g_wk  [(KVH_*HD_) * H_];
__device__ float g_wv  [(KVH_*HD_) * H_];
__device__ float g_wo  [H_ * (NH_*HD_)];
__device__ float g_win [NPROJ_ * H_];
__device__ float g_wout[H_ * INTER_];
__device__ float g_wgu [2 * MLPI_ * H_];
__device__ float g_wd  [H_ * MLPI_];

// ---------------- ptx helpers (baseline-safe) ----------------
__device__ __forceinline__ uint32_t smem_u32(const void* p) {
    uint32_t a;
    asm("{ .reg .u64 t; cvta.to.shared.u64 t, %1; cvt.u32.u64 %0, t; }" : "=r"(a) : "l"(p));
    return a;
}
__device__ __forceinline__ float rtf32(float x) {
    float y; asm("cvt.rna.tf32.f32 %0, %1;" : "=f"(y) : "f"(x)); return y;
}

#define MBARRIER_INIT(addr, cnt) \
    asm volatile("mbarrier.init.shared.b64 [%0], %1;" :: "r"((uint32_t)(addr)), "r"((uint32_t)(cnt)) : "memory")
#define MBARRIER_EXPECT_TX(addr, bytes) \
    asm volatile("mbarrier.arrive.expect_tx.shared.b64 _, [%0], %1;" :: "r"((uint32_t)(addr)), "r"((uint32_t)(bytes)) : "memory")
#define MBARRIER_WAIT_PARITY(addr, ph) do { \
    uint32_t _m = (uint32_t)(addr); uint32_t _p = (uint32_t)(ph); uint32_t _d; \
    asm volatile("{\n\t.reg .pred p;\n\t" \
        "mbarrier.try_wait.parity.acquire.cta.shared::cta.b64 p, [%1], %2;\n\t" \
        "selp.b32 %0, 1, 0, p;\n\t}" : "=r"(_d) : "r"(_m), "r"(_p) : "memory"); \
    if (!_d) { asm volatile("{\n\t.reg .pred P1;\n\t" \
        "WL_%=:\n\t" \
        "mbarrier.try_wait.parity.acquire.cta.shared::cta.b64 P1, [%0], %1, 0x989680;\n\t" \
        "@P1 bra.uni WD_%=;\n\tbra.uni WL_%=;\n\tWD_%=:\n\t}" \
        :: "r"(_m), "r"(_p) : "memory"); } \
} while (0)

__device__ __forceinline__ void tma2d(uint32_t smem, const void* tm, int x, int y, uint32_t mbar) {
    asm volatile("cp.async.bulk.tensor.2d.shared::cta.global.tile.mbarrier::complete_tx::bytes "
                 "[%0], [%1, {%2, %3}], [%4];"
                 :: "r"(smem), "l"(tm), "r"(x), "r"(y), "r"(mbar) : "memory");
}

// ---------------- tcgen05 (arch-specific: sm_103a pass only) ----------------
#if defined(__CUDA_ARCH_FEAT_SM103_ALL)
#define HAS_TCGEN05 1

#define TCGEN05_ALLOC(smem_addr, nCols) \
    asm volatile("tcgen05.alloc.cta_group::1.sync.aligned.shared::cta.b32 [%0], %1;" \
        :: "r"((uint32_t)(smem_addr)), "r"((uint32_t)(nCols)) : "memory")
#define TCGEN05_DEALLOC(tmem, nCols) \
    asm volatile("tcgen05.dealloc.cta_group::1.sync.aligned.b32 %0, %1;" :: "r"(tmem), "r"((uint32_t)(nCols)))
#define TCGEN05_COMMIT(mbar) \
    asm volatile("tcgen05.commit.cta_group::1.mbarrier::arrive::one.shared::cluster.b64 [%0];" \
        :: "r"((uint32_t)(mbar)) : "memory")
#define TCGEN05_FENCE_AFTER() asm volatile("tcgen05.fence::after_thread_sync;" ::: "memory")
#define TCGEN05_WAIT_LD() asm volatile("tcgen05.wait::ld.sync.aligned;" ::: "memory")

#define TCGEN05_LD_32X32B_X32(r, tmem_addr) \
    asm volatile("tcgen05.ld.sync.aligned.32x32b.x32.b32 " \
        "{%0, %1, %2, %3, %4, %5, %6, %7, %8, %9, %10, %11, %12, %13, %14, %15, " \
        " %16, %17, %18, %19, %20, %21, %22, %23, %24, %25, %26, %27, %28, %29, %30, %31}, [%32];" \
        : "=r"((r)[0]),  "=r"((r)[1]),  "=r"((r)[2]),  "=r"((r)[3]), \
          "=r"((r)[4]),  "=r"((r)[5]),  "=r"((r)[6]),  "=r"((r)[7]), \
          "=r"((r)[8]),  "=r"((r)[9]),  "=r"((r)[10]), "=r"((r)[11]), \
          "=r"((r)[12]), "=r"((r)[13]), "=r"((r)[14]), "=r"((r)[15]), \
          "=r"((r)[16]), "=r"((r)[17]), "=r"((r)[18]), "=r"((r)[19]), \
          "=r"((r)[20]), "=r"((r)[21]), "=r"((r)[22]), "=r"((r)[23]), \
          "=r"((r)[24]), "=r"((r)[25]), "=r"((r)[26]), "=r"((r)[27]), \
          "=r"((r)[28]), "=r"((r)[29]), "=r"((r)[30]), "=r"((r)[31]) \
        : "r"(tmem_addr))

__device__ __forceinline__ void mma_tf32_ss(uint32_t d, uint64_t ad, uint64_t bd,
                                            uint32_t idesc, uint32_t en) {
    asm volatile("{\n\t.reg .pred p;\n\tsetp.ne.u32 p, %4, 0;\n\t"
                 "tcgen05.mma.cta_group::1.kind::tf32 [%0], %1, %2, %3, {%5, %5, %5, %5}, p;\n\t}"
                 :: "r"(d), "l"(ad), "l"(bd), "r"(idesc), "r"(en), "r"(0u) : "memory");
}
#endif

// SW128 K-major SMEM descriptor (LBO=1, SBO=64, version=1)
static constexpr uint64_t SMEM_DESC_BASE_SW128 =
    (uint64_t(2) << 61) | (uint64_t(1) << 46) | (uint64_t(64) << 32) | (uint64_t(1) << 16);
#define MAKE_SMEM_DESC(base_addr) (SMEM_DESC_BASE_SW128 | ((uint64_t)((base_addr) >> 4) & 0x3FFF))

// ---------------- tcgen05 tf32 GEMM: C[M,N] = A[M,K] * B[N,K]^T (+bias) (+res) ----------------
#define GBM 128
#define GBN 256
#define GBK 32
#define GDEPTH 4
#define SM_A_OFF 1024
#define SM_B_OFF (1024 + GDEPTH * 16384)
#define GSMEM (1024 + GDEPTH * 16384 + GDEPTH * 32768)

template<bool ROUND>
__global__ void __launch_bounds__(128, 1)
gemm_tc(const __grid_constant__ CUtensorMap tmA,
        const __grid_constant__ CUtensorMap tmB,
        const float* __restrict__ Araw, const float* __restrict__ Braw,
        const float* __restrict__ bias, const float* __restrict__ res,
        float* __restrict__ C, int M, int N, int K) {
#if defined(HAS_TCGEN05)
    extern __shared__ __align__(1024) char smem[];
    uint32_t sb = smem_u32(smem);
    int tid = threadIdx.x, wid = tid >> 5, lane = tid & 31;
    int m0 = blockIdx.y * GBM, n0 = blockIdx.x * GBN;

    if (wid == 0) TCGEN05_ALLOC(sb + 0, 256);
    if (tid == 0) {
        for (int s = 0; s < GDEPTH; s++) {
            MBARRIER_INIT(sb + 8 + s * 16, 1);       // full
            MBARRIER_INIT(sb + 8 + s * 16 + 8, 1);   // empty
        }
    }
    __syncthreads();
    uint32_t tmem;
    asm volatile("ld.shared.b32 %0, [%1];" : "=r"(tmem) : "r"(sb + 0));

    int nst = K / GBK;
    if (tid == 0) {
        int pre = nst < GDEPTH ? nst : GDEPTH;
        for (int s = 0; s < pre; s++) {
            uint32_t full = sb + 8 + s * 16;
            MBARRIER_EXPECT_TX(full, 49152);
            tma2d(sb + SM_A_OFF + s * 16384, &tmA, s * GBK, m0, full);
            tma2d(sb + SM_B_OFF + s * 32768, &tmB, s * GBK, n0, full);
        }
        const uint32_t idesc = (1u << 4) | (2u << 7) | (2u << 10) |
                               ((GBN / 8) << 17) | ((GBM / 16) << 24);
        for (int s = 0; s < nst; s++) {
            int slot = s & (GDEPTH - 1);
            int ph = (s / GDEPTH) & 1;
            uint32_t full = sb + 8 + slot * 16;
            uint32_t empty = full + 8;
            MBARRIER_WAIT_PARITY(full, ph);
            uint64_t ad = MAKE_SMEM_DESC(sb + SM_A_OFF + slot * 16384);
            uint64_t bd = MAKE_SMEM_DESC(sb + SM_B_OFF + slot * 32768);
#pragma unroll
            for (int kk = 0; kk < 4; kk++)
                mma_tf32_ss(tmem, ad + kk * 2, bd + kk * 2, idesc,
                            (s > 0 || kk > 0) ? 1u : 0u);
            TCGEN05_COMMIT(empty);
            if (s > 0) {
                int rs = s - 1 + GDEPTH;
                if (rs < nst) {
                    int rslot = (s - 1) & (GDEPTH - 1);
                    int rph = ((s - 1) / GDEPTH) & 1;
                    uint32_t rfull = sb + 8 + rslot * 16;
                    MBARRIER_WAIT_PARITY(rfull + 8, rph);
                    MBARRIER_EXPECT_TX(rfull, 49152);
                    tma2d(sb + SM_A_OFF + rslot * 16384, &tmA, rs * GBK, m0, rfull);
                    tma2d(sb + SM_B_OFF + rslot * 32768, &tmB, rs * GBK, n0, rfull);
                }
            }
        }
        int ls = nst - 1;
        MBARRIER_WAIT_PARITY(sb + 8 + (ls & (GDEPTH - 1)) * 16 + 8, (ls / GDEPTH) & 1);
    }
    __syncthreads();
    TCGEN05_FENCE_AFTER();

    int m = m0 + wid * 32 + lane;
    bool mok = (m < M);
#pragma unroll 1
    for (int b = 0; b < 8; b++) {
        uint32_t r[32];
        TCGEN05_LD_32X32B_X32(r, tmem + b * 32);
        TCGEN05_WAIT_LD();
        if (mok) {
            float* crow = C + (size_t)m * N;
#pragma unroll
            for (int j4 = 0; j4 < 8; j4++) {
                int c = n0 + b * 32 + j4 * 4;
                if (c < N) {
                    float4 v;
                    v.x = __uint_as_float(r[j4 * 4 + 0]);
                    v.y = __uint_as_float(r[j4 * 4 + 1]);
                    v.z = __uint_as_float(r[j4 * 4 + 2]);
                    v.w = __uint_as_float(r[j4 * 4 + 3]);
                    if (bias) {
                        float4 bb = *(const float4*)(bias + c);
                        v.x += bb.x; v.y += bb.y; v.z += bb.z; v.w += bb.w;
                    }
                    if (res) {
                        float4 rr = *(const float4*)(res + (size_t)m * N + c);
                        v.x += rr.x; v.y += rr.y; v.z += rr.z; v.w += rr.w;
                    }
                    if (ROUND) {
                        v.x = rtf32(v.x); v.y = rtf32(v.y);
                        v.z = rtf32(v.z); v.w = rtf32(v.w);
                    }
                    *(float4*)(crow + c) = v;
                }
            }
        }
    }
    __syncthreads();
    if (wid == 0) TCGEN05_DEALLOC(tmem, 256);
#else
    // Fallback for the generic compute_103 PTX pass (never run on GB300).
    int m0 = blockIdx.y * GBM, n0 = blockIdx.x * GBN;
    for (int idx = threadIdx.x; idx < GBM * GBN; idx += blockDim.x) {
        int mi = idx / GBN, ni = idx % GBN;
        int m = m0 + mi, n = n0 + ni;
        if (m < M && n < N) {
            const float* a = Araw + (size_t)m * K;
            const float* b = Braw + (size_t)n * K;
            float acc = 0.f;
            for (int k = 0; k < K; k++) acc += a[k] * b[k];
            if (bias) acc += bias[n];
            if (res) acc += res[(size_t)m * N + n];
            if (ROUND) acc = rtf32(acc);
            C[(size_t)m * N + n] = acc;
        }
    }
#endif
}

// ---------------- weight rounding ----------------
__global__ void roundw_k(const float* __restrict__ src, float* __restrict__ dst, int n4) {
    int i = blockIdx.x * blockDim.x + threadIdx.x;
    if (i < n4) {
        float4 v = ((const float4*)src)[i];
        v.x = rtf32(v.x); v.y = rtf32(v.y); v.z = rtf32(v.z); v.w = rtf32(v.w);
        ((float4*)dst)[i] = v;
    }
}

// ---------------- rmsnorm ----------------
__global__ void rmsnorm_k(const float* __restrict__ x, const float* __restrict__ w,
                          float* __restrict__ out, int cols, float eps, int do_round) {
    int row = blockIdx.x;
    const float* xr = x + (size_t)row * cols;
    float ss = 0.f;
    for (int i = threadIdx.x; i < cols; i += blockDim.x) { float v = xr[i]; ss += v * v; }
    __shared__ float sh[32];
#pragma unroll
    for (int o = 16; o; o >>= 1) ss += __shfl_xor_sync(0xFFFFFFFFu, ss, o);
    if ((threadIdx.x & 31) == 0) sh[threadIdx.x >> 5] = ss;
    __syncthreads();
    if (threadIdx.x < 32) {
        float v = (threadIdx.x < (blockDim.x >> 5)) ? sh[threadIdx.x] : 0.f;
#pragma unroll
        for (int o = 16; o; o >>= 1) v += __shfl_xor_sync(0xFFFFFFFFu, v, o);
        if (threadIdx.x == 0) sh[0] = v;
    }
    __syncthreads();
    float scale = rsqrtf(sh[0] / (float)cols + eps);
    for (int i = threadIdx.x; i < cols; i += blockDim.x) {
        float v = xr[i] * scale * w[i];
        out[(size_t)row * cols + i] = do_round ? rtf32(v) : v;
    }
}

// ---------------- conv + silu ----------------
__global__ void conv_silu_k(const float* __restrict__ proj, const float* __restrict__ cw,
                            const float* __restrict__ cb, float* __restrict__ xbc) {
    int idx = blockIdx.x * blockDim.x + threadIdx.x;
    if (idx >= LMEM_ * CONVD_) return;
    int l = idx / CONVD_, c = idx % CONVD_;
    float acc = cb[c];
#pragma unroll
    for (int j = 0; j < CK_; j++) {
        int t = l + j - (CK_ - 1);
        if (t >= 0) acc += cw[c * CK_ + j] * proj[(size_t)t * NPROJ_ + INTER_ + c];
    }
    xbc[idx] = acc / (1.f + expf(-acc));
}

__global__ void dt_k(const float* __restrict__ proj, const float* __restrict__ dtb,
                     float* __restrict__ dt) {
    int idx = blockIdx.x * blockDim.x + threadIdx.x;
    if (idx >= LMEM_ * NH_) return;
    int l = idx / NH_, h = idx % NH_;
    float x = proj[(size_t)l * NPROJ_ + (INTER_ + CONVD_) + h] + dtb[h];
    dt[idx] = (x > 20.f) ? x : log1pf(expf(x));
}

// ---------------- mamba2 scan (R3 serial version — proven fastest) ----------------
__global__ void scan_k(const float* __restrict__ xbc, const float* __restrict__ dt,
                       const float* __restrict__ A_log, const float* __restrict__ Dp,
                       float* __restrict__ y) {
    int h = blockIdx.x;
    int tid = threadIdx.x;
    int g = h >> 2;
    float A  = -expf(A_log[h]);
    float Dh = Dp[h];
    __shared__ float Bs[2][S_], Cs[2][S_];
    float st[S_];
#pragma unroll
    for (int s = 0; s < S_; s++) st[s] = 0.f;

    float xv  = xbc[(size_t)0 * CONVD_ + h * HD_ + tid];
    float bv  = (tid < S_) ? xbc[INTER_ + g * S_ + tid]
                           : xbc[INTER_ + NG_ * S_ + g * S_ + (tid - S_)];
    float dtl = dt[h];

    for (int l = 0; l < LMEM_; l++) {
        int buf = l & 1;
        if (tid < S_) Bs[buf][tid] = bv; else Cs[buf][tid - S_] = bv;
        __syncthreads();
        float xn = 0.f, bn = 0.f, dtn = 0.f;
        if (l + 1 < LMEM_) {
            const float* nx = xbc + (size_t)(l + 1) * CONVD_;
            xn  = nx[h * HD_ + tid];
            bn  = (tid < S_) ? nx[INTER_ + g * S_ + tid]
                             : nx[INTER_ + NG_ * S_ + g * S_ + (tid - S_)];
            dtn = dt[(size_t)(l + 1) * NH_ + h];
        }
        float decay = expf(dtl * A);
        float dtx   = dtl * xv;
        float yv = 0.f;
#pragma unroll
        for (int s = 0; s < S_; s++) {
            st[s] = decay * st[s] + dtx * Bs[buf][s];
            yv += st[s] * Cs[buf][s];
        }
        yv += Dh * xv;
        y[(size_t)l * INTER_ + h * HD_ + tid] = yv;
        xv = xn; bv = bn; dtl = dtn;
    }
}

// ---------------- gated rmsnorm ----------------
__global__ void gatenorm_k(const float* __restrict__ y, const float* __restrict__ proj,
                           const float* __restrict__ mw, float* __restrict__ out) {
    int row = blockIdx.x;
    __shared__ float gsh[INTER_];
    __shared__ float sh[32];
    float ss = 0.f;
    for (int i = threadIdx.x; i < INTER_; i += blockDim.x) {
        float z  = proj[(size_t)row * NPROJ_ + i];
        float gv = y[(size_t)row * INTER_ + i] * (z / (1.f + expf(-z)));
        gsh[i] = gv;
        ss += gv * gv;
    }
#pragma unroll
    for (int o = 16; o; o >>= 1) ss += __shfl_xor_sync(0xFFFFFFFFu, ss, o);
    if ((threadIdx.x & 31) == 0) sh[threadIdx.x >> 5] = ss;
    __syncthreads();
    if (threadIdx.x < 32) {
        float v = (threadIdx.x < (blockDim.x >> 5)) ? sh[threadIdx.x] : 0.f;
#pragma unroll
        for (int o = 16; o; o >>= 1) v += __shfl_xor_sync(0xFFFFFFFFu, v, o);
        if (threadIdx.x == 0) sh[0] = v;
    }
    __syncthreads();
    float scale = rsqrtf(sh[0] / (float)INTER_ + MEPS_);
    for (int i = threadIdx.x; i < INTER_; i += blockDim.x)
        out[(size_t)row * INTER_ + i] = rtf32(gsh[i] * scale * mw[i]);
}

// ---------------- RoPE ----------------
__global__ void rope_q_k(float* __restrict__ q, const float* __restrict__ cosb,
                         const float* __restrict__ sinb) {
    int ri = blockIdx.y;
    int r = (ri < SINK_) ? ri : (T_ - WIN_) + (ri - SINK_);
    int i = blockIdx.x * blockDim.x + threadIdx.x;
    if (i >= NH_ * (HD_ / 2)) return;
    int hh = i >> 6, d = i & 63;
    float* qr = q + (size_t)r * (NH_ * HD_) + hh * HD_;
    float c0 = cosb[r * HD_ + d],      s0 = sinb[r * HD_ + d];
    float c1 = cosb[r * HD_ + d + 64], s1 = sinb[r * HD_ + d + 64];
    float a = qr[d], b = qr[d + 64];
    qr[d]      = a * c0 - b * s0;
    qr[d + 64] = b * c1 + a * s1;
}

__global__ void rope_k_k(float* __restrict__ k, const float* __restrict__ cosb,
                         const float* __restrict__ sinb) {
    int r = blockIdx.y;
    int i = threadIdx.x;
    if (i >= KVH_ * (HD_ / 2)) return;
    int hh = i >> 6, d = i & 63;
    float* kr = k + (size_t)r * (KVH_ * HD_) + hh * HD_;
    float c0 = cosb[r * HD_ + d],      s0 = sinb[r * HD_ + d];
    float c1 = cosb[r * HD_ + d + 64], s1 = sinb[r * HD_ + d + 64];
    float a = kr[d], b = kr[d + 64];
    kr[d]      = a * c0 - b * s0;
    kr[d + 64] = b * c1 + a * s1;
}

// ---------------- k/v row SINK replacement ----------------
__global__ void memact_kv_k(const float* __restrict__ merged,
                            const float* __restrict__ kw, const float* __restrict__ kb,
                            const float* __restrict__ vw, const float* __restrict__ vb,
                            float* __restrict__ kbuf, float* __restrict__ vbuf) {
    int p = blockIdx.x;
    const float* act = merged + (size_t)(SINK_ + LMEM_ - 1) * INTER_;
    int pp = (p < KVH_ * HD_) ? p : p - KVH_ * HD_;
    const float* W = (p < KVH_ * HD_) ? kw : vw;
    float bs       = (p < KVH_ * HD_) ? kb[pp] : vb[pp];
    float ss = 0.f;
    for (int i = threadIdx.x; i < H_; i += blockDim.x) ss += act[i] * W[(size_t)pp * H_ + i];
    __shared__ float sh[32];
#pragma unroll
    for (int o = 16; o; o >>= 1) ss += __shfl_xor_sync(0xFFFFFFFFu, ss, o);
    if ((threadIdx.x & 31) == 0) sh[threadIdx.x >> 5] = ss;
    __syncthreads();
    if (threadIdx.x == 0) {
        float v = 0.f;
        for (int w = 0; w < (int)(blockDim.x >> 5); w++) v += sh[w];
        v += bs;
        if (p < KVH_ * HD_) kbuf[(size_t)SINK_ * (KVH_ * HD_) + pp] = v;
        else                vbuf[(size_t)SINK_ * (KVH_ * HD_) + pp] = v;
    }
}

// ---------------- attention: 4-key ILP online softmax ----------------
__global__ void attn_k(const float* __restrict__ q, const float* __restrict__ k,
                       const float* __restrict__ v, float* __restrict__ merged) {
    int wid_g = blockIdx.x * (blockDim.x >> 5) + (threadIdx.x >> 5);
    if (wid_g >= (SINK_ + WIN_) * NH_) return;
    int lane = threadIdx.x & 31;
    int ri = wid_g >> 4;
    int h  = wid_g & 15;
    int r  = (ri < SINK_) ? ri : (T_ - WIN_) + (ri - SINK_);
    int g  = h >> 2;
    const float4 q4 = *(const float4*)(q + (size_t)r * (NH_ * HD_) + h * HD_ + lane * 4);
    const float* kb = k + g * HD_ + lane * 4;
    const float* vb = v + g * HD_ + lane * 4;
    const float scale = 0.08838834764831845f;
    const float sink_bonus = 0.5f * (float)(T_ - SINK_ - WIN_) / (float)T_;
    float mmax = -1e30f, denom = 0.f;
    float4 acc = make_float4(0.f, 0.f, 0.f, 0.f);

    for (int seg = 0; seg < 2; seg++) {
        int cbeg = seg ? max(SINK_ + 1, r - WIN_) : 0;
        int cend = seg ? r : min(r, SINK_);
        int c = cbeg;
        // quad keys: four independent shfl chains share one latency window
        for (; c + 3 <= cend; c += 4) {
            float4 kk0 = *(const float4*)(kb + (size_t)(c + 0) * (KVH_ * HD_));
            float4 kk1 = *(const float4*)(kb + (size_t)(c + 1) * (KVH_ * HD_));
            float4 kk2 = *(const float4*)(kb + (size_t)(c + 2) * (KVH_ * HD_));
            float4 kk3 = *(const float4*)(kb + (size_t)(c + 3) * (KVH_ * HD_));
            float s0 = q4.x * kk0.x + q4.y * kk0.y + q4.z * kk0.z + q4.w * kk0.w;
            float s1 = q4.x * kk1.x + q4.y * kk1.y + q4.z * kk1.z + q4.w * kk1.w;
            float s2 = q4.x * kk2.x + q4.y * kk2.y + q4.z * kk2.z + q4.w * kk2.w;
            float s3 = q4.x * kk3.x + q4.y * kk3.y + q4.z * kk3.z + q4.w * kk3.w;
#pragma unroll
            for (int o = 16; o; o >>= 1) {
                s0 += __shfl_xor_sync(0xFFFFFFFFu, s0, o);
                s1 += __shfl_xor_sync(0xFFFFFFFFu, s1, o);
                s2 += __shfl_xor_sync(0xFFFFFFFFu, s2, o);
                s3 += __shfl_xor_sync(0xFFFFFFFFu, s3, o);
            }
            s0 = s0 * scale + ((c + 0 == SINK_) ? sink_bonus : 0.f);
            s1 = s1 * scale + ((c + 1 == SINK_) ? sink_bonus : 0.f);
            s2 = s2 * scale + ((c + 2 == SINK_) ? sink_bonus : 0.f);
            s3 = s3 * scale + ((c + 3 == SINK_) ? sink_bonus : 0.f);
            float mn = fmaxf(fmaxf(mmax, fmaxf(s0, s1)), fmaxf(s2, s3));
            float corr = expf(mmax - mn);
            float p0 = expf(s0 - mn);
            float p1 = expf(s1 - mn);
            float p2 = expf(s2 - mn);
            float p3 = expf(s3 - mn);
            mmax = mn;
            denom = denom * corr + ((p0 + p1) + (p2 + p3));
            float4 v0 = *(const float4*)(vb + (size_t)(c + 0) * (KVH_ * HD_));
            float4 v1 = *(const float4*)(vb + (size_t)(c + 1) * (KVH_ * HD_));
            float4 v2 = *(const float4*)(vb + (size_t)(c + 2) * (KVH_ * HD_));
            float4 v3 = *(const float4*)(vb + (size_t)(c + 3) * (KVH_ * HD_));
            acc.x = acc.x * corr + (p0 * v0.x + p1 * v1.x) + (p2 * v2.x + p3 * v3.x);
            acc.y = acc.y * corr + (p0 * v0.y + p1 * v1.y) + (p2 * v2.y + p3 * v3.y);
            acc.z = acc.z * corr + (p0 * v0.z + p1 * v1.z) + (p2 * v2.z + p3 * v3.z);
            acc.w = acc.w * corr + (p0 * v0.w + p1 * v1.w) + (p2 * v2.w + p3 * v3.w);
        }
        // remainder keys (up to 3)
        for (; c <= cend; c++) {
            const float4 k0 = *(const float4*)(kb + (size_t)c * (KVH_ * HD_));
            float s0 = q4.x * k0.x + q4.y * k0.y + q4.z * k0.z + q4.w * k0.w;
#pragma unroll
            for (int o = 16; o; o >>= 1) s0 += __shfl_xor_sync(0xFFFFFFFFu, s0, o);
            s0 = s0 * scale + ((c == SINK_) ? sink_bonus : 0.f);
            float mn = fmaxf(mmax, s0);
            float corr = expf(mmax - mn);
            float p0 = expf(s0 - mn);
            mmax = mn;
            denom = denom * corr + p0;
            const float4 v0 = *(const float4*)(vb + (size_t)c * (KVH_ * HD_));
            acc.x = acc.x * corr + p0 * v0.x;
            acc.y = acc.y * corr + p0 * v0.y;
            acc.z = acc.z * corr + p0 * v0.z;
            acc.w = acc.w * corr + p0 * v0.w;
        }
    }
    float inv = 1.f / denom;
    float4 o4;
    o4.x = rtf32(acc.x * inv); o4.y = rtf32(acc.y * inv);
    o4.z = rtf32(acc.z * inv); o4.w = rtf32(acc.w * inv);
    *(float4*)(merged + (size_t)r * INTER_ + h * HD_ + lane * 4) = o4;
}

// ---------------- elementwise ----------------
__global__ void swiglu_fused_k(const float* __restrict__ gu, float* __restrict__ o) {
    int i = blockIdx.x * blockDim.x + threadIdx.x;
    if (i >= T_ * MLPI_) return;
    int row = i / MLPI_, c = i % MLPI_;
    float x = gu[(size_t)row * (2 * MLPI_) + c];
    float u = gu[(size_t)row * (2 * MLPI_) + MLPI_ + c];
    o[i] = rtf32((x / (1.f + expf(-x))) * u);
}

// ---------------- host ----------------
typedef CUresult (*PFN_encodeTiled)(CUtensorMap*, CUtensorMapDataType, cuuint32_t, void*,
                                    const cuuint64_t*, const cuuint64_t*, const cuuint32_t*,
                                    const cuuint32_t*, CUtensorMapInterleave, CUtensorMapSwizzle,
                                    CUtensorMapL2promotion, CUtensorMapFloatOOBfill);

static PFN_encodeTiled get_encoder() {
    void* p = nullptr;
    cudaDriverEntryPointQueryResult st;
    cudaGetDriverEntryPointByVersion("cuTensorMapEncodeTiled", &p, 12000, cudaEnableDefault, &st);
    return (PFN_encodeTiled)p;
}

static void make_tm(PFN_encodeTiled enc, CUtensorMap* tm, const float* base,
                    int rows, int cols, int box_rows) {
    cuuint64_t dims[2]    = {(cuuint64_t)cols, (cuuint64_t)rows};
    cuuint64_t strides[1] = {(cuuint64_t)cols * 4};
    cuuint32_t box[2]     = {32u, (cuuint32_t)box_rows};
    cuuint32_t es[2]      = {1u, 1u};
    enc(tm, CU_TENSOR_MAP_DATA_TYPE_FLOAT32, 2, (void*)base, dims, strides, box, es,
        CU_TENSOR_MAP_INTERLEAVE_NONE, CU_TENSOR_MAP_SWIZZLE_128B,
        CU_TENSOR_MAP_L2_PROMOTION_L2_128B, CU_TENSOR_MAP_FLOAT_OOB_FILL_NONE);
}

static PFN_encodeTiled g_enc = nullptr;

static void launch_gemm_tc(const float* A, const float* B,
                           const float* bias, const float* res, float* C,
                           int M, int N, int K, bool roundOut) {
    CUtensorMap tmA, tmB;
    make_tm(g_enc, &tmA, A, M, K, 128);
    make_tm(g_enc, &tmB, B, N, K, 256);
    dim3 grid((N + GBN - 1) / GBN, (M + GBM - 1) / GBM);
    if (roundOut) gemm_tc<true><<<grid, 128, GSMEM>>>(tmA, tmB, A, B, bias, res, C, M, N, K);
    else          gemm_tc<false><<<grid, 128, GSMEM>>>(tmA, tmB, A, B, bias, res, C, M, N, K);
}

static void roundw(const float* src, float* dst, int n) {
    int n4 = n / 4;
    roundw_k<<<(n4 + 255) / 256, 256>>>(src, dst, n4);
}

extern "C" void kernel_launch(void* const* d_in, const int* in_sizes, int n_in,
                              void* d_out, int out_size) {
    const float* hs      = (const float*)d_in[0];
    const float* cosb    = (const float*)d_in[1];
    const float* sinb    = (const float*)d_in[2];
    const float* ln1_w   = (const float*)d_in[3];
    const float* q_w     = (const float*)d_in[4];
    const float* q_b     = (const float*)d_in[5];
    const float* k_w     = (const float*)d_in[6];
    const float* k_b     = (const float*)d_in[7];
    const float* v_w     = (const float*)d_in[8];
    const float* v_b     = (const float*)d_in[9];
    const float* o_w     = (const float*)d_in[10];
    const float* inpj_w  = (const float*)d_in[11];
    const float* conv_w  = (const float*)d_in[12];
    const float* conv_b  = (const float*)d_in[13];
    const float* dt_bias = (const float*)d_in[14];
    const float* A_log   = (const float*)d_in[15];
    const float* Dp      = (const float*)d_in[16];
    const float* mnorm_w = (const float*)d_in[17];
    const float* outp_w  = (const float*)d_in[18];
    const float* ln2_w   = (const float*)d_in[19];
    const float* gate_w  = (const float*)d_in[20];
    const float* up_w    = (const float*)d_in[21];
    const float* down_w  = (const float*)d_in[22];
    float* out = (float*)d_out;

    float *pre, *proj, *xbc, *dtb, *ybuf, *gbuf, *qb, *kb, *vb, *merged, *hb, *mb, *gub, *gateb;
    float *wq, *wk, *wv, *wo, *win, *wout, *wgu, *wd;
    cudaGetSymbolAddress((void**)&pre,    g_pre);
    cudaGetSymbolAddress((void**)&proj,   g_proj);
    cudaGetSymbolAddress((void**)&xbc,    g_xbc);
    cudaGetSymbolAddress((void**)&dtb,    g_dt);
    cudaGetSymbolAddress((void**)&ybuf,   g_y);
    cudaGetSymbolAddress((void**)&gbuf,   g_g);
    cudaGetSymbolAddress((void**)&qb,     g_q);
    cudaGetSymbolAddress((void**)&kb,     g_k);
    cudaGetSymbolAddress((void**)&vb,     g_v);
    cudaGetSymbolAddress((void**)&merged, g_merged);
    cudaGetSymbolAddress((void**)&hb,     g_h);
    cudaGetSymbolAddress((void**)&mb,     g_m);
    cudaGetSymbolAddress((void**)&gub,    g_gu);
    cudaGetSymbolAddress((void**)&gateb,  g_gate);
    cudaGetSymbolAddress((void**)&wq,     g_wq);
    cudaGetSymbolAddress((void**)&wk,     g_wk);
    cudaGetSymbolAddress((void**)&wv,     g_wv);
    cudaGetSymbolAddress((void**)&wo,     g_wo);
    cudaGetSymbolAddress((void**)&win,    g_win);
    cudaGetSymbolAddress((void**)&wout,   g_wout);
    cudaGetSymbolAddress((void**)&wgu,    g_wgu);
    cudaGetSymbolAddress((void**)&wd,     g_wd);

    if (!g_enc) g_enc = get_encoder();
    static bool attrs_set = false;
    if (!attrs_set) {
        cudaFuncSetAttribute(gemm_tc<false>, cudaFuncAttributeMaxDynamicSharedMemorySize, GSMEM);
        cudaFuncSetAttribute(gemm_tc<true>,  cudaFuncAttributeMaxDynamicSharedMemorySize, GSMEM);
        attrs_set = true;
    }

    // 0. round weights to tf32 (unbiased rna); gate|up concatenated
    roundw(q_w,    wq,   NH_ * HD_ * H_);
    roundw(k_w,    wk,   KVH_ * HD_ * H_);
    roundw(v_w,    wv,   KVH_ * HD_ * H_);
    roundw(o_w,    wo,   H_ * NH_ * HD_);
    roundw(inpj_w, win,  NPROJ_ * H_);
    roundw(outp_w, wout, H_ * INTER_);
    roundw(gate_w, wgu,                       MLPI_ * H_);
    roundw(up_w,   wgu + (size_t)MLPI_ * H_,  MLPI_ * H_);
    roundw(down_w, wd,   H_ * MLPI_);

    // 1. pre-norm (tf32-rounded: feeds GEMMs only)
    rmsnorm_k<<<T_, 256>>>(hs, ln1_w, pre, H_, EPS_, 1);

    // 2. mamba branch on pre rows [64, 1536)
    launch_gemm_tc(pre + (size_t)SINK_ * H_, win, nullptr, nullptr, proj, LMEM_, NPROJ_, H_, false);
    conv_silu_k<<<(LMEM_ * CONVD_ + 255) / 256, 256>>>(proj, conv_w, conv_b, xbc);
    dt_k<<<(LMEM_ * NH_ + 255) / 256, 256>>>(proj, dt_bias, dtb);
    scan_k<<<NH_, 128>>>(xbc, dtb, A_log, Dp, ybuf);
    gatenorm_k<<<LMEM_, 256>>>(ybuf, proj, mnorm_w, gbuf);
    launch_gemm_tc(gbuf, wout, nullptr, nullptr, merged + (size_t)SINK_ * INTER_, LMEM_, INTER_, H_, true);

    // 3. q projection on consumed rows only; full k/v
    launch_gemm_tc(pre, wq, q_b, nullptr, qb, SINK_, NH_ * HD_, H_, false);
    launch_gemm_tc(pre + (size_t)(T_ - WIN_) * H_, wq, q_b, nullptr,
                   qb + (size_t)(T_ - WIN_) * (NH_ * HD_), WIN_, NH_ * HD_, H_, false);
    launch_gemm_tc(pre, wk, k_b, nullptr, kb, T_, KVH_ * HD_, H_, false);
    launch_gemm_tc(pre, wv, v_b, nullptr, vb, T_, KVH_ * HD_, H_, false);

    // 4. RoPE
    rope_q_k<<<dim3(4, SINK_ + WIN_), 256>>>(qb, cosb, sinb);
    rope_k_k<<<dim3(1, T_), 256>>>(kb, cosb, sinb);

    // 5. replace k/v at row SINK with mem_act projection (exact fp32 GEMV)
    memact_kv_k<<<2 * KVH_ * HD_, 256>>>(merged, k_w, k_b, v_w, v_b, kb, vb);

    // 6. attention -> merged rows [0,64) and [1536,2048)
    attn_k<<<((SINK_ + WIN_) * NH_ + 7) / 8, 256>>>(qb, kb, vb, merged);

    // 7. o projection + FUSED residual -> hb
    launch_gemm_tc(merged, wo, nullptr, hs, hb, T_, H_, NH_ * HD_, false);

    // 8. MLP (gate+up fused); down-proj + FUSED residual -> out
    rmsnorm_k<<<T_, 256>>>(hb, ln2_w, mb, H_, EPS_, 1);
    launch_gemm_tc(mb, wgu, nullptr, nullptr, gub, T_, 2 * MLPI_, H_, false);
    swiglu_fused_k<<<(T_ * MLPI_ + 255) / 256, 256>>>(gub, gateb);
    launch_gemm_tc(gateb, wd, nullptr, hb, out, T_, H_, MLPI_, false);
}

// round 15
// speedup vs baseline: 1.1394x; 1.0346x over previous
#include <cuda_runtime.h>
#include <cuda.h>
#include <cuda_bf16.h>
#include <math.h>
#include <stdint.h>

// ---------------- constants ----------------
#define T_      2048
#define H_      2048
#define NH_     16
#define KVH_    4
#define HD_     128
#define WIN_    512
#define SINK_   64
#define S_      64
#define NG_     4
#define MLPI_   5504
#define CK_     4
#define INTER_  2048
#define CONVD_  2560
#define NPROJ_  4624
#define LMEM_   1472
#define EPS_    1e-6f
#define MEPS_   1e-5f

// ---------------- scratch ----------------
__device__ float g_pre   [T_ * H_];
__device__ float g_proj  [LMEM_ * NPROJ_];
__device__ float g_xbc   [LMEM_ * CONVD_];
__device__ float g_dt    [LMEM_ * NH_];
__device__ float g_y     [LMEM_ * INTER_];
__device__ float g_g     [LMEM_ * INTER_];
__device__ float g_q     [T_ * (NH_ * HD_)];
__device__ float g_k     [T_ * (KVH_ * HD_)];
__device__ float g_v     [T_ * (KVH_ * HD_)];
__device__ float g_merged[T_ * INTER_];
__device__ float g_h     [T_ * H_];
__device__ float g_m     [T_ * H_];
__device__ float g_gu    [T_ * 2 * MLPI_];
__device__ float g_gate  [T_ * MLPI_];
// tf32-rounded weight copies
__device__ float g_wq  [(NH_*HD_) * H_];
__device__ float g_wk  [(KVH_*HD_) * H_];
__device__ float g_wv  [(KVH_*HD_) * H_];
__device__ float g_wo  [H_ * (NH_*HD_)];
__device__ float g_win [NPROJ_ * H_];
__device__ float g_wout[H_ * INTER_];
__device__ float g_wgu [2 * MLPI_ * H_];
__device__ float g_wd  [H_ * MLPI_];

// ---------------- ptx helpers (baseline-safe) ----------------
__device__ __forceinline__ uint32_t smem_u32(const void* p) {
    uint32_t a;
    asm("{ .reg .u64 t; cvta.to.shared.u64 t, %1; cvt.u32.u64 %0, t; }" : "=r"(a) : "l"(p));
    return a;
}
__device__ __forceinline__ float rtf32(float x) {
    float y; asm("cvt.rna.tf32.f32 %0, %1;" : "=f"(y) : "f"(x)); return y;
}

#define MBARRIER_INIT(addr, cnt) \
    asm volatile("mbarrier.init.shared.b64 [%0], %1;" :: "r"((uint32_t)(addr)), "r"((uint32_t)(cnt)) : "memory")
#define MBARRIER_EXPECT_TX(addr, bytes) \
    asm volatile("mbarrier.arrive.expect_tx.shared.b64 _, [%0], %1;" :: "r"((uint32_t)(addr)), "r"((uint32_t)(bytes)) : "memory")
#define MBARRIER_WAIT_PARITY(addr, ph) do { \
    uint32_t _m = (uint32_t)(addr); uint32_t _p = (uint32_t)(ph); uint32_t _d; \
    asm volatile("{\n\t.reg .pred p;\n\t" \
        "mbarrier.try_wait.parity.acquire.cta.shared::cta.b64 p, [%1], %2;\n\t" \
        "selp.b32 %0, 1, 0, p;\n\t}" : "=r"(_d) : "r"(_m), "r"(_p) : "memory"); \
    if (!_d) { asm volatile("{\n\t.reg .pred P1;\n\t" \
        "WL_%=:\n\t" \
        "mbarrier.try_wait.parity.acquire.cta.shared::cta.b64 P1, [%0], %1, 0x989680;\n\t" \
        "@P1 bra.uni WD_%=;\n\tbra.uni WL_%=;\n\tWD_%=:\n\t}" \
        :: "r"(_m), "r"(_p) : "memory"); } \
} while (0)

__device__ __forceinline__ void tma2d(uint32_t smem, const void* tm, int x, int y, uint32_t mbar) {
    asm volatile("cp.async.bulk.tensor.2d.shared::cta.global.tile.mbarrier::complete_tx::bytes "
                 "[%0], [%1, {%2, %3}], [%4];"
                 :: "r"(smem), "l"(tm), "r"(x), "r"(y), "r"(mbar) : "memory");
}

// ---------------- tcgen05 (arch-specific: sm_103a pass only) ----------------
#if defined(__CUDA_ARCH_FEAT_SM103_ALL)
#define HAS_TCGEN05 1

#define TCGEN05_ALLOC(smem_addr, nCols) \
    asm volatile("tcgen05.alloc.cta_group::1.sync.aligned.shared::cta.b32 [%0], %1;" \
        :: "r"((uint32_t)(smem_addr)), "r"((uint32_t)(nCols)) : "memory")
#define TCGEN05_DEALLOC(tmem, nCols) \
    asm volatile("tcgen05.dealloc.cta_group::1.sync.aligned.b32 %0, %1;" :: "r"(tmem), "r"((uint32_t)(nCols)))
#define TCGEN05_COMMIT(mbar) \
    asm volatile("tcgen05.commit.cta_group::1.mbarrier::arrive::one.shared::cluster.b64 [%0];" \
        :: "r"((uint32_t)(mbar)) : "memory")
#define TCGEN05_FENCE_AFTER() asm volatile("tcgen05.fence::after_thread_sync;" ::: "memory")
#define TCGEN05_WAIT_LD() asm volatile("tcgen05.wait::ld.sync.aligned;" ::: "memory")

#define TCGEN05_LD_32X32B_X32(r, tmem_addr) \
    asm volatile("tcgen05.ld.sync.aligned.32x32b.x32.b32 " \
        "{%0, %1, %2, %3, %4, %5, %6, %7, %8, %9, %10, %11, %12, %13, %14, %15, " \
        " %16, %17, %18, %19, %20, %21, %22, %23, %24, %25, %26, %27, %28, %29, %30, %31}, [%32];" \
        : "=r"((r)[0]),  "=r"((r)[1]),  "=r"((r)[2]),  "=r"((r)[3]), \
          "=r"((r)[4]),  "=r"((r)[5]),  "=r"((r)[6]),  "=r"((r)[7]), \
          "=r"((r)[8]),  "=r"((r)[9]),  "=r"((r)[10]), "=r"((r)[11]), \
          "=r"((r)[12]), "=r"((r)[13]), "=r"((r)[14]), "=r"((r)[15]), \
          "=r"((r)[16]), "=r"((r)[17]), "=r"((r)[18]), "=r"((r)[19]), \
          "=r"((r)[20]), "=r"((r)[21]), "=r"((r)[22]), "=r"((r)[23]), \
          "=r"((r)[24]), "=r"((r)[25]), "=r"((r)[26]), "=r"((r)[27]), \
          "=r"((r)[28]), "=r"((r)[29]), "=r"((r)[30]), "=r"((r)[31]) \
        : "r"(tmem_addr))

__device__ __forceinline__ void mma_tf32_ss(uint32_t d, uint64_t ad, uint64_t bd,
                                            uint32_t idesc, uint32_t en) {
    asm volatile("{\n\t.reg .pred p;\n\tsetp.ne.u32 p, %4, 0;\n\t"
                 "tcgen05.mma.cta_group::1.kind::tf32 [%0], %1, %2, %3, {%5, %5, %5, %5}, p;\n\t}"
                 :: "r"(d), "l"(ad), "l"(bd), "r"(idesc), "r"(en), "r"(0u) : "memory");
}
#endif

// SW128 K-major SMEM descriptor (LBO=1, SBO=64, version=1)
static constexpr uint64_t SMEM_DESC_BASE_SW128 =
    (uint64_t(2) << 61) | (uint64_t(1) << 46) | (uint64_t(64) << 32) | (uint64_t(1) << 16);
#define MAKE_SMEM_DESC(base_addr) (SMEM_DESC_BASE_SW128 | ((uint64_t)((base_addr) >> 4) & 0x3FFF))

// ---------------- tcgen05 tf32 GEMM: C[M,N] = A[M,K] * B[N,K]^T (+bias) (+res) ----------------
#define GBM 128
#define GBN 256
#define GBK 32
#define GDEPTH 4
#define SM_A_OFF 1024
#define SM_B_OFF (1024 + GDEPTH * 16384)
#define GSMEM (1024 + GDEPTH * 16384 + GDEPTH * 32768)

template<bool ROUND>
__global__ void __launch_bounds__(128, 1)
gemm_tc(const __grid_constant__ CUtensorMap tmA,
        const __grid_constant__ CUtensorMap tmB,
        const float* __restrict__ Araw, const float* __restrict__ Braw,
        const float* __restrict__ bias, const float* __restrict__ res,
        float* __restrict__ C, int M, int N, int K) {
#if defined(HAS_TCGEN05)
    extern __shared__ __align__(1024) char smem[];
    uint32_t sb = smem_u32(smem);
    int tid = threadIdx.x, wid = tid >> 5, lane = tid & 31;
    int m0 = blockIdx.y * GBM, n0 = blockIdx.x * GBN;

    if (wid == 0) TCGEN05_ALLOC(sb + 0, 256);
    if (tid == 0) {
        for (int s = 0; s < GDEPTH; s++) {
            MBARRIER_INIT(sb + 8 + s * 16, 1);       // full
            MBARRIER_INIT(sb + 8 + s * 16 + 8, 1);   // empty
        }
    }
    __syncthreads();
    uint32_t tmem;
    asm volatile("ld.shared.b32 %0, [%1];" : "=r"(tmem) : "r"(sb + 0));

    int nst = K / GBK;
    if (tid == 0) {
        int pre = nst < GDEPTH ? nst : GDEPTH;
        for (int s = 0; s < pre; s++) {
            uint32_t full = sb + 8 + s * 16;
            MBARRIER_EXPECT_TX(full, 49152);
            tma2d(sb + SM_A_OFF + s * 16384, &tmA, s * GBK, m0, full);
            tma2d(sb + SM_B_OFF + s * 32768, &tmB, s * GBK, n0, full);
        }
        const uint32_t idesc = (1u << 4) | (2u << 7) | (2u << 10) |
                               ((GBN / 8) << 17) | ((GBM / 16) << 24);
        for (int s = 0; s < nst; s++) {
            int slot = s & (GDEPTH - 1);
            int ph = (s / GDEPTH) & 1;
            uint32_t full = sb + 8 + slot * 16;
            uint32_t empty = full + 8;
            MBARRIER_WAIT_PARITY(full, ph);
            uint64_t ad = MAKE_SMEM_DESC(sb + SM_A_OFF + slot * 16384);
            uint64_t bd = MAKE_SMEM_DESC(sb + SM_B_OFF + slot * 32768);
#pragma unroll
            for (int kk = 0; kk < 4; kk++)
                mma_tf32_ss(tmem, ad + kk * 2, bd + kk * 2, idesc,
                            (s > 0 || kk > 0) ? 1u : 0u);
            TCGEN05_COMMIT(empty);
            if (s > 0) {
                int rs = s - 1 + GDEPTH;
                if (rs < nst) {
                    int rslot = (s - 1) & (GDEPTH - 1);
                    int rph = ((s - 1) / GDEPTH) & 1;
                    uint32_t rfull = sb + 8 + rslot * 16;
                    MBARRIER_WAIT_PARITY(rfull + 8, rph);
                    MBARRIER_EXPECT_TX(rfull, 49152);
                    tma2d(sb + SM_A_OFF + rslot * 16384, &tmA, rs * GBK, m0, rfull);
                    tma2d(sb + SM_B_OFF + rslot * 32768, &tmB, rs * GBK, n0, rfull);
                }
            }
        }
        int ls = nst - 1;
        MBARRIER_WAIT_PARITY(sb + 8 + (ls & (GDEPTH - 1)) * 16 + 8, (ls / GDEPTH) & 1);
    }
    __syncthreads();
    TCGEN05_FENCE_AFTER();

    int m = m0 + wid * 32 + lane;
    bool mok = (m < M);
#pragma unroll 1
    for (int b = 0; b < 8; b++) {
        uint32_t r[32];
        TCGEN05_LD_32X32B_X32(r, tmem + b * 32);
        TCGEN05_WAIT_LD();
        if (mok) {
            float* crow = C + (size_t)m * N;
#pragma unroll
            for (int j4 = 0; j4 < 8; j4++) {
                int c = n0 + b * 32 + j4 * 4;
                if (c < N) {
                    float4 v;
                    v.x = __uint_as_float(r[j4 * 4 + 0]);
                    v.y = __uint_as_float(r[j4 * 4 + 1]);
                    v.z = __uint_as_float(r[j4 * 4 + 2]);
                    v.w = __uint_as_float(r[j4 * 4 + 3]);
                    if (bias) {
                        float4 bb = *(const float4*)(bias + c);
                        v.x += bb.x; v.y += bb.y; v.z += bb.z; v.w += bb.w;
                    }
                    if (res) {
                        float4 rr = *(const float4*)(res + (size_t)m * N + c);
                        v.x += rr.x; v.y += rr.y; v.z += rr.z; v.w += rr.w;
                    }
                    if (ROUND) {
                        v.x = rtf32(v.x); v.y = rtf32(v.y);
                        v.z = rtf32(v.z); v.w = rtf32(v.w);
                    }
                    *(float4*)(crow + c) = v;
                }
            }
        }
    }
    __syncthreads();
    if (wid == 0) TCGEN05_DEALLOC(tmem, 256);
#else
    // Fallback for the generic compute_103 PTX pass (never run on GB300).
    int m0 = blockIdx.y * GBM, n0 = blockIdx.x * GBN;
    for (int idx = threadIdx.x; idx < GBM * GBN; idx += blockDim.x) {
        int mi = idx / GBN, ni = idx % GBN;
        int m = m0 + mi, n = n0 + ni;
        if (m < M && n < N) {
            const float* a = Araw + (size_t)m * K;
            const float* b = Braw + (size_t)n * K;
            float acc = 0.f;
            for (int k = 0; k < K; k++) acc += a[k] * b[k];
            if (bias) acc += bias[n];
            if (res) acc += res[(size_t)m * N + n];
            if (ROUND) acc = rtf32(acc);
            C[(size_t)m * N + n] = acc;
        }
    }
#endif
}

// ---------------- weight rounding ----------------
__global__ void roundw_k(const float* __restrict__ src, float* __restrict__ dst, int n4) {
    int i = blockIdx.x * blockDim.x + threadIdx.x;
    if (i < n4) {
        float4 v = ((const float4*)src)[i];
        v.x = rtf32(v.x); v.y = rtf32(v.y); v.z = rtf32(v.z); v.w = rtf32(v.w);
        ((float4*)dst)[i] = v;
    }
}

// ---------------- rmsnorm ----------------
__global__ void rmsnorm_k(const float* __restrict__ x, const float* __restrict__ w,
                          float* __restrict__ out, int cols, float eps, int do_round) {
    int row = blockIdx.x;
    const float* xr = x + (size_t)row * cols;
    float ss = 0.f;
    for (int i = threadIdx.x; i < cols; i += blockDim.x) { float v = xr[i]; ss += v * v; }
    __shared__ float sh[32];
#pragma unroll
    for (int o = 16; o; o >>= 1) ss += __shfl_xor_sync(0xFFFFFFFFu, ss, o);
    if ((threadIdx.x & 31) == 0) sh[threadIdx.x >> 5] = ss;
    __syncthreads();
    if (threadIdx.x < 32) {
        float v = (threadIdx.x < (blockDim.x >> 5)) ? sh[threadIdx.x] : 0.f;
#pragma unroll
        for (int o = 16; o; o >>= 1) v += __shfl_xor_sync(0xFFFFFFFFu, v, o);
        if (threadIdx.x == 0) sh[0] = v;
    }
    __syncthreads();
    float scale = rsqrtf(sh[0] / (float)cols + eps);
    for (int i = threadIdx.x; i < cols; i += blockDim.x) {
        float v = xr[i] * scale * w[i];
        out[(size_t)row * cols + i] = do_round ? rtf32(v) : v;
    }
}

// ---------------- conv + silu ----------------
__global__ void conv_silu_k(const float* __restrict__ proj, const float* __restrict__ cw,
                            const float* __restrict__ cb, float* __restrict__ xbc) {
    int idx = blockIdx.x * blockDim.x + threadIdx.x;
    if (idx >= LMEM_ * CONVD_) return;
    int l = idx / CONVD_, c = idx % CONVD_;
    float acc = cb[c];
#pragma unroll
    for (int j = 0; j < CK_; j++) {
        int t = l + j - (CK_ - 1);
        if (t >= 0) acc += cw[c * CK_ + j] * proj[(size_t)t * NPROJ_ + INTER_ + c];
    }
    xbc[idx] = acc / (1.f + expf(-acc));
}

__global__ void dt_k(const float* __restrict__ proj, const float* __restrict__ dtb,
                     float* __restrict__ dt) {
    int idx = blockIdx.x * blockDim.x + threadIdx.x;
    if (idx >= LMEM_ * NH_) return;
    int l = idx / NH_, h = idx % NH_;
    float x = proj[(size_t)l * NPROJ_ + (INTER_ + CONVD_) + h] + dtb[h];
    dt[idx] = (x > 20.f) ? x : log1pf(expf(x));
}

// ---------------- mamba2 scan (R3 serial version — proven fastest) ----------------
__global__ void scan_k(const float* __restrict__ xbc, const float* __restrict__ dt,
                       const float* __restrict__ A_log, const float* __restrict__ Dp,
                       float* __restrict__ y) {
    int h = blockIdx.x;
    int tid = threadIdx.x;
    int g = h >> 2;
    float A  = -expf(A_log[h]);
    float Dh = Dp[h];
    __shared__ float Bs[2][S_], Cs[2][S_];
    float st[S_];
#pragma unroll
    for (int s = 0; s < S_; s++) st[s] = 0.f;

    float xv  = xbc[(size_t)0 * CONVD_ + h * HD_ + tid];
    float bv  = (tid < S_) ? xbc[INTER_ + g * S_ + tid]
                           : xbc[INTER_ + NG_ * S_ + g * S_ + (tid - S_)];
    float dtl = dt[h];

    for (int l = 0; l < LMEM_; l++) {
        int buf = l & 1;
        if (tid < S_) Bs[buf][tid] = bv; else Cs[buf][tid - S_] = bv;
        __syncthreads();
        float xn = 0.f, bn = 0.f, dtn = 0.f;
        if (l + 1 < LMEM_) {
            const float* nx = xbc + (size_t)(l + 1) * CONVD_;
            xn  = nx[h * HD_ + tid];
            bn  = (tid < S_) ? nx[INTER_ + g * S_ + tid]
                             : nx[INTER_ + NG_ * S_ + g * S_ + (tid - S_)];
            dtn = dt[(size_t)(l + 1) * NH_ + h];
        }
        float decay = expf(dtl * A);
        float dtx   = dtl * xv;
        float yv = 0.f;
#pragma unroll
        for (int s = 0; s < S_; s++) {
            st[s] = decay * st[s] + dtx * Bs[buf][s];
            yv += st[s] * Cs[buf][s];
        }
        yv += Dh * xv;
        y[(size_t)l * INTER_ + h * HD_ + tid] = yv;
        xv = xn; bv = bn; dtl = dtn;
    }
}

// ---------------- gated rmsnorm ----------------
__global__ void gatenorm_k(const float* __restrict__ y, const float* __restrict__ proj,
                           const float* __restrict__ mw, float* __restrict__ out) {
    int row = blockIdx.x;
    __shared__ float gsh[INTER_];
    __shared__ float sh[32];
    float ss = 0.f;
    for (int i = threadIdx.x; i < INTER_; i += blockDim.x) {
        float z  = proj[(size_t)row * NPROJ_ + i];
        float gv = y[(size_t)row * INTER_ + i] * (z / (1.f + expf(-z)));
        gsh[i] = gv;
        ss += gv * gv;
    }
#pragma unroll
    for (int o = 16; o; o >>= 1) ss += __shfl_xor_sync(0xFFFFFFFFu, ss, o);
    if ((threadIdx.x & 31) == 0) sh[threadIdx.x >> 5] = ss;
    __syncthreads();
    if (threadIdx.x < 32) {
        float v = (threadIdx.x < (blockDim.x >> 5)) ? sh[threadIdx.x] : 0.f;
#pragma unroll
        for (int o = 16; o; o >>= 1) v += __shfl_xor_sync(0xFFFFFFFFu, v, o);
        if (threadIdx.x == 0) sh[0] = v;
    }
    __syncthreads();
    float scale = rsqrtf(sh[0] / (float)INTER_ + MEPS_);
    for (int i = threadIdx.x; i < INTER_; i += blockDim.x)
        out[(size_t)row * INTER_ + i] = rtf32(gsh[i] * scale * mw[i]);
}

// ---------------- RoPE ----------------
__global__ void rope_q_k(float* __restrict__ q, const float* __restrict__ cosb,
                         const float* __restrict__ sinb) {
    int ri = blockIdx.y;
    int r = (ri < SINK_) ? ri : (T_ - WIN_) + (ri - SINK_);
    int i = blockIdx.x * blockDim.x + threadIdx.x;
    if (i >= NH_ * (HD_ / 2)) return;
    int hh = i >> 6, d = i & 63;
    float* qr = q + (size_t)r * (NH_ * HD_) + hh * HD_;
    float c0 = cosb[r * HD_ + d],      s0 = sinb[r * HD_ + d];
    float c1 = cosb[r * HD_ + d + 64], s1 = sinb[r * HD_ + d + 64];
    float a = qr[d], b = qr[d + 64];
    qr[d]      = a * c0 - b * s0;
    qr[d + 64] = b * c1 + a * s1;
}

__global__ void rope_k_k(float* __restrict__ k, const float* __restrict__ cosb,
                         const float* __restrict__ sinb) {
    int r = blockIdx.y;
    int i = threadIdx.x;
    if (i >= KVH_ * (HD_ / 2)) return;
    int hh = i >> 6, d = i & 63;
    float* kr = k + (size_t)r * (KVH_ * HD_) + hh * HD_;
    float c0 = cosb[r * HD_ + d],      s0 = sinb[r * HD_ + d];
    float c1 = cosb[r * HD_ + d + 64], s1 = sinb[r * HD_ + d + 64];
    float a = kr[d], b = kr[d + 64];
    kr[d]      = a * c0 - b * s0;
    kr[d + 64] = b * c1 + a * s1;
}

// ---------------- k/v row SINK replacement ----------------
__global__ void memact_kv_k(const float* __restrict__ merged,
                            const float* __restrict__ kw, const float* __restrict__ kb,
                            const float* __restrict__ vw, const float* __restrict__ vb,
                            float* __restrict__ kbuf, float* __restrict__ vbuf) {
    int p = blockIdx.x;
    const float* act = merged + (size_t)(SINK_ + LMEM_ - 1) * INTER_;
    int pp = (p < KVH_ * HD_) ? p : p - KVH_ * HD_;
    const float* W = (p < KVH_ * HD_) ? kw : vw;
    float bs       = (p < KVH_ * HD_) ? kb[pp] : vb[pp];
    float ss = 0.f;
    for (int i = threadIdx.x; i < H_; i += blockDim.x) ss += act[i] * W[(size_t)pp * H_ + i];
    __shared__ float sh[32];
#pragma unroll
    for (int o = 16; o; o >>= 1) ss += __shfl_xor_sync(0xFFFFFFFFu, ss, o);
    if ((threadIdx.x & 31) == 0) sh[threadIdx.x >> 5] = ss;
    __syncthreads();
    if (threadIdx.x == 0) {
        float v = 0.f;
        for (int w = 0; w < (int)(blockDim.x >> 5); w++) v += sh[w];
        v += bs;
        if (p < KVH_ * HD_) kbuf[(size_t)SINK_ * (KVH_ * HD_) + pp] = v;
        else                vbuf[(size_t)SINK_ * (KVH_ * HD_) + pp] = v;
    }
}

// ---------------- attention: 8-key ILP online softmax, fast exp ----------------
__global__ void attn_k(const float* __restrict__ q, const float* __restrict__ k,
                       const float* __restrict__ v, float* __restrict__ merged) {
    int wid_g = blockIdx.x * (blockDim.x >> 5) + (threadIdx.x >> 5);
    if (wid_g >= (SINK_ + WIN_) * NH_) return;
    int lane = threadIdx.x & 31;
    int ri = wid_g >> 4;
    int h  = wid_g & 15;
    int r  = (ri < SINK_) ? ri : (T_ - WIN_) + (ri - SINK_);
    int g  = h >> 2;
    const float4 q4 = *(const float4*)(q + (size_t)r * (NH_ * HD_) + h * HD_ + lane * 4);
    const float* kb = k + g * HD_ + lane * 4;
    const float* vb = v + g * HD_ + lane * 4;
    const float scale = 0.08838834764831845f;
    const float sink_bonus = 0.5f * (float)(T_ - SINK_ - WIN_) / (float)T_;
    float mmax = -1e30f, denom = 0.f;
    float4 acc = make_float4(0.f, 0.f, 0.f, 0.f);

    for (int seg = 0; seg < 2; seg++) {
        int cbeg = seg ? max(SINK_ + 1, r - WIN_) : 0;
        int cend = seg ? r : min(r, SINK_);
        int c = cbeg;
        // 8 keys: eight independent shfl chains share one latency window
        for (; c + 7 <= cend; c += 8) {
            float s[8];
#pragma unroll
            for (int j = 0; j < 8; j++) {
                float4 kk = *(const float4*)(kb + (size_t)(c + j) * (KVH_ * HD_));
                s[j] = q4.x * kk.x + q4.y * kk.y + q4.z * kk.z + q4.w * kk.w;
            }
#pragma unroll
            for (int o = 16; o; o >>= 1) {
#pragma unroll
                for (int j = 0; j < 8; j++)
                    s[j] += __shfl_xor_sync(0xFFFFFFFFu, s[j], o);
            }
#pragma unroll
            for (int j = 0; j < 8; j++)
                s[j] = s[j] * scale + ((c + j == SINK_) ? sink_bonus : 0.f);
            float m01 = fmaxf(s[0], s[1]), m23 = fmaxf(s[2], s[3]);
            float m45 = fmaxf(s[4], s[5]), m67 = fmaxf(s[6], s[7]);
            float mn = fmaxf(mmax, fmaxf(fmaxf(m01, m23), fmaxf(m45, m67)));
            float corr = __expf(mmax - mn);
            float p[8];
#pragma unroll
            for (int j = 0; j < 8; j++) p[j] = __expf(s[j] - mn);
            mmax = mn;
            denom = denom * corr +
                    (((p[0] + p[1]) + (p[2] + p[3])) + ((p[4] + p[5]) + (p[6] + p[7])));
            float4 vx[8];
#pragma unroll
            for (int j = 0; j < 8; j++)
                vx[j] = *(const float4*)(vb + (size_t)(c + j) * (KVH_ * HD_));
            float ax = 0.f, ay = 0.f, az = 0.f, aw = 0.f;
#pragma unroll
            for (int j = 0; j < 8; j++) {
                ax += p[j] * vx[j].x; ay += p[j] * vx[j].y;
                az += p[j] * vx[j].z; aw += p[j] * vx[j].w;
            }
            acc.x = acc.x * corr + ax;
            acc.y = acc.y * corr + ay;
            acc.z = acc.z * corr + az;
            acc.w = acc.w * corr + aw;
        }
        // remainder keys (up to 7)
        for (; c <= cend; c++) {
            const float4 k0 = *(const float4*)(kb + (size_t)c * (KVH_ * HD_));
            float s0 = q4.x * k0.x + q4.y * k0.y + q4.z * k0.z + q4.w * k0.w;
#pragma unroll
            for (int o = 16; o; o >>= 1) s0 += __shfl_xor_sync(0xFFFFFFFFu, s0, o);
            s0 = s0 * scale + ((c == SINK_) ? sink_bonus : 0.f);
            float mn = fmaxf(mmax, s0);
            float corr = __expf(mmax - mn);
            float p0 = __expf(s0 - mn);
            mmax = mn;
            denom = denom * corr + p0;
            const float4 v0 = *(const float4*)(vb + (size_t)c * (KVH_ * HD_));
            acc.x = acc.x * corr + p0 * v0.x;
            acc.y = acc.y * corr + p0 * v0.y;
            acc.z = acc.z * corr + p0 * v0.z;
            acc.w = acc.w * corr + p0 * v0.w;
        }
    }
    float inv = 1.f / denom;
    float4 o4;
    o4.x = rtf32(acc.x * inv); o4.y = rtf32(acc.y * inv);
    o4.z = rtf32(acc.z * inv); o4.w = rtf32(acc.w * inv);
    *(float4*)(merged + (size_t)r * INTER_ + h * HD_ + lane * 4) = o4;
}

// ---------------- elementwise ----------------
__global__ void swiglu_fused_k(const float* __restrict__ gu, float* __restrict__ o) {
    int i = blockIdx.x * blockDim.x + threadIdx.x;
    if (i >= T_ * MLPI_) return;
    int row = i / MLPI_, c = i % MLPI_;
    float x = gu[(size_t)row * (2 * MLPI_) + c];
    float u = gu[(size_t)row * (2 * MLPI_) + MLPI_ + c];
    o[i] = rtf32((x / (1.f + expf(-x))) * u);
}

// ---------------- host ----------------
typedef CUresult (*PFN_encodeTiled)(CUtensorMap*, CUtensorMapDataType, cuuint32_t, void*,
                                    const cuuint64_t*, const cuuint64_t*, const cuuint32_t*,
                                    const cuuint32_t*, CUtensorMapInterleave, CUtensorMapSwizzle,
                                    CUtensorMapL2promotion, CUtensorMapFloatOOBfill);

static PFN_encodeTiled get_encoder() {
    void* p = nullptr;
    cudaDriverEntryPointQueryResult st;
    cudaGetDriverEntryPointByVersion("cuTensorMapEncodeTiled", &p, 12000, cudaEnableDefault, &st);
    return (PFN_encodeTiled)p;
}

static void make_tm(PFN_encodeTiled enc, CUtensorMap* tm, const float* base,
                    int rows, int cols, int box_rows) {
    cuuint64_t dims[2]    = {(cuuint64_t)cols, (cuuint64_t)rows};
    cuuint64_t strides[1] = {(cuuint64_t)cols * 4};
    cuuint32_t box[2]     = {32u, (cuuint32_t)box_rows};
    cuuint32_t es[2]      = {1u, 1u};
    enc(tm, CU_TENSOR_MAP_DATA_TYPE_FLOAT32, 2, (void*)base, dims, strides, box, es,
        CU_TENSOR_MAP_INTERLEAVE_NONE, CU_TENSOR_MAP_SWIZZLE_128B,
        CU_TENSOR_MAP_L2_PROMOTION_L2_128B, CU_TENSOR_MAP_FLOAT_OOB_FILL_NONE);
}

static PFN_encodeTiled g_enc = nullptr;

static void launch_gemm_tc(const float* A, const float* B,
                           const float* bias, const float* res, float* C,
                           int M, int N, int K, bool roundOut) {
    CUtensorMap tmA, tmB;
    make_tm(g_enc, &tmA, A, M, K, 128);
    make_tm(g_enc, &tmB, B, N, K, 256);
    dim3 grid((N + GBN - 1) / GBN, (M + GBM - 1) / GBM);
    if (roundOut) gemm_tc<true><<<grid, 128, GSMEM>>>(tmA, tmB, A, B, bias, res, C, M, N, K);
    else          gemm_tc<false><<<grid, 128, GSMEM>>>(tmA, tmB, A, B, bias, res, C, M, N, K);
}

static void roundw(const float* src, float* dst, int n) {
    int n4 = n / 4;
    roundw_k<<<(n4 + 255) / 256, 256>>>(src, dst, n4);
}

extern "C" void kernel_launch(void* const* d_in, const int* in_sizes, int n_in,
                              void* d_out, int out_size) {
    const float* hs      = (const float*)d_in[0];
    const float* cosb    = (const float*)d_in[1];
    const float* sinb    = (const float*)d_in[2];
    const float* ln1_w   = (const float*)d_in[3];
    const float* q_w     = (const float*)d_in[4];
    const float* q_b     = (const float*)d_in[5];
    const float* k_w     = (const float*)d_in[6];
    const float* k_b     = (const float*)d_in[7];
    const float* v_w     = (const float*)d_in[8];
    const float* v_b     = (const float*)d_in[9];
    const float* o_w     = (const float*)d_in[10];
    const float* inpj_w  = (const float*)d_in[11];
    const float* conv_w  = (const float*)d_in[12];
    const float* conv_b  = (const float*)d_in[13];
    const float* dt_bias = (const float*)d_in[14];
    const float* A_log   = (const float*)d_in[15];
    const float* Dp      = (const float*)d_in[16];
    const float* mnorm_w = (const float*)d_in[17];
    const float* outp_w  = (const float*)d_in[18];
    const float* ln2_w   = (const float*)d_in[19];
    const float* gate_w  = (const float*)d_in[20];
    const float* up_w    = (const float*)d_in[21];
    const float* down_w  = (const float*)d_in[22];
    float* out = (float*)d_out;

    float *pre, *proj, *xbc, *dtb, *ybuf, *gbuf, *qb, *kb, *vb, *merged, *hb, *mb, *gub, *gateb;
    float *wq, *wk, *wv, *wo, *win, *wout, *wgu, *wd;
    cudaGetSymbolAddress((void**)&pre,    g_pre);
    cudaGetSymbolAddress((void**)&proj,   g_proj);
    cudaGetSymbolAddress((void**)&xbc,    g_xbc);
    cudaGetSymbolAddress((void**)&dtb,    g_dt);
    cudaGetSymbolAddress((void**)&ybuf,   g_y);
    cudaGetSymbolAddress((void**)&gbuf,   g_g);
    cudaGetSymbolAddress((void**)&qb,     g_q);
    cudaGetSymbolAddress((void**)&kb,     g_k);
    cudaGetSymbolAddress((void**)&vb,     g_v);
    cudaGetSymbolAddress((void**)&merged, g_merged);
    cudaGetSymbolAddress((void**)&hb,     g_h);
    cudaGetSymbolAddress((void**)&mb,     g_m);
    cudaGetSymbolAddress((void**)&gub,    g_gu);
    cudaGetSymbolAddress((void**)&gateb,  g_gate);
    cudaGetSymbolAddress((void**)&wq,     g_wq);
    cudaGetSymbolAddress((void**)&wk,     g_wk);
    cudaGetSymbolAddress((void**)&wv,     g_wv);
    cudaGetSymbolAddress((void**)&wo,     g_wo);
    cudaGetSymbolAddress((void**)&win,    g_win);
    cudaGetSymbolAddress((void**)&wout,   g_wout);
    cudaGetSymbolAddress((void**)&wgu,    g_wgu);
    cudaGetSymbolAddress((void**)&wd,     g_wd);

    if (!g_enc) g_enc = get_encoder();
    static bool attrs_set = false;
    if (!attrs_set) {
        cudaFuncSetAttribute(gemm_tc<false>, cudaFuncAttributeMaxDynamicSharedMemorySize, GSMEM);
        cudaFuncSetAttribute(gemm_tc<true>,  cudaFuncAttributeMaxDynamicSharedMemorySize, GSMEM);
        attrs_set = true;
    }

    // 0. round weights to tf32 (unbiased rna); gate|up concatenated
    roundw(q_w,    wq,   NH_ * HD_ * H_);
    roundw(k_w,    wk,   KVH_ * HD_ * H_);
    roundw(v_w,    wv,   KVH_ * HD_ * H_);
    roundw(o_w,    wo,   H_ * NH_ * HD_);
    roundw(inpj_w, win,  NPROJ_ * H_);
    roundw(outp_w, wout, H_ * INTER_);
    roundw(gate_w, wgu,                       MLPI_ * H_);
    roundw(up_w,   wgu + (size_t)MLPI_ * H_,  MLPI_ * H_);
    roundw(down_w, wd,   H_ * MLPI_);

    // 1. pre-norm (tf32-rounded: feeds GEMMs only)
    rmsnorm_k<<<T_, 256>>>(hs, ln1_w, pre, H_, EPS_, 1);

    // 2. mamba branch on pre rows [64, 1536)
    launch_gemm_tc(pre + (size_t)SINK_ * H_, win, nullptr, nullptr, proj, LMEM_, NPROJ_, H_, false);
    conv_silu_k<<<(LMEM_ * CONVD_ + 255) / 256, 256>>>(proj, conv_w, conv_b, xbc);
    dt_k<<<(LMEM_ * NH_ + 255) / 256, 256>>>(proj, dt_bias, dtb);
    scan_k<<<NH_, 128>>>(xbc, dtb, A_log, Dp, ybuf);
    gatenorm_k<<<LMEM_, 256>>>(ybuf, proj, mnorm_w, gbuf);
    launch_gemm_tc(gbuf, wout, nullptr, nullptr, merged + (size_t)SINK_ * INTER_, LMEM_, INTER_, H_, true);

    // 3. q projection on consumed rows only; full k/v
    launch_gemm_tc(pre, wq, q_b, nullptr, qb, SINK_, NH_ * HD_, H_, false);
    launch_gemm_tc(pre + (size_t)(T_ - WIN_) * H_, wq, q_b, nullptr,
                   qb + (size_t)(T_ - WIN_) * (NH_ * HD_), WIN_, NH_ * HD_, H_, false);
    launch_gemm_tc(pre, wk, k_b, nullptr, kb, T_, KVH_ * HD_, H_, false);
    launch_gemm_tc(pre, wv, v_b, nullptr, vb, T_, KVH_ * HD_, H_, false);

    // 4. RoPE
    rope_q_k<<<dim3(4, SINK_ + WIN_), 256>>>(qb, cosb, sinb);
    rope_k_k<<<dim3(1, T_), 256>>>(kb, cosb, sinb);

    // 5. replace k/v at row SINK with mem_act projection (exact fp32 GEMV)
    memact_kv_k<<<2 * KVH_ * HD_, 256>>>(merged, k_w, k_b, v_w, v_b, kb, vb);

    // 6. attention -> merged rows [0,64) and [1536,2048)
    attn_k<<<((SINK_ + WIN_) * NH_ + 7) / 8, 256>>>(qb, kb, vb, merged);

    // 7. o projection + FUSED residual -> hb
    launch_gemm_tc(merged, wo, nullptr, hs, hb, T_, H_, NH_ * HD_, false);

    // 8. MLP (gate+up fused); down-proj + FUSED residual -> out
    rmsnorm_k<<<T_, 256>>>(hb, ln2_w, mb, H_, EPS_, 1);
    launch_gemm_tc(mb, wgu, nullptr, nullptr, gub, T_, 2 * MLPI_, H_, false);
    swiglu_fused_k<<<(T_ * MLPI_ + 255) / 256, 256>>>(gub, gateb);
    launch_gemm_tc(gateb, wd, nullptr, hb, out, T_, H_, MLPI_, false);
}

// round 16
// speedup vs baseline: 1.1451x; 1.0050x over previous
#include <cuda_runtime.h>
#include <cuda.h>
#include <cuda_bf16.h>
#include <math.h>
#include <stdint.h>

// ---------------- constants ----------------
#define T_      2048
#define H_      2048
#define NH_     16
#define KVH_    4
#define HD_     128
#define WIN_    512
#define SINK_   64
#define S_      64
#define NG_     4
#define MLPI_   5504
#define CK_     4
#define INTER_  2048
#define CONVD_  2560
#define NPROJ_  4624
#define LMEM_   1472
#define EPS_    1e-6f
#define MEPS_   1e-5f

// ---------------- scratch ----------------
__device__ float g_pre   [T_ * H_];
__device__ float g_proj  [LMEM_ * NPROJ_];
__device__ float g_xbc   [LMEM_ * CONVD_];
__device__ float g_dt    [LMEM_ * NH_];
__device__ float g_y     [LMEM_ * INTER_];
__device__ float g_g     [LMEM_ * INTER_];
__device__ float g_q     [T_ * (NH_ * HD_)];
__device__ float g_k     [T_ * (KVH_ * HD_)];
__device__ float g_v     [T_ * (KVH_ * HD_)];
__device__ float g_merged[T_ * INTER_];
__device__ float g_h     [T_ * H_];
__device__ float g_m     [T_ * H_];
__device__ float g_gu    [T_ * 2 * MLPI_];
__device__ float g_gate  [T_ * MLPI_];
// tf32-rounded weight copies
__device__ float g_wq  [(NH_*HD_) * H_];
__device__ float g_wk  [(KVH_*HD_) * H_];
__device__ float g_wv  [(KVH_*HD_) * H_];
__device__ float g_wo  [H_ * (NH_*HD_)];
__device__ float g_win [NPROJ_ * H_];
__device__ float g_wout[H_ * INTER_];
__device__ float g_wgu [2 * MLPI_ * H_];
__device__ float g_wd  [H_ * MLPI_];

// ---------------- ptx helpers (baseline-safe) ----------------
__device__ __forceinline__ uint32_t smem_u32(const void* p) {
    uint32_t a;
    asm("{ .reg .u64 t; cvta.to.shared.u64 t, %1; cvt.u32.u64 %0, t; }" : "=r"(a) : "l"(p));
    return a;
}
__device__ __forceinline__ float rtf32(float x) {
    float y; asm("cvt.rna.tf32.f32 %0, %1;" : "=f"(y) : "f"(x)); return y;
}
// fast silu: x / (1 + e^-x) with MUFU exp + fast division
__device__ __forceinline__ float fsilu(float x) {
    return __fdividef(x, 1.f + __expf(-x));
}

#define MBARRIER_INIT(addr, cnt) \
    asm volatile("mbarrier.init.shared.b64 [%0], %1;" :: "r"((uint32_t)(addr)), "r"((uint32_t)(cnt)) : "memory")
#define MBARRIER_EXPECT_TX(addr, bytes) \
    asm volatile("mbarrier.arrive.expect_tx.shared.b64 _, [%0], %1;" :: "r"((uint32_t)(addr)), "r"((uint32_t)(bytes)) : "memory")
#define MBARRIER_WAIT_PARITY(addr, ph) do { \
    uint32_t _m = (uint32_t)(addr); uint32_t _p = (uint32_t)(ph); uint32_t _d; \
    asm volatile("{\n\t.reg .pred p;\n\t" \
        "mbarrier.try_wait.parity.acquire.cta.shared::cta.b64 p, [%1], %2;\n\t" \
        "selp.b32 %0, 1, 0, p;\n\t}" : "=r"(_d) : "r"(_m), "r"(_p) : "memory"); \
    if (!_d) { asm volatile("{\n\t.reg .pred P1;\n\t" \
        "WL_%=:\n\t" \
        "mbarrier.try_wait.parity.acquire.cta.shared::cta.b64 P1, [%0], %1, 0x989680;\n\t" \
        "@P1 bra.uni WD_%=;\n\tbra.uni WL_%=;\n\tWD_%=:\n\t}" \
        :: "r"(_m), "r"(_p) : "memory"); } \
} while (0)

__device__ __forceinline__ void tma2d(uint32_t smem, const void* tm, int x, int y, uint32_t mbar) {
    asm volatile("cp.async.bulk.tensor.2d.shared::cta.global.tile.mbarrier::complete_tx::bytes "
                 "[%0], [%1, {%2, %3}], [%4];"
                 :: "r"(smem), "l"(tm), "r"(x), "r"(y), "r"(mbar) : "memory");
}

// ---------------- tcgen05 (arch-specific: sm_103a pass only) ----------------
#if defined(__CUDA_ARCH_FEAT_SM103_ALL)
#define HAS_TCGEN05 1

#define TCGEN05_ALLOC(smem_addr, nCols) \
    asm volatile("tcgen05.alloc.cta_group::1.sync.aligned.shared::cta.b32 [%0], %1;" \
        :: "r"((uint32_t)(smem_addr)), "r"((uint32_t)(nCols)) : "memory")
#define TCGEN05_DEALLOC(tmem, nCols) \
    asm volatile("tcgen05.dealloc.cta_group::1.sync.aligned.b32 %0, %1;" :: "r"(tmem), "r"((uint32_t)(nCols)))
#define TCGEN05_COMMIT(mbar) \
    asm volatile("tcgen05.commit.cta_group::1.mbarrier::arrive::one.shared::cluster.b64 [%0];" \
        :: "r"((uint32_t)(mbar)) : "memory")
#define TCGEN05_FENCE_AFTER() asm volatile("tcgen05.fence::after_thread_sync;" ::: "memory")
#define TCGEN05_WAIT_LD() asm volatile("tcgen05.wait::ld.sync.aligned;" ::: "memory")

#define TCGEN05_LD_32X32B_X32(r, tmem_addr) \
    asm volatile("tcgen05.ld.sync.aligned.32x32b.x32.b32 " \
        "{%0, %1, %2, %3, %4, %5, %6, %7, %8, %9, %10, %11, %12, %13, %14, %15, " \
        " %16, %17, %18, %19, %20, %21, %22, %23, %24, %25, %26, %27, %28, %29, %30, %31}, [%32];" \
        : "=r"((r)[0]),  "=r"((r)[1]),  "=r"((r)[2]),  "=r"((r)[3]), \
          "=r"((r)[4]),  "=r"((r)[5]),  "=r"((r)[6]),  "=r"((r)[7]), \
          "=r"((r)[8]),  "=r"((r)[9]),  "=r"((r)[10]), "=r"((r)[11]), \
          "=r"((r)[12]), "=r"((r)[13]), "=r"((r)[14]), "=r"((r)[15]), \
          "=r"((r)[16]), "=r"((r)[17]), "=r"((r)[18]), "=r"((r)[19]), \
          "=r"((r)[20]), "=r"((r)[21]), "=r"((r)[22]), "=r"((r)[23]), \
          "=r"((r)[24]), "=r"((r)[25]), "=r"((r)[26]), "=r"((r)[27]), \
          "=r"((r)[28]), "=r"((r)[29]), "=r"((r)[30]), "=r"((r)[31]) \
        : "r"(tmem_addr))

__device__ __forceinline__ void mma_tf32_ss(uint32_t d, uint64_t ad, uint64_t bd,
                                            uint32_t idesc, uint32_t en) {
    asm volatile("{\n\t.reg .pred p;\n\tsetp.ne.u32 p, %4, 0;\n\t"
                 "tcgen05.mma.cta_group::1.kind::tf32 [%0], %1, %2, %3, {%5, %5, %5, %5}, p;\n\t}"
                 :: "r"(d), "l"(ad), "l"(bd), "r"(idesc), "r"(en), "r"(0u) : "memory");
}
#endif

// SW128 K-major SMEM descriptor (LBO=1, SBO=64, version=1)
static constexpr uint64_t SMEM_DESC_BASE_SW128 =
    (uint64_t(2) << 61) | (uint64_t(1) << 46) | (uint64_t(64) << 32) | (uint64_t(1) << 16);
#define MAKE_SMEM_DESC(base_addr) (SMEM_DESC_BASE_SW128 | ((uint64_t)((base_addr) >> 4) & 0x3FFF))

// ---------------- tcgen05 tf32 GEMM: C[M,N] = A[M,K] * B[N,K]^T (+bias) (+res) ----------------
#define GBM 128
#define GBN 256
#define GBK 32
#define GDEPTH 4
#define SM_A_OFF 1024
#define SM_B_OFF (1024 + GDEPTH * 16384)
#define GSMEM (1024 + GDEPTH * 16384 + GDEPTH * 32768)

template<bool ROUND>
__global__ void __launch_bounds__(128, 1)
gemm_tc(const __grid_constant__ CUtensorMap tmA,
        const __grid_constant__ CUtensorMap tmB,
        const float* __restrict__ Araw, const float* __restrict__ Braw,
        const float* __restrict__ bias, const float* __restrict__ res,
        float* __restrict__ C, int M, int N, int K) {
#if defined(HAS_TCGEN05)
    extern __shared__ __align__(1024) char smem[];
    uint32_t sb = smem_u32(smem);
    int tid = threadIdx.x, wid = tid >> 5, lane = tid & 31;
    int m0 = blockIdx.y * GBM, n0 = blockIdx.x * GBN;

    if (wid == 0) TCGEN05_ALLOC(sb + 0, 256);
    if (tid == 0) {
        for (int s = 0; s < GDEPTH; s++) {
            MBARRIER_INIT(sb + 8 + s * 16, 1);       // full
            MBARRIER_INIT(sb + 8 + s * 16 + 8, 1);   // empty
        }
    }
    __syncthreads();
    uint32_t tmem;
    asm volatile("ld.shared.b32 %0, [%1];" : "=r"(tmem) : "r"(sb + 0));

    int nst = K / GBK;
    if (tid == 0) {
        int pre = nst < GDEPTH ? nst : GDEPTH;
        for (int s = 0; s < pre; s++) {
            uint32_t full = sb + 8 + s * 16;
            MBARRIER_EXPECT_TX(full, 49152);
            tma2d(sb + SM_A_OFF + s * 16384, &tmA, s * GBK, m0, full);
            tma2d(sb + SM_B_OFF + s * 32768, &tmB, s * GBK, n0, full);
        }
        const uint32_t idesc = (1u << 4) | (2u << 7) | (2u << 10) |
                               ((GBN / 8) << 17) | ((GBM / 16) << 24);
        for (int s = 0; s < nst; s++) {
            int slot = s & (GDEPTH - 1);
            int ph = (s / GDEPTH) & 1;
            uint32_t full = sb + 8 + slot * 16;
            uint32_t empty = full + 8;
            MBARRIER_WAIT_PARITY(full, ph);
            uint64_t ad = MAKE_SMEM_DESC(sb + SM_A_OFF + slot * 16384);
            uint64_t bd = MAKE_SMEM_DESC(sb + SM_B_OFF + slot * 32768);
#pragma unroll
            for (int kk = 0; kk < 4; kk++)
                mma_tf32_ss(tmem, ad + kk * 2, bd + kk * 2, idesc,
                            (s > 0 || kk > 0) ? 1u : 0u);
            TCGEN05_COMMIT(empty);
            if (s > 0) {
                int rs = s - 1 + GDEPTH;
                if (rs < nst) {
                    int rslot = (s - 1) & (GDEPTH - 1);
                    int rph = ((s - 1) / GDEPTH) & 1;
                    uint32_t rfull = sb + 8 + rslot * 16;
                    MBARRIER_WAIT_PARITY(rfull + 8, rph);
                    MBARRIER_EXPECT_TX(rfull, 49152);
                    tma2d(sb + SM_A_OFF + rslot * 16384, &tmA, rs * GBK, m0, rfull);
                    tma2d(sb + SM_B_OFF + rslot * 32768, &tmB, rs * GBK, n0, rfull);
                }
            }
        }
        int ls = nst - 1;
        MBARRIER_WAIT_PARITY(sb + 8 + (ls & (GDEPTH - 1)) * 16 + 8, (ls / GDEPTH) & 1);
    }
    __syncthreads();
    TCGEN05_FENCE_AFTER();

    int m = m0 + wid * 32 + lane;
    bool mok = (m < M);
#pragma unroll 1
    for (int b = 0; b < 8; b++) {
        uint32_t r[32];
        TCGEN05_LD_32X32B_X32(r, tmem + b * 32);
        TCGEN05_WAIT_LD();
        if (mok) {
            float* crow = C + (size_t)m * N;
#pragma unroll
            for (int j4 = 0; j4 < 8; j4++) {
                int c = n0 + b * 32 + j4 * 4;
                if (c < N) {
                    float4 v;
                    v.x = __uint_as_float(r[j4 * 4 + 0]);
                    v.y = __uint_as_float(r[j4 * 4 + 1]);
                    v.z = __uint_as_float(r[j4 * 4 + 2]);
                    v.w = __uint_as_float(r[j4 * 4 + 3]);
                    if (bias) {
                        float4 bb = *(const float4*)(bias + c);
                        v.x += bb.x; v.y += bb.y; v.z += bb.z; v.w += bb.w;
                    }
                    if (res) {
                        float4 rr = *(const float4*)(res + (size_t)m * N + c);
                        v.x += rr.x; v.y += rr.y; v.z += rr.z; v.w += rr.w;
                    }
                    if (ROUND) {
                        v.x = rtf32(v.x); v.y = rtf32(v.y);
                        v.z = rtf32(v.z); v.w = rtf32(v.w);
                    }
                    *(float4*)(crow + c) = v;
                }
            }
        }
    }
    __syncthreads();
    if (wid == 0) TCGEN05_DEALLOC(tmem, 256);
#else
    // Fallback for the generic compute_103 PTX pass (never run on GB300).
    int m0 = blockIdx.y * GBM, n0 = blockIdx.x * GBN;
    for (int idx = threadIdx.x; idx < GBM * GBN; idx += blockDim.x) {
        int mi = idx / GBN, ni = idx % GBN;
        int m = m0 + mi, n = n0 + ni;
        if (m < M && n < N) {
            const float* a = Araw + (size_t)m * K;
            const float* b = Braw + (size_t)n * K;
            float acc = 0.f;
            for (int k = 0; k < K; k++) acc += a[k] * b[k];
            if (bias) acc += bias[n];
            if (res) acc += res[(size_t)m * N + n];
            if (ROUND) acc = rtf32(acc);
            C[(size_t)m * N + n] = acc;
        }
    }
#endif
}

// ---------------- weight rounding ----------------
__global__ void roundw_k(const float* __restrict__ src, float* __restrict__ dst, int n4) {
    int i = blockIdx.x * blockDim.x + threadIdx.x;
    if (i < n4) {
        float4 v = ((const float4*)src)[i];
        v.x = rtf32(v.x); v.y = rtf32(v.y); v.z = rtf32(v.z); v.w = rtf32(v.w);
        ((float4*)dst)[i] = v;
    }
}

// ---------------- rmsnorm ----------------
__global__ void rmsnorm_k(const float* __restrict__ x, const float* __restrict__ w,
                          float* __restrict__ out, int cols, float eps, int do_round) {
    int row = blockIdx.x;
    const float* xr = x + (size_t)row * cols;
    float ss = 0.f;
    for (int i = threadIdx.x; i < cols; i += blockDim.x) { float v = xr[i]; ss += v * v; }
    __shared__ float sh[32];
#pragma unroll
    for (int o = 16; o; o >>= 1) ss += __shfl_xor_sync(0xFFFFFFFFu, ss, o);
    if ((threadIdx.x & 31) == 0) sh[threadIdx.x >> 5] = ss;
    __syncthreads();
    if (threadIdx.x < 32) {
        float v = (threadIdx.x < (blockDim.x >> 5)) ? sh[threadIdx.x] : 0.f;
#pragma unroll
        for (int o = 16; o; o >>= 1) v += __shfl_xor_sync(0xFFFFFFFFu, v, o);
        if (threadIdx.x == 0) sh[0] = v;
    }
    __syncthreads();
    float scale = rsqrtf(sh[0] / (float)cols + eps);
    for (int i = threadIdx.x; i < cols; i += blockDim.x) {
        float v = xr[i] * scale * w[i];
        out[(size_t)row * cols + i] = do_round ? rtf32(v) : v;
    }
}

// ---------------- conv + silu (fast silu) ----------------
__global__ void conv_silu_k(const float* __restrict__ proj, const float* __restrict__ cw,
                            const float* __restrict__ cb, float* __restrict__ xbc) {
    int idx = blockIdx.x * blockDim.x + threadIdx.x;
    if (idx >= LMEM_ * CONVD_) return;
    int l = idx / CONVD_, c = idx % CONVD_;
    float acc = cb[c];
#pragma unroll
    for (int j = 0; j < CK_; j++) {
        int t = l + j - (CK_ - 1);
        if (t >= 0) acc += cw[c * CK_ + j] * proj[(size_t)t * NPROJ_ + INTER_ + c];
    }
    xbc[idx] = fsilu(acc);
}

__global__ void dt_k(const float* __restrict__ proj, const float* __restrict__ dtb,
                     float* __restrict__ dt) {
    int idx = blockIdx.x * blockDim.x + threadIdx.x;
    if (idx >= LMEM_ * NH_) return;
    int l = idx / NH_, h = idx % NH_;
    float x = proj[(size_t)l * NPROJ_ + (INTER_ + CONVD_) + h] + dtb[h];
    dt[idx] = (x > 20.f) ? x : log1pf(expf(x));
}

// ---------------- mamba2 scan (R3 serial version — proven fastest) ----------------
__global__ void scan_k(const float* __restrict__ xbc, const float* __restrict__ dt,
                       const float* __restrict__ A_log, const float* __restrict__ Dp,
                       float* __restrict__ y) {
    int h = blockIdx.x;
    int tid = threadIdx.x;
    int g = h >> 2;
    float A  = -expf(A_log[h]);
    float Dh = Dp[h];
    __shared__ float Bs[2][S_], Cs[2][S_];
    float st[S_];
#pragma unroll
    for (int s = 0; s < S_; s++) st[s] = 0.f;

    float xv  = xbc[(size_t)0 * CONVD_ + h * HD_ + tid];
    float bv  = (tid < S_) ? xbc[INTER_ + g * S_ + tid]
                           : xbc[INTER_ + NG_ * S_ + g * S_ + (tid - S_)];
    float dtl = dt[h];

    for (int l = 0; l < LMEM_; l++) {
        int buf = l & 1;
        if (tid < S_) Bs[buf][tid] = bv; else Cs[buf][tid - S_] = bv;
        __syncthreads();
        float xn = 0.f, bn = 0.f, dtn = 0.f;
        if (l + 1 < LMEM_) {
            const float* nx = xbc + (size_t)(l + 1) * CONVD_;
            xn  = nx[h * HD_ + tid];
            bn  = (tid < S_) ? nx[INTER_ + g * S_ + tid]
                             : nx[INTER_ + NG_ * S_ + g * S_ + (tid - S_)];
            dtn = dt[(size_t)(l + 1) * NH_ + h];
        }
        float decay = expf(dtl * A);
        float dtx   = dtl * xv;
        float yv = 0.f;
#pragma unroll
        for (int s = 0; s < S_; s++) {
            st[s] = decay * st[s] + dtx * Bs[buf][s];
            yv += st[s] * Cs[buf][s];
        }
        yv += Dh * xv;
        y[(size_t)l * INTER_ + h * HD_ + tid] = yv;
        xv = xn; bv = bn; dtl = dtn;
    }
}

// ---------------- gated rmsnorm (fast silu) ----------------
__global__ void gatenorm_k(const float* __restrict__ y, const float* __restrict__ proj,
                           const float* __restrict__ mw, float* __restrict__ out) {
    int row = blockIdx.x;
    __shared__ float gsh[INTER_];
    __shared__ float sh[32];
    float ss = 0.f;
    for (int i = threadIdx.x; i < INTER_; i += blockDim.x) {
        float z  = proj[(size_t)row * NPROJ_ + i];
        float gv = y[(size_t)row * INTER_ + i] * fsilu(z);
        gsh[i] = gv;
        ss += gv * gv;
    }
#pragma unroll
    for (int o = 16; o; o >>= 1) ss += __shfl_xor_sync(0xFFFFFFFFu, ss, o);
    if ((threadIdx.x & 31) == 0) sh[threadIdx.x >> 5] = ss;
    __syncthreads();
    if (threadIdx.x < 32) {
        float v = (threadIdx.x < (blockDim.x >> 5)) ? sh[threadIdx.x] : 0.f;
#pragma unroll
        for (int o = 16; o; o >>= 1) v += __shfl_xor_sync(0xFFFFFFFFu, v, o);
        if (threadIdx.x == 0) sh[0] = v;
    }
    __syncthreads();
    float scale = rsqrtf(sh[0] / (float)INTER_ + MEPS_);
    for (int i = threadIdx.x; i < INTER_; i += blockDim.x)
        out[(size_t)row * INTER_ + i] = rtf32(gsh[i] * scale * mw[i]);
}

// ---------------- RoPE ----------------
__global__ void rope_q_k(float* __restrict__ q, const float* __restrict__ cosb,
                         const float* __restrict__ sinb) {
    int ri = blockIdx.y;
    int r = (ri < SINK_) ? ri : (T_ - WIN_) + (ri - SINK_);
    int i = blockIdx.x * blockDim.x + threadIdx.x;
    if (i >= NH_ * (HD_ / 2)) return;
    int hh = i >> 6, d = i & 63;
    float* qr = q + (size_t)r * (NH_ * HD_) + hh * HD_;
    float c0 = cosb[r * HD_ + d],      s0 = sinb[r * HD_ + d];
    float c1 = cosb[r * HD_ + d + 64], s1 = sinb[r * HD_ + d + 64];
    float a = qr[d], b = qr[d + 64];
    qr[d]      = a * c0 - b * s0;
    qr[d + 64] = b * c1 + a * s1;
}

__global__ void rope_k_k(float* __restrict__ k, const float* __restrict__ cosb,
                         const float* __restrict__ sinb) {
    int r = blockIdx.y;
    int i = threadIdx.x;
    if (i >= KVH_ * (HD_ / 2)) return;
    int hh = i >> 6, d = i & 63;
    float* kr = k + (size_t)r * (KVH_ * HD_) + hh * HD_;
    float c0 = cosb[r * HD_ + d],      s0 = sinb[r * HD_ + d];
    float c1 = cosb[r * HD_ + d + 64], s1 = sinb[r * HD_ + d + 64];
    float a = kr[d], b = kr[d + 64];
    kr[d]      = a * c0 - b * s0;
    kr[d + 64] = b * c1 + a * s1;
}

// ---------------- k/v row SINK replacement ----------------
__global__ void memact_kv_k(const float* __restrict__ merged,
                            const float* __restrict__ kw, const float* __restrict__ kb,
                            const float* __restrict__ vw, const float* __restrict__ vb,
                            float* __restrict__ kbuf, float* __restrict__ vbuf) {
    int p = blockIdx.x;
    const float* act = merged + (size_t)(SINK_ + LMEM_ - 1) * INTER_;
    int pp = (p < KVH_ * HD_) ? p : p - KVH_ * HD_;
    const float* W = (p < KVH_ * HD_) ? kw : vw;
    float bs       = (p < KVH_ * HD_) ? kb[pp] : vb[pp];
    float ss = 0.f;
    for (int i = threadIdx.x; i < H_; i += blockDim.x) ss += act[i] * W[(size_t)pp * H_ + i];
    __shared__ float sh[32];
#pragma unroll
    for (int o = 16; o; o >>= 1) ss += __shfl_xor_sync(0xFFFFFFFFu, ss, o);
    if ((threadIdx.x & 31) == 0) sh[threadIdx.x >> 5] = ss;
    __syncthreads();
    if (threadIdx.x == 0) {
        float v = 0.f;
        for (int w = 0; w < (int)(blockDim.x >> 5); w++) v += sh[w];
        v += bs;
        if (p < KVH_ * HD_) kbuf[(size_t)SINK_ * (KVH_ * HD_) + pp] = v;
        else                vbuf[(size_t)SINK_ * (KVH_ * HD_) + pp] = v;
    }
}

// ---------------- attention: 8-key ILP online softmax, fast exp ----------------
__global__ void attn_k(const float* __restrict__ q, const float* __restrict__ k,
                       const float* __restrict__ v, float* __restrict__ merged) {
    int wid_g = blockIdx.x * (blockDim.x >> 5) + (threadIdx.x >> 5);
    if (wid_g >= (SINK_ + WIN_) * NH_) return;
    int lane = threadIdx.x & 31;
    int ri = wid_g >> 4;
    int h  = wid_g & 15;
    int r  = (ri < SINK_) ? ri : (T_ - WIN_) + (ri - SINK_);
    int g  = h >> 2;
    const float4 q4 = *(const float4*)(q + (size_t)r * (NH_ * HD_) + h * HD_ + lane * 4);
    const float* kb = k + g * HD_ + lane * 4;
    const float* vb = v + g * HD_ + lane * 4;
    const float scale = 0.08838834764831845f;
    const float sink_bonus = 0.5f * (float)(T_ - SINK_ - WIN_) / (float)T_;
    float mmax = -1e30f, denom = 0.f;
    float4 acc = make_float4(0.f, 0.f, 0.f, 0.f);

    for (int seg = 0; seg < 2; seg++) {
        int cbeg = seg ? max(SINK_ + 1, r - WIN_) : 0;
        int cend = seg ? r : min(r, SINK_);
        int c = cbeg;
        // 8 keys: eight independent shfl chains share one latency window
        for (; c + 7 <= cend; c += 8) {
            float s[8];
#pragma unroll
            for (int j = 0; j < 8; j++) {
                float4 kk = *(const float4*)(kb + (size_t)(c + j) * (KVH_ * HD_));
                s[j] = q4.x * kk.x + q4.y * kk.y + q4.z * kk.z + q4.w * kk.w;
            }
#pragma unroll
            for (int o = 16; o; o >>= 1) {
#pragma unroll
                for (int j = 0; j < 8; j++)
                    s[j] += __shfl_xor_sync(0xFFFFFFFFu, s[j], o);
            }
#pragma unroll
            for (int j = 0; j < 8; j++)
                s[j] = s[j] * scale + ((c + j == SINK_) ? sink_bonus : 0.f);
            float m01 = fmaxf(s[0], s[1]), m23 = fmaxf(s[2], s[3]);
            float m45 = fmaxf(s[4], s[5]), m67 = fmaxf(s[6], s[7]);
            float mn = fmaxf(mmax, fmaxf(fmaxf(m01, m23), fmaxf(m45, m67)));
            float corr = __expf(mmax - mn);
            float p[8];
#pragma unroll
            for (int j = 0; j < 8; j++) p[j] = __expf(s[j] - mn);
            mmax = mn;
            denom = denom * corr +
                    (((p[0] + p[1]) + (p[2] + p[3])) + ((p[4] + p[5]) + (p[6] + p[7])));
            float4 vx[8];
#pragma unroll
            for (int j = 0; j < 8; j++)
                vx[j] = *(const float4*)(vb + (size_t)(c + j) * (KVH_ * HD_));
            float ax = 0.f, ay = 0.f, az = 0.f, aw = 0.f;
#pragma unroll
            for (int j = 0; j < 8; j++) {
                ax += p[j] * vx[j].x; ay += p[j] * vx[j].y;
                az += p[j] * vx[j].z; aw += p[j] * vx[j].w;
            }
            acc.x = acc.x * corr + ax;
            acc.y = acc.y * corr + ay;
            acc.z = acc.z * corr + az;
            acc.w = acc.w * corr + aw;
        }
        // remainder keys (up to 7)
        for (; c <= cend; c++) {
            const float4 k0 = *(const float4*)(kb + (size_t)c * (KVH_ * HD_));
            float s0 = q4.x * k0.x + q4.y * k0.y + q4.z * k0.z + q4.w * k0.w;
#pragma unroll
            for (int o = 16; o; o >>= 1) s0 += __shfl_xor_sync(0xFFFFFFFFu, s0, o);
            s0 = s0 * scale + ((c == SINK_) ? sink_bonus : 0.f);
            float mn = fmaxf(mmax, s0);
            float corr = __expf(mmax - mn);
            float p0 = __expf(s0 - mn);
            mmax = mn;
            denom = denom * corr + p0;
            const float4 v0 = *(const float4*)(vb + (size_t)c * (KVH_ * HD_));
            acc.x = acc.x * corr + p0 * v0.x;
            acc.y = acc.y * corr + p0 * v0.y;
            acc.z = acc.z * corr + p0 * v0.z;
            acc.w = acc.w * corr + p0 * v0.w;
        }
    }
    float inv = 1.f / denom;
    float4 o4;
    o4.x = rtf32(acc.x * inv); o4.y = rtf32(acc.y * inv);
    o4.z = rtf32(acc.z * inv); o4.w = rtf32(acc.w * inv);
    *(float4*)(merged + (size_t)r * INTER_ + h * HD_ + lane * 4) = o4;
}

// ---------------- elementwise (fast silu) ----------------
__global__ void swiglu_fused_k(const float* __restrict__ gu, float* __restrict__ o) {
    int i = blockIdx.x * blockDim.x + threadIdx.x;
    if (i >= T_ * MLPI_) return;
    int row = i / MLPI_, c = i % MLPI_;
    float x = gu[(size_t)row * (2 * MLPI_) + c];
    float u = gu[(size_t)row * (2 * MLPI_) + MLPI_ + c];
    o[i] = rtf32(fsilu(x) * u);
}

// ---------------- host ----------------
typedef CUresult (*PFN_encodeTiled)(CUtensorMap*, CUtensorMapDataType, cuuint32_t, void*,
                                    const cuuint64_t*, const cuuint64_t*, const cuuint32_t*,
                                    const cuuint32_t*, CUtensorMapInterleave, CUtensorMapSwizzle,
                                    CUtensorMapL2promotion, CUtensorMapFloatOOBfill);

static PFN_encodeTiled get_encoder() {
    void* p = nullptr;
    cudaDriverEntryPointQueryResult st;
    cudaGetDriverEntryPointByVersion("cuTensorMapEncodeTiled", &p, 12000, cudaEnableDefault, &st);
    return (PFN_encodeTiled)p;
}

static void make_tm(PFN_encodeTiled enc, CUtensorMap* tm, const float* base,
                    int rows, int cols, int box_rows) {
    cuuint64_t dims[2]    = {(cuuint64_t)cols, (cuuint64_t)rows};
    cuuint64_t strides[1] = {(cuuint64_t)cols * 4};
    cuuint32_t box[2]     = {32u, (cuuint32_t)box_rows};
    cuuint32_t es[2]      = {1u, 1u};
    enc(tm, CU_TENSOR_MAP_DATA_TYPE_FLOAT32, 2, (void*)base, dims, strides, box, es,
        CU_TENSOR_MAP_INTERLEAVE_NONE, CU_TENSOR_MAP_SWIZZLE_128B,
        CU_TENSOR_MAP_L2_PROMOTION_L2_128B, CU_TENSOR_MAP_FLOAT_OOB_FILL_NONE);
}

static PFN_encodeTiled g_enc = nullptr;

static void launch_gemm_tc(const float* A, const float* B,
                           const float* bias, const float* res, float* C,
                           int M, int N, int K, bool roundOut) {
    CUtensorMap tmA, tmB;
    make_tm(g_enc, &tmA, A, M, K, 128);
    make_tm(g_enc, &tmB, B, N, K, 256);
    dim3 grid((N + GBN - 1) / GBN, (M + GBM - 1) / GBM);
    if (roundOut) gemm_tc<true><<<grid, 128, GSMEM>>>(tmA, tmB, A, B, bias, res, C, M, N, K);
    else          gemm_tc<false><<<grid, 128, GSMEM>>>(tmA, tmB, A, B, bias, res, C, M, N, K);
}

static void roundw(const float* src, float* dst, int n) {
    int n4 = n / 4;
    roundw_k<<<(n4 + 255) / 256, 256>>>(src, dst, n4);
}

extern "C" void kernel_launch(void* const* d_in, const int* in_sizes, int n_in,
                              void* d_out, int out_size) {
    const float* hs      = (const float*)d_in[0];
    const float* cosb    = (const float*)d_in[1];
    const float* sinb    = (const float*)d_in[2];
    const float* ln1_w   = (const float*)d_in[3];
    const float* q_w     = (const float*)d_in[4];
    const float* q_b     = (const float*)d_in[5];
    const float* k_w     = (const float*)d_in[6];
    const float* k_b     = (const float*)d_in[7];
    const float* v_w     = (const float*)d_in[8];
    const float* v_b     = (const float*)d_in[9];
    const float* o_w     = (const float*)d_in[10];
    const float* inpj_w  = (const float*)d_in[11];
    const float* conv_w  = (const float*)d_in[12];
    const float* conv_b  = (const float*)d_in[13];
    const float* dt_bias = (const float*)d_in[14];
    const float* A_log   = (const float*)d_in[15];
    const float* Dp      = (const float*)d_in[16];
    const float* mnorm_w = (const float*)d_in[17];
    const float* outp_w  = (const float*)d_in[18];
    const float* ln2_w   = (const float*)d_in[19];
    const float* gate_w  = (const float*)d_in[20];
    const float* up_w    = (const float*)d_in[21];
    const float* down_w  = (const float*)d_in[22];
    float* out = (float*)d_out;

    float *pre, *proj, *xbc, *dtb, *ybuf, *gbuf, *qb, *kb, *vb, *merged, *hb, *mb, *gub, *gateb;
    float *wq, *wk, *wv, *wo, *win, *wout, *wgu, *wd;
    cudaGetSymbolAddress((void**)&pre,    g_pre);
    cudaGetSymbolAddress((void**)&proj,   g_proj);
    cudaGetSymbolAddress((void**)&xbc,    g_xbc);
    cudaGetSymbolAddress((void**)&dtb,    g_dt);
    cudaGetSymbolAddress((void**)&ybuf,   g_y);
    cudaGetSymbolAddress((void**)&gbuf,   g_g);
    cudaGetSymbolAddress((void**)&qb,     g_q);
    cudaGetSymbolAddress((void**)&kb,     g_k);
    cudaGetSymbolAddress((void**)&vb,     g_v);
    cudaGetSymbolAddress((void**)&merged, g_merged);
    cudaGetSymbolAddress((void**)&hb,     g_h);
    cudaGetSymbolAddress((void**)&mb,     g_m);
    cudaGetSymbolAddress((void**)&gub,    g_gu);
    cudaGetSymbolAddress((void**)&gateb,  g_gate);
    cudaGetSymbolAddress((void**)&wq,     g_wq);
    cudaGetSymbolAddress((void**)&wk,     g_wk);
    cudaGetSymbolAddress((void**)&wv,     g_wv);
    cudaGetSymbolAddress((void**)&wo,     g_wo);
    cudaGetSymbolAddress((void**)&win,    g_win);
    cudaGetSymbolAddress((void**)&wout,   g_wout);
    cudaGetSymbolAddress((void**)&wgu,    g_wgu);
    cudaGetSymbolAddress((void**)&wd,     g_wd);

    if (!g_enc) g_enc = get_encoder();
    static bool attrs_set = false;
    if (!attrs_set) {
        cudaFuncSetAttribute(gemm_tc<false>, cudaFuncAttributeMaxDynamicSharedMemorySize, GSMEM);
        cudaFuncSetAttribute(gemm_tc<true>,  cudaFuncAttributeMaxDynamicSharedMemorySize, GSMEM);
        attrs_set = true;
    }

    // 0. round weights to tf32 (unbiased rna); gate|up concatenated
    roundw(q_w,    wq,   NH_ * HD_ * H_);
    roundw(k_w,    wk,   KVH_ * HD_ * H_);
    roundw(v_w,    wv,   KVH_ * HD_ * H_);
    roundw(o_w,    wo,   H_ * NH_ * HD_);
    roundw(inpj_w, win,  NPROJ_ * H_);
    roundw(outp_w, wout, H_ * INTER_);
    roundw(gate_w, wgu,                       MLPI_ * H_);
    roundw(up_w,   wgu + (size_t)MLPI_ * H_,  MLPI_ * H_);
    roundw(down_w, wd,   H_ * MLPI_);

    // 1. pre-norm (tf32-rounded: feeds GEMMs only)
    rmsnorm_k<<<T_, 256>>>(hs, ln1_w, pre, H_, EPS_, 1);

    // 2. mamba branch on pre rows [64, 1536)
    launch_gemm_tc(pre + (size_t)SINK_ * H_, win, nullptr, nullptr, proj, LMEM_, NPROJ_, H_, false);
    conv_silu_k<<<(LMEM_ * CONVD_ + 255) / 256, 256>>>(proj, conv_w, conv_b, xbc);
    dt_k<<<(LMEM_ * NH_ + 255) / 256, 256>>>(proj, dt_bias, dtb);
    scan_k<<<NH_, 128>>>(xbc, dtb, A_log, Dp, ybuf);
    gatenorm_k<<<LMEM_, 256>>>(ybuf, proj, mnorm_w, gbuf);
    launch_gemm_tc(gbuf, wout, nullptr, nullptr, merged + (size_t)SINK_ * INTER_, LMEM_, INTER_, H_, true);

    // 3. q projection on consumed rows only; full k/v
    launch_gemm_tc(pre, wq, q_b, nullptr, qb, SINK_, NH_ * HD_, H_, false);
    launch_gemm_tc(pre + (size_t)(T_ - WIN_) * H_, wq, q_b, nullptr,
                   qb + (size_t)(T_ - WIN_) * (NH_ * HD_), WIN_, NH_ * HD_, H_, false);
    launch_gemm_tc(pre, wk, k_b, nullptr, kb, T_, KVH_ * HD_, H_, false);
    launch_gemm_tc(pre, wv, v_b, nullptr, vb, T_, KVH_ * HD_, H_, false);

    // 4. RoPE
    rope_q_k<<<dim3(4, SINK_ + WIN_), 256>>>(qb, cosb, sinb);
    rope_k_k<<<dim3(1, T_), 256>>>(kb, cosb, sinb);

    // 5. replace k/v at row SINK with mem_act projection (exact fp32 GEMV)
    memact_kv_k<<<2 * KVH_ * HD_, 256>>>(merged, k_w, k_b, v_w, v_b, kb, vb);

    // 6. attention -> merged rows [0,64) and [1536,2048)
    attn_k<<<((SINK_ + WIN_) * NH_ + 7) / 8, 256>>>(qb, kb, vb, merged);

    // 7. o projection + FUSED residual -> hb
    launch_gemm_tc(merged, wo, nullptr, hs, hb, T_, H_, NH_ * HD_, false);

    // 8. MLP (gate+up fused); down-proj + FUSED residual -> out
    rmsnorm_k<<<T_, 256>>>(hb, ln2_w, mb, H_, EPS_, 1);
    launch_gemm_tc(mb, wgu, nullptr, nullptr, gub, T_, 2 * MLPI_, H_, false);
    swiglu_fused_k<<<(T_ * MLPI_ + 255) / 256, 256>>>(gub, gateb);
    launch_gemm_tc(gateb, wd, nullptr, hb, out, T_, H_, MLPI_, false);
}

// round 17
// speedup vs baseline: 1.1736x; 1.0249x over previous
#include <cuda_runtime.h>
#include <cuda.h>
#include <cuda_bf16.h>
#include <math.h>
#include <stdint.h>

// ---------------- constants ----------------
#define T_      2048
#define H_      2048
#define NH_     16
#define KVH_    4
#define HD_     128
#define WIN_    512
#define SINK_   64
#define S_      64
#define NG_     4
#define MLPI_   5504
#define CK_     4
#define INTER_  2048
#define CONVD_  2560
#define NPROJ_  4624
#define LMEM_   1472
#define EPS_    1e-6f
#define MEPS_   1e-5f

// ---------------- scratch ----------------
__device__ float g_pre   [T_ * H_];
__device__ float g_proj  [LMEM_ * NPROJ_];
__device__ float g_xbc   [LMEM_ * CONVD_];
__device__ float g_dt    [LMEM_ * NH_];
__device__ float g_y     [LMEM_ * INTER_];
__device__ float g_g     [LMEM_ * INTER_];
__device__ float g_q     [T_ * (NH_ * HD_)];
__device__ float g_k     [T_ * (KVH_ * HD_)];
__device__ float g_v     [T_ * (KVH_ * HD_)];
__device__ float g_merged[T_ * INTER_];
__device__ float g_h     [T_ * H_];
__device__ float g_m     [T_ * H_];
__device__ float g_gu    [T_ * 2 * MLPI_];
__device__ float g_gate  [T_ * MLPI_];
// tf32-rounded weight copies
__device__ float g_wq  [(NH_*HD_) * H_];
__device__ float g_wk  [(KVH_*HD_) * H_];
__device__ float g_wv  [(KVH_*HD_) * H_];
__device__ float g_wo  [H_ * (NH_*HD_)];
__device__ float g_win [NPROJ_ * H_];
__device__ float g_wout[H_ * INTER_];
__device__ float g_wgu [2 * MLPI_ * H_];
__device__ float g_wd  [H_ * MLPI_];

// ---------------- ptx helpers (baseline-safe) ----------------
__device__ __forceinline__ uint32_t smem_u32(const void* p) {
    uint32_t a;
    asm("{ .reg .u64 t; cvta.to.shared.u64 t, %1; cvt.u32.u64 %0, t; }" : "=r"(a) : "l"(p));
    return a;
}
__device__ __forceinline__ float rtf32(float x) {
    float y; asm("cvt.rna.tf32.f32 %0, %1;" : "=f"(y) : "f"(x)); return y;
}
// fast silu: x / (1 + e^-x) with MUFU exp + fast division
__device__ __forceinline__ float fsilu(float x) {
    return __fdividef(x, 1.f + __expf(-x));
}

#define MBARRIER_INIT(addr, cnt) \
    asm volatile("mbarrier.init.shared.b64 [%0], %1;" :: "r"((uint32_t)(addr)), "r"((uint32_t)(cnt)) : "memory")
#define MBARRIER_EXPECT_TX(addr, bytes) \
    asm volatile("mbarrier.arrive.expect_tx.shared.b64 _, [%0], %1;" :: "r"((uint32_t)(addr)), "r"((uint32_t)(bytes)) : "memory")
#define MBARRIER_WAIT_PARITY(addr, ph) do { \
    uint32_t _m = (uint32_t)(addr); uint32_t _p = (uint32_t)(ph); uint32_t _d; \
    asm volatile("{\n\t.reg .pred p;\n\t" \
        "mbarrier.try_wait.parity.acquire.cta.shared::cta.b64 p, [%1], %2;\n\t" \
        "selp.b32 %0, 1, 0, p;\n\t}" : "=r"(_d) : "r"(_m), "r"(_p) : "memory"); \
    if (!_d) { asm volatile("{\n\t.reg .pred P1;\n\t" \
        "WL_%=:\n\t" \
        "mbarrier.try_wait.parity.acquire.cta.shared::cta.b64 P1, [%0], %1, 0x989680;\n\t" \
        "@P1 bra.uni WD_%=;\n\tbra.uni WL_%=;\n\tWD_%=:\n\t}" \
        :: "r"(_m), "r"(_p) : "memory"); } \
} while (0)

__device__ __forceinline__ void tma2d(uint32_t smem, const void* tm, int x, int y, uint32_t mbar) {
    asm volatile("cp.async.bulk.tensor.2d.shared::cta.global.tile.mbarrier::complete_tx::bytes "
                 "[%0], [%1, {%2, %3}], [%4];"
                 :: "r"(smem), "l"(tm), "r"(x), "r"(y), "r"(mbar) : "memory");
}

// ---------------- tcgen05 (arch-specific: sm_103a pass only) ----------------
#if defined(__CUDA_ARCH_FEAT_SM103_ALL)
#define HAS_TCGEN05 1

#define TCGEN05_ALLOC(smem_addr, nCols) \
    asm volatile("tcgen05.alloc.cta_group::1.sync.aligned.shared::cta.b32 [%0], %1;" \
        :: "r"((uint32_t)(smem_addr)), "r"((uint32_t)(nCols)) : "memory")
#define TCGEN05_DEALLOC(tmem, nCols) \
    asm volatile("tcgen05.dealloc.cta_group::1.sync.aligned.b32 %0, %1;" :: "r"(tmem), "r"((uint32_t)(nCols)))
#define TCGEN05_COMMIT(mbar) \
    asm volatile("tcgen05.commit.cta_group::1.mbarrier::arrive::one.shared::cluster.b64 [%0];" \
        :: "r"((uint32_t)(mbar)) : "memory")
#define TCGEN05_FENCE_AFTER() asm volatile("tcgen05.fence::after_thread_sync;" ::: "memory")
#define TCGEN05_WAIT_LD() asm volatile("tcgen05.wait::ld.sync.aligned;" ::: "memory")

#define TCGEN05_LD_32X32B_X32(r, tmem_addr) \
    asm volatile("tcgen05.ld.sync.aligned.32x32b.x32.b32 " \
        "{%0, %1, %2, %3, %4, %5, %6, %7, %8, %9, %10, %11, %12, %13, %14, %15, " \
        " %16, %17, %18, %19, %20, %21, %22, %23, %24, %25, %26, %27, %28, %29, %30, %31}, [%32];" \
        : "=r"((r)[0]),  "=r"((r)[1]),  "=r"((r)[2]),  "=r"((r)[3]), \
          "=r"((r)[4]),  "=r"((r)[5]),  "=r"((r)[6]),  "=r"((r)[7]), \
          "=r"((r)[8]),  "=r"((r)[9]),  "=r"((r)[10]), "=r"((r)[11]), \
          "=r"((r)[12]), "=r"((r)[13]), "=r"((r)[14]), "=r"((r)[15]), \
          "=r"((r)[16]), "=r"((r)[17]), "=r"((r)[18]), "=r"((r)[19]), \
          "=r"((r)[20]), "=r"((r)[21]), "=r"((r)[22]), "=r"((r)[23]), \
          "=r"((r)[24]), "=r"((r)[25]), "=r"((r)[26]), "=r"((r)[27]), \
          "=r"((r)[28]), "=r"((r)[29]), "=r"((r)[30]), "=r"((r)[31]) \
        : "r"(tmem_addr))

__device__ __forceinline__ void mma_tf32_ss(uint32_t d, uint64_t ad, uint64_t bd,
                                            uint32_t idesc, uint32_t en) {
    asm volatile("{\n\t.reg .pred p;\n\tsetp.ne.u32 p, %4, 0;\n\t"
                 "tcgen05.mma.cta_group::1.kind::tf32 [%0], %1, %2, %3, {%5, %5, %5, %5}, p;\n\t}"
                 :: "r"(d), "l"(ad), "l"(bd), "r"(idesc), "r"(en), "r"(0u) : "memory");
}
#endif

// SW128 K-major SMEM descriptor (LBO=1, SBO=64, version=1)
static constexpr uint64_t SMEM_DESC_BASE_SW128 =
    (uint64_t(2) << 61) | (uint64_t(1) << 46) | (uint64_t(64) << 32) | (uint64_t(1) << 16);
#define MAKE_SMEM_DESC(base_addr) (SMEM_DESC_BASE_SW128 | ((uint64_t)((base_addr) >> 4) & 0x3FFF))

// ---------------- tcgen05 tf32 GEMM: C[M,N] = A[M,K] * B[N,K]^T (+bias) (+res) ----------------
#define GBM 128
#define GBN 256
#define GBK 32
#define GDEPTH 4
#define SM_A_OFF 1024
#define SM_B_OFF (1024 + GDEPTH * 16384)
#define GSMEM (1024 + GDEPTH * 16384 + GDEPTH * 32768)

template<bool ROUND>
__global__ void __launch_bounds__(128, 1)
gemm_tc(const __grid_constant__ CUtensorMap tmA,
        const __grid_constant__ CUtensorMap tmB,
        const float* __restrict__ Araw, const float* __restrict__ Braw,
        const float* __restrict__ bias, const float* __restrict__ res,
        float* __restrict__ C, int M, int N, int K) {
#if defined(HAS_TCGEN05)
    extern __shared__ __align__(1024) char smem[];
    uint32_t sb = smem_u32(smem);
    int tid = threadIdx.x, wid = tid >> 5, lane = tid & 31;
    int m0 = blockIdx.y * GBM, n0 = blockIdx.x * GBN;

    if (wid == 0) TCGEN05_ALLOC(sb + 0, 256);
    if (tid == 0) {
        for (int s = 0; s < GDEPTH; s++) {
            MBARRIER_INIT(sb + 8 + s * 16, 1);       // full
            MBARRIER_INIT(sb + 8 + s * 16 + 8, 1);   // empty
        }
    }
    __syncthreads();
    uint32_t tmem;
    asm volatile("ld.shared.b32 %0, [%1];" : "=r"(tmem) : "r"(sb + 0));

    int nst = K / GBK;
    if (tid == 0) {
        int pre = nst < GDEPTH ? nst : GDEPTH;
        for (int s = 0; s < pre; s++) {
            uint32_t full = sb + 8 + s * 16;
            MBARRIER_EXPECT_TX(full, 49152);
            tma2d(sb + SM_A_OFF + s * 16384, &tmA, s * GBK, m0, full);
            tma2d(sb + SM_B_OFF + s * 32768, &tmB, s * GBK, n0, full);
        }
        const uint32_t idesc = (1u << 4) | (2u << 7) | (2u << 10) |
                               ((GBN / 8) << 17) | ((GBM / 16) << 24);
        for (int s = 0; s < nst; s++) {
            int slot = s & (GDEPTH - 1);
            int ph = (s / GDEPTH) & 1;
            uint32_t full = sb + 8 + slot * 16;
            uint32_t empty = full + 8;
            MBARRIER_WAIT_PARITY(full, ph);
            uint64_t ad = MAKE_SMEM_DESC(sb + SM_A_OFF + slot * 16384);
            uint64_t bd = MAKE_SMEM_DESC(sb + SM_B_OFF + slot * 32768);
#pragma unroll
            for (int kk = 0; kk < 4; kk++)
                mma_tf32_ss(tmem, ad + kk * 2, bd + kk * 2, idesc,
                            (s > 0 || kk > 0) ? 1u : 0u);
            TCGEN05_COMMIT(empty);
            if (s > 0) {
                int rs = s - 1 + GDEPTH;
                if (rs < nst) {
                    int rslot = (s - 1) & (GDEPTH - 1);
                    int rph = ((s - 1) / GDEPTH) & 1;
                    uint32_t rfull = sb + 8 + rslot * 16;
                    MBARRIER_WAIT_PARITY(rfull + 8, rph);
                    MBARRIER_EXPECT_TX(rfull, 49152);
                    tma2d(sb + SM_A_OFF + rslot * 16384, &tmA, rs * GBK, m0, rfull);
                    tma2d(sb + SM_B_OFF + rslot * 32768, &tmB, rs * GBK, n0, rfull);
                }
            }
        }
        int ls = nst - 1;
        MBARRIER_WAIT_PARITY(sb + 8 + (ls & (GDEPTH - 1)) * 16 + 8, (ls / GDEPTH) & 1);
    }
    __syncthreads();
    TCGEN05_FENCE_AFTER();

    int m = m0 + wid * 32 + lane;
    bool mok = (m < M);
#pragma unroll 1
    for (int b = 0; b < 8; b++) {
        uint32_t r[32];
        TCGEN05_LD_32X32B_X32(r, tmem + b * 32);
        TCGEN05_WAIT_LD();
        if (mok) {
            float* crow = C + (size_t)m * N;
#pragma unroll
            for (int j4 = 0; j4 < 8; j4++) {
                int c = n0 + b * 32 + j4 * 4;
                if (c < N) {
                    float4 v;
                    v.x = __uint_as_float(r[j4 * 4 + 0]);
                    v.y = __uint_as_float(r[j4 * 4 + 1]);
                    v.z = __uint_as_float(r[j4 * 4 + 2]);
                    v.w = __uint_as_float(r[j4 * 4 + 3]);
                    if (bias) {
                        float4 bb = *(const float4*)(bias + c);
                        v.x += bb.x; v.y += bb.y; v.z += bb.z; v.w += bb.w;
                    }
                    if (res) {
                        float4 rr = *(const float4*)(res + (size_t)m * N + c);
                        v.x += rr.x; v.y += rr.y; v.z += rr.z; v.w += rr.w;
                    }
                    if (ROUND) {
                        v.x = rtf32(v.x); v.y = rtf32(v.y);
                        v.z = rtf32(v.z); v.w = rtf32(v.w);
                    }
                    *(float4*)(crow + c) = v;
                }
            }
        }
    }
    __syncthreads();
    if (wid == 0) TCGEN05_DEALLOC(tmem, 256);
#else
    // Fallback for the generic compute_103 PTX pass (never run on GB300).
    int m0 = blockIdx.y * GBM, n0 = blockIdx.x * GBN;
    for (int idx = threadIdx.x; idx < GBM * GBN; idx += blockDim.x) {
        int mi = idx / GBN, ni = idx % GBN;
        int m = m0 + mi, n = n0 + ni;
        if (m < M && n < N) {
            const float* a = Araw + (size_t)m * K;
            const float* b = Braw + (size_t)n * K;
            float acc = 0.f;
            for (int k = 0; k < K; k++) acc += a[k] * b[k];
            if (bias) acc += bias[n];
            if (res) acc += res[(size_t)m * N + n];
            if (ROUND) acc = rtf32(acc);
            C[(size_t)m * N + n] = acc;
        }
    }
#endif
}

// ---------------- weight rounding ----------------
__global__ void roundw_k(const float* __restrict__ src, float* __restrict__ dst, int n4) {
    int i = blockIdx.x * blockDim.x + threadIdx.x;
    if (i < n4) {
        float4 v = ((const float4*)src)[i];
        v.x = rtf32(v.x); v.y = rtf32(v.y); v.z = rtf32(v.z); v.w = rtf32(v.w);
        ((float4*)dst)[i] = v;
    }
}

// ---------------- rmsnorm ----------------
__global__ void rmsnorm_k(const float* __restrict__ x, const float* __restrict__ w,
                          float* __restrict__ out, int cols, float eps, int do_round) {
    int row = blockIdx.x;
    const float* xr = x + (size_t)row * cols;
    float ss = 0.f;
    for (int i = threadIdx.x; i < cols; i += blockDim.x) { float v = xr[i]; ss += v * v; }
    __shared__ float sh[32];
#pragma unroll
    for (int o = 16; o; o >>= 1) ss += __shfl_xor_sync(0xFFFFFFFFu, ss, o);
    if ((threadIdx.x & 31) == 0) sh[threadIdx.x >> 5] = ss;
    __syncthreads();
    if (threadIdx.x < 32) {
        float v = (threadIdx.x < (blockDim.x >> 5)) ? sh[threadIdx.x] : 0.f;
#pragma unroll
        for (int o = 16; o; o >>= 1) v += __shfl_xor_sync(0xFFFFFFFFu, v, o);
        if (threadIdx.x == 0) sh[0] = v;
    }
    __syncthreads();
    float scale = rsqrtf(sh[0] / (float)cols + eps);
    for (int i = threadIdx.x; i < cols; i += blockDim.x) {
        float v = xr[i] * scale * w[i];
        out[(size_t)row * cols + i] = do_round ? rtf32(v) : v;
    }
}

// ---------------- conv + silu (fast silu) ----------------
__global__ void conv_silu_k(const float* __restrict__ proj, const float* __restrict__ cw,
                            const float* __restrict__ cb, float* __restrict__ xbc) {
    int idx = blockIdx.x * blockDim.x + threadIdx.x;
    if (idx >= LMEM_ * CONVD_) return;
    int l = idx / CONVD_, c = idx % CONVD_;
    float acc = cb[c];
#pragma unroll
    for (int j = 0; j < CK_; j++) {
        int t = l + j - (CK_ - 1);
        if (t >= 0) acc += cw[c * CK_ + j] * proj[(size_t)t * NPROJ_ + INTER_ + c];
    }
    xbc[idx] = fsilu(acc);
}

__global__ void dt_k(const float* __restrict__ proj, const float* __restrict__ dtb,
                     float* __restrict__ dt) {
    int idx = blockIdx.x * blockDim.x + threadIdx.x;
    if (idx >= LMEM_ * NH_) return;
    int l = idx / NH_, h = idx % NH_;
    float x = proj[(size_t)l * NPROJ_ + (INTER_ + CONVD_) + h] + dtb[h];
    dt[idx] = (x > 20.f) ? x : log1pf(expf(x));
}

// ---------------- mamba2 scan: packed f32x2 FFMA2 inner loop (sm_103a) ----------------
__global__ void scan_k(const float* __restrict__ xbc, const float* __restrict__ dt,
                       const float* __restrict__ A_log, const float* __restrict__ Dp,
                       float* __restrict__ y) {
    int h = blockIdx.x;
    int tid = threadIdx.x;
    int g = h >> 2;
    float A  = -expf(A_log[h]);
    float Dh = Dp[h];
    __shared__ __align__(16) float Bs[2][S_], Cs[2][S_];

    float xv  = xbc[(size_t)0 * CONVD_ + h * HD_ + tid];
    float bv  = (tid < S_) ? xbc[INTER_ + g * S_ + tid]
                           : xbc[INTER_ + NG_ * S_ + g * S_ + (tid - S_)];
    float dtl = dt[h];

#if defined(HAS_TCGEN05)
    // state packed as 32 f32x2 registers; FFMA2 halves per-step instruction count
    unsigned long long st2[S_ / 2];
#pragma unroll
    for (int s = 0; s < S_ / 2; s++) st2[s] = 0ull;

    for (int l = 0; l < LMEM_; l++) {
        int buf = l & 1;
        if (tid < S_) Bs[buf][tid] = bv; else Cs[buf][tid - S_] = bv;
        __syncthreads();
        float xn = 0.f, bn = 0.f, dtn = 0.f;
        if (l + 1 < LMEM_) {
            const float* nx = xbc + (size_t)(l + 1) * CONVD_;
            xn  = nx[h * HD_ + tid];
            bn  = (tid < S_) ? nx[INTER_ + g * S_ + tid]
                             : nx[INTER_ + NG_ * S_ + g * S_ + (tid - S_)];
            dtn = dt[(size_t)(l + 1) * NH_ + h];
        }
        float decay = expf(dtl * A);
        float dtx   = dtl * xv;
        unsigned long long d2, x2, y2 = 0ull;
        {
            uint32_t du = __float_as_uint(decay), xu = __float_as_uint(dtx);
            asm("mov.b64 %0, {%1, %1};" : "=l"(d2) : "r"(du));
            asm("mov.b64 %0, {%1, %1};" : "=l"(x2) : "r"(xu));
        }
        const unsigned long long* B2 = (const unsigned long long*)&Bs[buf][0];
        const unsigned long long* C2 = (const unsigned long long*)&Cs[buf][0];
#pragma unroll
        for (int s = 0; s < S_ / 2; s++) {
            unsigned long long b2 = B2[s];
            unsigned long long c2 = C2[s];
            unsigned long long t2;
            asm("mul.rn.f32x2 %0, %1, %2;" : "=l"(t2) : "l"(x2), "l"(b2));
            asm("fma.rn.f32x2 %0, %1, %2, %3;" : "=l"(st2[s]) : "l"(d2), "l"(st2[s]), "l"(t2));
            asm("fma.rn.f32x2 %0, %1, %2, %3;" : "=l"(y2) : "l"(st2[s]), "l"(c2), "l"(y2));
        }
        uint32_t ylo, yhi;
        asm("mov.b64 {%0, %1}, %2;" : "=r"(ylo), "=r"(yhi) : "l"(y2));
        float yv = __uint_as_float(ylo) + __uint_as_float(yhi) + Dh * xv;
        y[(size_t)l * INTER_ + h * HD_ + tid] = yv;
        xv = xn; bv = bn; dtl = dtn;
    }
#else
    // scalar fallback for the generic compute_103 pass (never run on GB300)
    float st[S_];
#pragma unroll
    for (int s = 0; s < S_; s++) st[s] = 0.f;
    for (int l = 0; l < LMEM_; l++) {
        int buf = l & 1;
        if (tid < S_) Bs[buf][tid] = bv; else Cs[buf][tid - S_] = bv;
        __syncthreads();
        float xn = 0.f, bn = 0.f, dtn = 0.f;
        if (l + 1 < LMEM_) {
            const float* nx = xbc + (size_t)(l + 1) * CONVD_;
            xn  = nx[h * HD_ + tid];
            bn  = (tid < S_) ? nx[INTER_ + g * S_ + tid]
                             : nx[INTER_ + NG_ * S_ + g * S_ + (tid - S_)];
            dtn = dt[(size_t)(l + 1) * NH_ + h];
        }
        float decay = expf(dtl * A);
        float dtx   = dtl * xv;
        float yv = 0.f;
#pragma unroll
        for (int s = 0; s < S_; s++) {
            st[s] = decay * st[s] + dtx * Bs[buf][s];
            yv += st[s] * Cs[buf][s];
        }
        yv += Dh * xv;
        y[(size_t)l * INTER_ + h * HD_ + tid] = yv;
        xv = xn; bv = bn; dtl = dtn;
    }
#endif
}

// ---------------- gated rmsnorm (fast silu) ----------------
__global__ void gatenorm_k(const float* __restrict__ y, const float* __restrict__ proj,
                           const float* __restrict__ mw, float* __restrict__ out) {
    int row = blockIdx.x;
    __shared__ float gsh[INTER_];
    __shared__ float sh[32];
    float ss = 0.f;
    for (int i = threadIdx.x; i < INTER_; i += blockDim.x) {
        float z  = proj[(size_t)row * NPROJ_ + i];
        float gv = y[(size_t)row * INTER_ + i] * fsilu(z);
        gsh[i] = gv;
        ss += gv * gv;
    }
#pragma unroll
    for (int o = 16; o; o >>= 1) ss += __shfl_xor_sync(0xFFFFFFFFu, ss, o);
    if ((threadIdx.x & 31) == 0) sh[threadIdx.x >> 5] = ss;
    __syncthreads();
    if (threadIdx.x < 32) {
        float v = (threadIdx.x < (blockDim.x >> 5)) ? sh[threadIdx.x] : 0.f;
#pragma unroll
        for (int o = 16; o; o >>= 1) v += __shfl_xor_sync(0xFFFFFFFFu, v, o);
        if (threadIdx.x == 0) sh[0] = v;
    }
    __syncthreads();
    float scale = rsqrtf(sh[0] / (float)INTER_ + MEPS_);
    for (int i = threadIdx.x; i < INTER_; i += blockDim.x)
        out[(size_t)row * INTER_ + i] = rtf32(gsh[i] * scale * mw[i]);
}

// ---------------- RoPE ----------------
__global__ void rope_q_k(float* __restrict__ q, const float* __restrict__ cosb,
                         const float* __restrict__ sinb) {
    int ri = blockIdx.y;
    int r = (ri < SINK_) ? ri : (T_ - WIN_) + (ri - SINK_);
    int i = blockIdx.x * blockDim.x + threadIdx.x;
    if (i >= NH_ * (HD_ / 2)) return;
    int hh = i >> 6, d = i & 63;
    float* qr = q + (size_t)r * (NH_ * HD_) + hh * HD_;
    float c0 = cosb[r * HD_ + d],      s0 = sinb[r * HD_ + d];
    float c1 = cosb[r * HD_ + d + 64], s1 = sinb[r * HD_ + d + 64];
    float a = qr[d], b = qr[d + 64];
    qr[d]      = a * c0 - b * s0;
    qr[d + 64] = b * c1 + a * s1;
}

__global__ void rope_k_k(float* __restrict__ k, const float* __restrict__ cosb,
                         const float* __restrict__ sinb) {
    int r = blockIdx.y;
    int i = threadIdx.x;
    if (i >= KVH_ * (HD_ / 2)) return;
    int hh = i >> 6, d = i & 63;
    float* kr = k + (size_t)r * (KVH_ * HD_) + hh * HD_;
    float c0 = cosb[r * HD_ + d],      s0 = sinb[r * HD_ + d];
    float c1 = cosb[r * HD_ + d + 64], s1 = sinb[r * HD_ + d + 64];
    float a = kr[d], b = kr[d + 64];
    kr[d]      = a * c0 - b * s0;
    kr[d + 64] = b * c1 + a * s1;
}

// ---------------- k/v row SINK replacement ----------------
__global__ void memact_kv_k(const float* __restrict__ merged,
                            const float* __restrict__ kw, const float* __restrict__ kb,
                            const float* __restrict__ vw, const float* __restrict__ vb,
                            float* __restrict__ kbuf, float* __restrict__ vbuf) {
    int p = blockIdx.x;
    const float* act = merged + (size_t)(SINK_ + LMEM_ - 1) * INTER_;
    int pp = (p < KVH_ * HD_) ? p : p - KVH_ * HD_;
    const float* W = (p < KVH_ * HD_) ? kw : vw;
    float bs       = (p < KVH_ * HD_) ? kb[pp] : vb[pp];
    float ss = 0.f;
    for (int i = threadIdx.x; i < H_; i += blockDim.x) ss += act[i] * W[(size_t)pp * H_ + i];
    __shared__ float sh[32];
#pragma unroll
    for (int o = 16; o; o >>= 1) ss += __shfl_xor_sync(0xFFFFFFFFu, ss, o);
    if ((threadIdx.x & 31) == 0) sh[threadIdx.x >> 5] = ss;
    __syncthreads();
    if (threadIdx.x == 0) {
        float v = 0.f;
        for (int w = 0; w < (int)(blockDim.x >> 5); w++) v += sh[w];
        v += bs;
        if (p < KVH_ * HD_) kbuf[(size_t)SINK_ * (KVH_ * HD_) + pp] = v;
        else                vbuf[(size_t)SINK_ * (KVH_ * HD_) + pp] = v;
    }
}

// ---------------- attention: 8-key ILP online softmax, fast exp ----------------
__global__ void attn_k(const float* __restrict__ q, const float* __restrict__ k,
                       const float* __restrict__ v, float* __restrict__ merged) {
    int wid_g = blockIdx.x * (blockDim.x >> 5) + (threadIdx.x >> 5);
    if (wid_g >= (SINK_ + WIN_) * NH_) return;
    int lane = threadIdx.x & 31;
    int ri = wid_g >> 4;
    int h  = wid_g & 15;
    int r  = (ri < SINK_) ? ri : (T_ - WIN_) + (ri - SINK_);
    int g  = h >> 2;
    const float4 q4 = *(const float4*)(q + (size_t)r * (NH_ * HD_) + h * HD_ + lane * 4);
    const float* kb = k + g * HD_ + lane * 4;
    const float* vb = v + g * HD_ + lane * 4;
    const float scale = 0.08838834764831845f;
    const float sink_bonus = 0.5f * (float)(T_ - SINK_ - WIN_) / (float)T_;
    float mmax = -1e30f, denom = 0.f;
    float4 acc = make_float4(0.f, 0.f, 0.f, 0.f);

    for (int seg = 0; seg < 2; seg++) {
        int cbeg = seg ? max(SINK_ + 1, r - WIN_) : 0;
        int cend = seg ? r : min(r, SINK_);
        int c = cbeg;
        for (; c + 7 <= cend; c += 8) {
            float s[8];
#pragma unroll
            for (int j = 0; j < 8; j++) {
                float4 kk = *(const float4*)(kb + (size_t)(c + j) * (KVH_ * HD_));
                s[j] = q4.x * kk.x + q4.y * kk.y + q4.z * kk.z + q4.w * kk.w;
            }
#pragma unroll
            for (int o = 16; o; o >>= 1) {
#pragma unroll
                for (int j = 0; j < 8; j++)
                    s[j] += __shfl_xor_sync(0xFFFFFFFFu, s[j], o);
            }
#pragma unroll
            for (int j = 0; j < 8; j++)
                s[j] = s[j] * scale + ((c + j == SINK_) ? sink_bonus : 0.f);
            float m01 = fmaxf(s[0], s[1]), m23 = fmaxf(s[2], s[3]);
            float m45 = fmaxf(s[4], s[5]), m67 = fmaxf(s[6], s[7]);
            float mn = fmaxf(mmax, fmaxf(fmaxf(m01, m23), fmaxf(m45, m67)));
            float corr = __expf(mmax - mn);
            float p[8];
#pragma unroll
            for (int j = 0; j < 8; j++) p[j] = __expf(s[j] - mn);
            mmax = mn;
            denom = denom * corr +
                    (((p[0] + p[1]) + (p[2] + p[3])) + ((p[4] + p[5]) + (p[6] + p[7])));
            float4 vx[8];
#pragma unroll
            for (int j = 0; j < 8; j++)
                vx[j] = *(const float4*)(vb + (size_t)(c + j) * (KVH_ * HD_));
            float ax = 0.f, ay = 0.f, az = 0.f, aw = 0.f;
#pragma unroll
            for (int j = 0; j < 8; j++) {
                ax += p[j] * vx[j].x; ay += p[j] * vx[j].y;
                az += p[j] * vx[j].z; aw += p[j] * vx[j].w;
            }
            acc.x = acc.x * corr + ax;
            acc.y = acc.y * corr + ay;
            acc.z = acc.z * corr + az;
            acc.w = acc.w * corr + aw;
        }
        for (; c <= cend; c++) {
            const float4 k0 = *(const float4*)(kb + (size_t)c * (KVH_ * HD_));
            float s0 = q4.x * k0.x + q4.y * k0.y + q4.z * k0.z + q4.w * k0.w;
#pragma unroll
            for (int o = 16; o; o >>= 1) s0 += __shfl_xor_sync(0xFFFFFFFFu, s0, o);
            s0 = s0 * scale + ((c == SINK_) ? sink_bonus : 0.f);
            float mn = fmaxf(mmax, s0);
            float corr = __expf(mmax - mn);
            float p0 = __expf(s0 - mn);
            mmax = mn;
            denom = denom * corr + p0;
            const float4 v0 = *(const float4*)(vb + (size_t)c * (KVH_ * HD_));
            acc.x = acc.x * corr + p0 * v0.x;
            acc.y = acc.y * corr + p0 * v0.y;
            acc.z = acc.z * corr + p0 * v0.z;
            acc.w = acc.w * corr + p0 * v0.w;
        }
    }
    float inv = 1.f / denom;
    float4 o4;
    o4.x = rtf32(acc.x * inv); o4.y = rtf32(acc.y * inv);
    o4.z = rtf32(acc.z * inv); o4.w = rtf32(acc.w * inv);
    *(float4*)(merged + (size_t)r * INTER_ + h * HD_ + lane * 4) = o4;
}

// ---------------- elementwise (fast silu) ----------------
__global__ void swiglu_fused_k(const float* __restrict__ gu, float* __restrict__ o) {
    int i = blockIdx.x * blockDim.x + threadIdx.x;
    if (i >= T_ * MLPI_) return;
    int row = i / MLPI_, c = i % MLPI_;
    float x = gu[(size_t)row * (2 * MLPI_) + c];
    float u = gu[(size_t)row * (2 * MLPI_) + MLPI_ + c];
    o[i] = rtf32(fsilu(x) * u);
}

// ---------------- host ----------------
typedef CUresult (*PFN_encodeTiled)(CUtensorMap*, CUtensorMapDataType, cuuint32_t, void*,
                                    const cuuint64_t*, const cuuint64_t*, const cuuint32_t*,
                                    const cuuint32_t*, CUtensorMapInterleave, CUtensorMapSwizzle,
                                    CUtensorMapL2promotion, CUtensorMapFloatOOBfill);

static PFN_encodeTiled get_encoder() {
    void* p = nullptr;
    cudaDriverEntryPointQueryResult st;
    cudaGetDriverEntryPointByVersion("cuTensorMapEncodeTiled", &p, 12000, cudaEnableDefault, &st);
    return (PFN_encodeTiled)p;
}

static void make_tm(PFN_encodeTiled enc, CUtensorMap* tm, const float* base,
                    int rows, int cols, int box_rows) {
    cuuint64_t dims[2]    = {(cuuint64_t)cols, (cuuint64_t)rows};
    cuuint64_t strides[1] = {(cuuint64_t)cols * 4};
    cuuint32_t box[2]     = {32u, (cuuint32_t)box_rows};
    cuuint32_t es[2]      = {1u, 1u};
    enc(tm, CU_TENSOR_MAP_DATA_TYPE_FLOAT32, 2, (void*)base, dims, strides, box, es,
        CU_TENSOR_MAP_INTERLEAVE_NONE, CU_TENSOR_MAP_SWIZZLE_128B,
        CU_TENSOR_MAP_L2_PROMOTION_L2_128B, CU_TENSOR_MAP_FLOAT_OOB_FILL_NONE);
}

static PFN_encodeTiled g_enc = nullptr;

static void launch_gemm_tc(const float* A, const float* B,
                           const float* bias, const float* res, float* C,
                           int M, int N, int K, bool roundOut) {
    CUtensorMap tmA, tmB;
    make_tm(g_enc, &tmA, A, M, K, 128);
    make_tm(g_enc, &tmB, B, N, K, 256);
    dim3 grid((N + GBN - 1) / GBN, (M + GBM - 1) / GBM);
    if (roundOut) gemm_tc<true><<<grid, 128, GSMEM>>>(tmA, tmB, A, B, bias, res, C, M, N, K);
    else          gemm_tc<false><<<grid, 128, GSMEM>>>(tmA, tmB, A, B, bias, res, C, M, N, K);
}

static void roundw(const float* src, float* dst, int n) {
    int n4 = n / 4;
    roundw_k<<<(n4 + 255) / 256, 256>>>(src, dst, n4);
}

extern "C" void kernel_launch(void* const* d_in, const int* in_sizes, int n_in,
                              void* d_out, int out_size) {
    const float* hs      = (const float*)d_in[0];
    const float* cosb    = (const float*)d_in[1];
    const float* sinb    = (const float*)d_in[2];
    const float* ln1_w   = (const float*)d_in[3];
    const float* q_w     = (const float*)d_in[4];
    const float* q_b     = (const float*)d_in[5];
    const float* k_w     = (const float*)d_in[6];
    const float* k_b     = (const float*)d_in[7];
    const float* v_w     = (const float*)d_in[8];
    const float* v_b     = (const float*)d_in[9];
    const float* o_w     = (const float*)d_in[10];
    const float* inpj_w  = (const float*)d_in[11];
    const float* conv_w  = (const float*)d_in[12];
    const float* conv_b  = (const float*)d_in[13];
    const float* dt_bias = (const float*)d_in[14];
    const float* A_log   = (const float*)d_in[15];
    const float* Dp      = (const float*)d_in[16];
    const float* mnorm_w = (const float*)d_in[17];
    const float* outp_w  = (const float*)d_in[18];
    const float* ln2_w   = (const float*)d_in[19];
    const float* gate_w  = (const float*)d_in[20];
    const float* up_w    = (const float*)d_in[21];
    const float* down_w  = (const float*)d_in[22];
    float* out = (float*)d_out;

    float *pre, *proj, *xbc, *dtb, *ybuf, *gbuf, *qb, *kb, *vb, *merged, *hb, *mb, *gub, *gateb;
    float *wq, *wk, *wv, *wo, *win, *wout, *wgu, *wd;
    cudaGetSymbolAddress((void**)&pre,    g_pre);
    cudaGetSymbolAddress((void**)&proj,   g_proj);
    cudaGetSymbolAddress((void**)&xbc,    g_xbc);
    cudaGetSymbolAddress((void**)&dtb,    g_dt);
    cudaGetSymbolAddress((void**)&ybuf,   g_y);
    cudaGetSymbolAddress((void**)&gbuf,   g_g);
    cudaGetSymbolAddress((void**)&qb,     g_q);
    cudaGetSymbolAddress((void**)&kb,     g_k);
    cudaGetSymbolAddress((void**)&vb,     g_v);
    cudaGetSymbolAddress((void**)&merged, g_merged);
    cudaGetSymbolAddress((void**)&hb,     g_h);
    cudaGetSymbolAddress((void**)&mb,     g_m);
    cudaGetSymbolAddress((void**)&gub,    g_gu);
    cudaGetSymbolAddress((void**)&gateb,  g_gate);
    cudaGetSymbolAddress((void**)&wq,     g_wq);
    cudaGetSymbolAddress((void**)&wk,     g_wk);
    cudaGetSymbolAddress((void**)&wv,     g_wv);
    cudaGetSymbolAddress((void**)&wo,     g_wo);
    cudaGetSymbolAddress((void**)&win,    g_win);
    cudaGetSymbolAddress((void**)&wout,   g_wout);
    cudaGetSymbolAddress((void**)&wgu,    g_wgu);
    cudaGetSymbolAddress((void**)&wd,     g_wd);

    if (!g_enc) g_enc = get_encoder();
    static bool attrs_set = false;
    if (!attrs_set) {
        cudaFuncSetAttribute(gemm_tc<false>, cudaFuncAttributeMaxDynamicSharedMemorySize, GSMEM);
        cudaFuncSetAttribute(gemm_tc<true>,  cudaFuncAttributeMaxDynamicSharedMemorySize, GSMEM);
        attrs_set = true;
    }

    // 0. round weights to tf32 (unbiased rna); gate|up concatenated
    roundw(q_w,    wq,   NH_ * HD_ * H_);
    roundw(k_w,    wk,   KVH_ * HD_ * H_);
    roundw(v_w,    wv,   KVH_ * HD_ * H_);
    roundw(o_w,    wo,   H_ * NH_ * HD_);
    roundw(inpj_w, win,  NPROJ_ * H_);
    roundw(outp_w, wout, H_ * INTER_);
    roundw(gate_w, wgu,                       MLPI_ * H_);
    roundw(up_w,   wgu + (size_t)MLPI_ * H_,  MLPI_ * H_);
    roundw(down_w, wd,   H_ * MLPI_);

    // 1. pre-norm (tf32-rounded: feeds GEMMs only)
    rmsnorm_k<<<T_, 256>>>(hs, ln1_w, pre, H_, EPS_, 1);

    // 2. mamba branch on pre rows [64, 1536)
    launch_gemm_tc(pre + (size_t)SINK_ * H_, win, nullptr, nullptr, proj, LMEM_, NPROJ_, H_, false);
    conv_silu_k<<<(LMEM_ * CONVD_ + 255) / 256, 256>>>(proj, conv_w, conv_b, xbc);
    dt_k<<<(LMEM_ * NH_ + 255) / 256, 256>>>(proj, dt_bias, dtb);
    scan_k<<<NH_, 128>>>(xbc, dtb, A_log, Dp, ybuf);
    gatenorm_k<<<LMEM_, 256>>>(ybuf, proj, mnorm_w, gbuf);
    launch_gemm_tc(gbuf, wout, nullptr, nullptr, merged + (size_t)SINK_ * INTER_, LMEM_, INTER_, H_, true);

    // 3. q projection on consumed rows only; full k/v
    launch_gemm_tc(pre, wq, q_b, nullptr, qb, SINK_, NH_ * HD_, H_, false);
    launch_gemm_tc(pre + (size_t)(T_ - WIN_) * H_, wq, q_b, nullptr,
                   qb + (size_t)(T_ - WIN_) * (NH_ * HD_), WIN_, NH_ * HD_, H_, false);
    launch_gemm_tc(pre, wk, k_b, nullptr, kb, T_, KVH_ * HD_, H_, false);
    launch_gemm_tc(pre, wv, v_b, nullptr, vb, T_, KVH_ * HD_, H_, false);

    // 4. RoPE
    rope_q_k<<<dim3(4, SINK_ + WIN_), 256>>>(qb, cosb, sinb);
    rope_k_k<<<dim3(1, T_), 256>>>(kb, cosb, sinb);

    // 5. replace k/v at row SINK with mem_act projection (exact fp32 GEMV)
    memact_kv_k<<<2 * KVH_ * HD_, 256>>>(merged, k_w, k_b, v_w, v_b, kb, vb);

    // 6. attention -> merged rows [0,64) and [1536,2048)
    attn_k<<<((SINK_ + WIN_) * NH_ + 7) / 8, 256>>>(qb, kb, vb, merged);

    // 7. o projection + FUSED residual -> hb
    launch_gemm_tc(merged, wo, nullptr, hs, hb, T_, H_, NH_ * HD_, false);

    // 8. MLP (gate+up fused); down-proj + FUSED residual -> out
    rmsnorm_k<<<T_, 256>>>(hb, ln2_w, mb, H_, EPS_, 1);
    launch_gemm_tc(mb, wgu, nullptr, nullptr, gub, T_, 2 * MLPI_, H_, false);
    swiglu_fused_k<<<(T_ * MLPI_ + 255) / 256, 256>>>(gub, gateb);
    launch_gemm_tc(gateb, wd, nullptr, hb, out, T_, H_, MLPI_, false);
}